// round 7
// baseline (speedup 1.0000x reference)
#include <cuda_runtime.h>
#include <math.h>
#include <stdint.h>

#define Bn 32
#define Tn 2048
#define Dn 1024
#define En 16
#define Ln 8
#define Pmax 720
#define SUBSEG 32
#define NSUB 4
#define NPART 16

typedef unsigned long long ull;

__device__ __forceinline__ void fma2(ull& d, ull a, ull b) {
    asm("fma.rn.f32x2 %0, %1, %2, %0;" : "+l"(d) : "l"(a), "l"(b));
}
__device__ __forceinline__ float2 u2f(ull v) {
    float2 f; asm("mov.b64 {%0,%1}, %2;" : "=f"(f.x), "=f"(f.y) : "l"(v)); return f;
}
__device__ __forceinline__ float gelu_f(float x) {
    return 0.5f * x * (1.0f + erff(x * 0.70710678118654752440f));
}

// ---------------- scratch ----------------
__device__ float g_step_base[Pmax * Dn];
__device__ float g_t1p[8 * Ln * Dn];
__device__ float g_qeffp[8 * Ln * Dn];
__device__ float g_qeff[Ln * Dn];
__device__ float g_ssum[Bn * Ln * NPART];
__device__ float g_upart[(size_t)NPART * Bn * Ln * Dn];
__device__ float g_U[Bn * Ln * Dn];
__device__ float g_pA[8 * Bn * Ln * Dn];
__device__ float g_pLC[8 * Bn * Ln * Dn];
__device__ float g_pk2[8 * Bn * Ln * Dn];
__device__ float g_pB[8 * Bn * Ln * Dn];
__device__ float g_pC[8 * Bn * Ln * Dn];
__device__ float g_plvw[8 * Bn * Ln * Dn];
__device__ float g_k2[Bn * Ln * Dn];
__device__ float g_lvw[Bn * Ln * Dn];
__device__ float g_bcat[Dn * 2048];
__device__ float g_pcat[2 * Pmax * 2048];
__device__ float g_qb2[Pmax * Dn];
__device__ float g_bh[Pmax * Dn];
__device__ float g_A2[Bn * Pmax * Ln];
__device__ float4 g_sel[Bn * Pmax];

// ---------------- step_base ----------------
__global__ void k_stepbase(const float* __restrict__ qpos,
                           const float* __restrict__ tbl, int pl) {
    int i = blockIdx.x * 256 + threadIdx.x;
    if (i < pl * Dn)
        g_step_base[i] = qpos[i] + tbl[(size_t)pl * Dn + (i & (Dn - 1))];
}

// ---------------- pack B for the fused P-GEMM ----------------
__global__ void k_pack(const float* __restrict__ sqw, const float* __restrict__ gw1,
                       float alpha) {
    int i = blockIdx.x * 256 + threadIdx.x;
    int row = i >> 9;
    int c4 = i & 511;
    float4 v;
    if (c4 < 256) {
        v = ((const float4*)sqw)[row * 256 + c4];
        v.x *= alpha; v.y *= alpha; v.z *= alpha; v.w *= alpha;
    } else {
        v = ((const float4*)gw1)[row * 256 + (c4 - 256)];
    }
    ((float4*)g_bcat)[i] = v;
}

// ---------------- 64x64 fp32x2 GEMM (kept for thin M=8 qeff GEMMs) ----------------
#define GEMM_PREFETCH(k0)                                                        \
    {                                                                            \
        for (int r = 0; r < 4; r++) {                                            \
            int i = tid + 256 * r;                                               \
            int row = i >> 4, col = i & 15;                                      \
            int gm = m0 + row;                                                   \
            float v = 0.f;                                                       \
            if (gm < M) {                                                        \
                size_t off = (size_t)gm * K + (k0) + col;                        \
                v = A[off];                                                      \
                for (int s = 1; s < nsumA; s++) v += A[off + (size_t)s * strideA]; \
            }                                                                    \
            ra[r] = v;                                                           \
        }                                                                        \
        if (!transB) {                                                           \
            for (int r = 0; r < 4; r++) {                                        \
                int i = tid + 256 * r;                                           \
                rb[r] = B[(size_t)((k0) + (i >> 6)) * N + n0 + (i & 63)];        \
            }                                                                    \
        } else {                                                                 \
            for (int r = 0; r < 4; r++) {                                        \
                int i = tid + 256 * r;                                           \
                rb[r] = B[(size_t)(n0 + (i >> 4)) * K + (k0) + (i & 15)];        \
            }                                                                    \
        }                                                                        \
    }

#define GEMM_STORE(bf)                                                           \
    {                                                                            \
        for (int r = 0; r < 4; r++) {                                            \
            int i = tid + 256 * r;                                               \
            *(float2*)&As2[bf][i & 15][2 * (i >> 4)] = make_float2(ra[r], ra[r]); \
        }                                                                        \
        if (!transB) {                                                           \
            for (int r = 0; r < 4; r++) {                                        \
                int i = tid + 256 * r;                                           \
                Bs[bf][i >> 6][i & 63] = rb[r];                                  \
            }                                                                    \
        } else {                                                                 \
            for (int r = 0; r < 4; r++) {                                        \
                int i = tid + 256 * r;                                           \
                Bs[bf][i & 15][i >> 4] = rb[r];                                  \
            }                                                                    \
        }                                                                        \
    }

#define GEMM_COMPUTE(bf)                                                         \
    {                                                                            \
        _Pragma("unroll")                                                        \
        for (int kk = 0; kk < 16; kk++) {                                        \
            ulonglong2 a01 = *(const ulonglong2*)&As2[bf][kk][ty * 8];           \
            ulonglong2 a23 = *(const ulonglong2*)&As2[bf][kk][ty * 8 + 4];       \
            ulonglong2 bb  = *(const ulonglong2*)&Bs[bf][kk][tx * 4];            \
            fma2(acc[0][0], a01.x, bb.x); fma2(acc[0][1], a01.x, bb.y);          \
            fma2(acc[1][0], a01.y, bb.x); fma2(acc[1][1], a01.y, bb.y);          \
            fma2(acc[2][0], a23.x, bb.x); fma2(acc[2][1], a23.x, bb.y);          \
            fma2(acc[3][0], a23.y, bb.x); fma2(acc[3][1], a23.y, bb.y);          \
        }                                                                        \
    }

__global__ void k_gemm(const float* __restrict__ A, const float* __restrict__ B,
                       float* __restrict__ C, int M, int N, int K,
                       int transB, const float* __restrict__ bias, float alpha,
                       int nsumA, int strideA) {
    __shared__ float As2[2][16][136];
    __shared__ float Bs[2][16][68];
    int tid = threadIdx.x;
    int tx = tid & 15, ty = tid >> 4;
    int m0 = blockIdx.y * 64, n0 = blockIdx.x * 64;
    int kper = K / gridDim.z;
    int kbeg = blockIdx.z * kper;
    C += (size_t)blockIdx.z * M * N;
    int nk = kper / 16;

    ull acc[4][2];
#pragma unroll
    for (int i = 0; i < 4; i++) { acc[i][0] = 0ULL; acc[i][1] = 0ULL; }

    float ra[4], rb[4];
    int buf = 0;
    GEMM_PREFETCH(kbeg);
    GEMM_STORE(0);
    __syncthreads();
    for (int kt = 0; kt < nk; kt++) {
        if (kt + 1 < nk) GEMM_PREFETCH(kbeg + (kt + 1) * 16);
        GEMM_COMPUTE(buf);
        if (kt + 1 < nk) {
            GEMM_STORE(buf ^ 1);
            __syncthreads();
            buf ^= 1;
        }
    }
#pragma unroll
    for (int i = 0; i < 4; i++) {
        int m = m0 + ty * 4 + i;
        if (m >= M) continue;
        float2 p0 = u2f(acc[i][0]), p1 = u2f(acc[i][1]);
        float4 o;
        o.x = alpha * p0.x; o.y = alpha * p0.y;
        o.z = alpha * p1.x; o.w = alpha * p1.y;
        if (bias) {
            o.x += bias[n0 + tx * 4];     o.y += bias[n0 + tx * 4 + 1];
            o.z += bias[n0 + tx * 4 + 2]; o.w += bias[n0 + tx * 4 + 3];
        }
        *(float4*)&C[(size_t)m * N + n0 + tx * 4] = o;
    }
}

// ---------------- 128x128 fp32x2 GEMM, 8x8 microtile (fma-bound) ----------------
// dyn smem: As2 [2][16][264] dup-A, Bs [2][16][136]. 256 threads, split-K via z.
#define AS2(bf, kk, x) smg[(bf) * (16 * 264) + (kk) * 264 + (x)]
#define BS(bf, kk, x)  smg[2 * 16 * 264 + (bf) * (16 * 136) + (kk) * 136 + (x)]

__global__ void __launch_bounds__(256, 2) k_gemm128(
    const float* __restrict__ A, const float* __restrict__ B,
    float* __restrict__ C, int M, int N, int K,
    float alpha, int nsumA, int strideA) {
    extern __shared__ float smg[];
    int tid = threadIdx.x;
    int tx = tid & 15, ty = tid >> 4;
    int m0 = blockIdx.y * 128, n0 = blockIdx.x * 128;
    int kper = K / gridDim.z;
    int kbeg = blockIdx.z * kper;
    C += (size_t)blockIdx.z * M * N;
    int nk = kper / 16;

    ull acc[8][4];
#pragma unroll
    for (int i = 0; i < 8; i++)
#pragma unroll
        for (int j = 0; j < 4; j++) acc[i][j] = 0ULL;

    float ra[8], rb[8];
#define G128_PREFETCH(k0)                                                        \
    {                                                                            \
        for (int r = 0; r < 8; r++) {                                            \
            int i = tid + 256 * r;                                               \
            int row = i >> 4, col = i & 15;                                      \
            int gm = m0 + row;                                                   \
            float v = 0.f;                                                       \
            if (gm < M) {                                                        \
                size_t off = (size_t)gm * K + (k0) + col;                        \
                v = A[off];                                                      \
                for (int s = 1; s < nsumA; s++) v += A[off + (size_t)s * strideA]; \
            }                                                                    \
            ra[r] = v;                                                           \
        }                                                                        \
        for (int r = 0; r < 8; r++) {                                            \
            int i = tid + 256 * r;                                               \
            rb[r] = B[(size_t)((k0) + (i >> 7)) * N + n0 + (i & 127)];           \
        }                                                                        \
    }
#define G128_STORE(bf)                                                           \
    {                                                                            \
        for (int r = 0; r < 8; r++) {                                            \
            int i = tid + 256 * r;                                               \
            *(float2*)&AS2(bf, i & 15, 2 * (i >> 4)) = make_float2(ra[r], ra[r]); \
        }                                                                        \
        for (int r = 0; r < 8; r++) {                                            \
            int i = tid + 256 * r;                                               \
            BS(bf, i >> 7, i & 127) = rb[r];                                     \
        }                                                                        \
    }
#define G128_COMPUTE(bf)                                                         \
    {                                                                            \
        _Pragma("unroll")                                                        \
        for (int kk = 0; kk < 16; kk++) {                                        \
            ulonglong2 a0 = *(const ulonglong2*)&AS2(bf, kk, ty * 16);           \
            ulonglong2 a1 = *(const ulonglong2*)&AS2(bf, kk, ty * 16 + 4);       \
            ulonglong2 a2 = *(const ulonglong2*)&AS2(bf, kk, ty * 16 + 8);       \
            ulonglong2 a3 = *(const ulonglong2*)&AS2(bf, kk, ty * 16 + 12);      \
            ulonglong2 b0 = *(const ulonglong2*)&BS(bf, kk, tx * 8);             \
            ulonglong2 b1 = *(const ulonglong2*)&BS(bf, kk, tx * 8 + 4);         \
            fma2(acc[0][0], a0.x, b0.x); fma2(acc[0][1], a0.x, b0.y);            \
            fma2(acc[0][2], a0.x, b1.x); fma2(acc[0][3], a0.x, b1.y);            \
            fma2(acc[1][0], a0.y, b0.x); fma2(acc[1][1], a0.y, b0.y);            \
            fma2(acc[1][2], a0.y, b1.x); fma2(acc[1][3], a0.y, b1.y);            \
            fma2(acc[2][0], a1.x, b0.x); fma2(acc[2][1], a1.x, b0.y);            \
            fma2(acc[2][2], a1.x, b1.x); fma2(acc[2][3], a1.x, b1.y);            \
            fma2(acc[3][0], a1.y, b0.x); fma2(acc[3][1], a1.y, b0.y);            \
            fma2(acc[3][2], a1.y, b1.x); fma2(acc[3][3], a1.y, b1.y);            \
            fma2(acc[4][0], a2.x, b0.x); fma2(acc[4][1], a2.x, b0.y);            \
            fma2(acc[4][2], a2.x, b1.x); fma2(acc[4][3], a2.x, b1.y);            \
            fma2(acc[5][0], a2.y, b0.x); fma2(acc[5][1], a2.y, b0.y);            \
            fma2(acc[5][2], a2.y, b1.x); fma2(acc[5][3], a2.y, b1.y);            \
            fma2(acc[6][0], a3.x, b0.x); fma2(acc[6][1], a3.x, b0.y);            \
            fma2(acc[6][2], a3.x, b1.x); fma2(acc[6][3], a3.x, b1.y);            \
            fma2(acc[7][0], a3.y, b0.x); fma2(acc[7][1], a3.y, b0.y);            \
            fma2(acc[7][2], a3.y, b1.x); fma2(acc[7][3], a3.y, b1.y);            \
        }                                                                        \
    }
    int buf = 0;
    G128_PREFETCH(kbeg);
    G128_STORE(0);
    __syncthreads();
    for (int kt = 0; kt < nk; kt++) {
        if (kt + 1 < nk) G128_PREFETCH(kbeg + (kt + 1) * 16);
        G128_COMPUTE(buf);
        if (kt + 1 < nk) {
            G128_STORE(buf ^ 1);
            __syncthreads();
            buf ^= 1;
        }
    }
#pragma unroll
    for (int i = 0; i < 8; i++) {
        int m = m0 + ty * 8 + i;
        if (m >= M) continue;
        float2 p0 = u2f(acc[i][0]), p1 = u2f(acc[i][1]);
        float2 p2 = u2f(acc[i][2]), p3 = u2f(acc[i][3]);
        float4 o0 = make_float4(alpha * p0.x, alpha * p0.y, alpha * p1.x, alpha * p1.y);
        float4 o1 = make_float4(alpha * p2.x, alpha * p2.y, alpha * p3.x, alpha * p3.y);
        *(float4*)&C[(size_t)m * N + n0 + tx * 8] = o0;
        *(float4*)&C[(size_t)m * N + n0 + tx * 8 + 4] = o1;
    }
}

// ---------------- generic partial reduction ----------------
__global__ void k_redN(float4* __restrict__ dst, const float4* __restrict__ src,
                       int n4, int nparts, int stride4) {
    int i = blockIdx.x * 256 + threadIdx.x;
    if (i >= n4) return;
    float4 s = src[i];
    for (int p = 1; p < nparts; p++) {
        float4 t = src[i + (size_t)p * stride4];
        s.x += t.x; s.y += t.y; s.z += t.z; s.w += t.w;
    }
    dst[i] = s;
}

// ---------------- de-interleave + reduce the packed P-GEMM ----------------
__global__ void k_redsplit(int pl) {
    int i = blockIdx.x * 256 + threadIdx.x;
    if (i >= pl * 256) return;
    int p = i >> 8, d4 = i & 255;
    const float4* s = (const float4*)g_pcat;
    size_t base = (size_t)p * 512 + d4;
    size_t part = (size_t)pl * 512;
    float4 a = s[base], b = s[base + part];
    float4 c = s[base + 256], d = s[base + 256 + part];
    float4 q, h;
    q.x = a.x + b.x; q.y = a.y + b.y; q.z = a.z + b.z; q.w = a.w + b.w;
    h.x = c.x + d.x; h.y = c.y + d.y; h.z = c.z + d.z; h.w = c.w + d.w;
    ((float4*)g_qb2)[i] = q;
    ((float4*)g_bh)[i] = h;
}

// ---------------- fused stage-1 (single DRAM pass, 512 threads) -------------------
__global__ void __launch_bounds__(512) k_fused1(const float* __restrict__ ctx) {
    extern __shared__ float smf[];
    float* qs  = smf;                    // 8*1024
    float* ck  = qs + Ln * Dn;           // 32*1024
    float* ps2 = ck + SUBSEG * Dn;       // [tt][2l] dup pairs: 32*16
    float* prt = ps2 + SUBSEG * 16;      // 32 tt * 16 (l*2+h)
    int tid = threadIdx.x;
    for (int i = tid; i < Ln * Dn / 4; i += 512)
        ((float4*)qs)[i] = ((const float4*)g_qeff)[i];
    int b = blockIdx.y;
    int w = tid >> 5, lane = tid & 31;
    int g = w >> 1, h = w & 1;

    ull uacc[Ln];
#pragma unroll
    for (int l = 0; l < Ln; l++) uacc[l] = 0ULL;
    float ssum = 0.f;

    for (int sub = 0; sub < NSUB; sub++) {
        int t0 = (blockIdx.x * NSUB + sub) * SUBSEG;
        const float* base = ctx + ((size_t)b * Tn + t0 + g * 4) * Dn + h * 512;
        __syncthreads();

        // phase A: 4 token rows x half-d per warp
        ull acc[4][Ln];
#pragma unroll
        for (int tt = 0; tt < 4; tt++)
#pragma unroll
            for (int l = 0; l < Ln; l++) acc[tt][l] = 0ULL;
#pragma unroll
        for (int i = 0; i < 4; i++) {
            int d = (lane + 32 * i) * 4;
            ulonglong2 c0 = *(const ulonglong2*)(base + d);
            ulonglong2 c1 = *(const ulonglong2*)(base + Dn + d);
            ulonglong2 c2 = *(const ulonglong2*)(base + 2 * Dn + d);
            ulonglong2 c3 = *(const ulonglong2*)(base + 3 * Dn + d);
            int ckd = h * 512 + d;
            *(ulonglong2*)&ck[(g * 4 + 0) * Dn + ckd] = c0;
            *(ulonglong2*)&ck[(g * 4 + 1) * Dn + ckd] = c1;
            *(ulonglong2*)&ck[(g * 4 + 2) * Dn + ckd] = c2;
            *(ulonglong2*)&ck[(g * 4 + 3) * Dn + ckd] = c3;
#pragma unroll
            for (int l = 0; l < Ln; l++) {
                ulonglong2 q = *(const ulonglong2*)&qs[l * Dn + ckd];
                fma2(acc[0][l], c0.x, q.x); fma2(acc[0][l], c0.y, q.y);
                fma2(acc[1][l], c1.x, q.x); fma2(acc[1][l], c1.y, q.y);
                fma2(acc[2][l], c2.x, q.x); fma2(acc[2][l], c2.y, q.y);
                fma2(acc[3][l], c3.x, q.x); fma2(acc[3][l], c3.y, q.y);
            }
        }
#pragma unroll
        for (int tt = 0; tt < 4; tt++)
#pragma unroll
            for (int l = 0; l < Ln; l++) {
                float2 f = u2f(acc[tt][l]);
                float v = f.x + f.y;
                for (int off = 16; off; off >>= 1)
                    v += __shfl_xor_sync(0xffffffffu, v, off);
                if (lane == 0)
                    prt[(g * 4 + tt) * 16 + l * 2 + h] = v;
            }
        __syncthreads();

        // finalize: exp (shift-free softmax; scores tiny, clamp for safety)
        if (tid < 256) {
            int tt = tid >> 3, l = tid & 7;
            float v = prt[tt * 16 + l * 2] + prt[tt * 16 + l * 2 + 1];
            float e = expf(fminf(v, 60.0f));
            ps2[tt * 16 + 2 * l] = e;
            ps2[tt * 16 + 2 * l + 1] = e;
        }
        __syncthreads();

        // phase B: warps 0-7 accumulate exp-sum for l = w (lane = tt)
        if (w < Ln) {
            float s = ps2[lane * 16 + 2 * w];
            for (int off = 16; off; off >>= 1)
                s += __shfl_xor_sync(0xffffffffu, s, off);
            ssum += s;
        }

        // phase C: U accumulation; probs loaded as 4 broadcast LDS.128 per token
        int d2 = tid * 2;
#pragma unroll 2
        for (int tt = 0; tt < SUBSEG; tt++) {
            ull c = *(const ull*)&ck[tt * Dn + d2];
            ulonglong2 p01 = *(const ulonglong2*)&ps2[tt * 16];
            ulonglong2 p23 = *(const ulonglong2*)&ps2[tt * 16 + 4];
            ulonglong2 p45 = *(const ulonglong2*)&ps2[tt * 16 + 8];
            ulonglong2 p67 = *(const ulonglong2*)&ps2[tt * 16 + 12];
            fma2(uacc[0], p01.x, c); fma2(uacc[1], p01.y, c);
            fma2(uacc[2], p23.x, c); fma2(uacc[3], p23.y, c);
            fma2(uacc[4], p45.x, c); fma2(uacc[5], p45.y, c);
            fma2(uacc[6], p67.x, c); fma2(uacc[7], p67.y, c);
        }
    }
#pragma unroll
    for (int l = 0; l < Ln; l++) {
        float2 f = u2f(uacc[l]);
        *(float2*)&g_upart[(((size_t)blockIdx.x * Bn + b) * Ln + l) * Dn + tid * 2] = f;
    }
    if (w < Ln && lane == 0)
        g_ssum[((size_t)b * Ln + w) * NPART + blockIdx.x] = ssum;
}

// ---------------- combine stage-1 partials ----------------
__global__ void k_comb1() {
    __shared__ float inv[Ln];
    int b = blockIdx.y, dc = blockIdx.x;
    int tid = threadIdx.x;
    if (tid < Ln) {
        float s0 = 0.f, s1 = 0.f, s2 = 0.f, s3 = 0.f;
#pragma unroll
        for (int g = 0; g < NPART; g += 4) {
            s0 += g_ssum[((size_t)b * Ln + tid) * NPART + g];
            s1 += g_ssum[((size_t)b * Ln + tid) * NPART + g + 1];
            s2 += g_ssum[((size_t)b * Ln + tid) * NPART + g + 2];
            s3 += g_ssum[((size_t)b * Ln + tid) * NPART + g + 3];
        }
        inv[tid] = 1.0f / ((s0 + s1) + (s2 + s3));
    }
    __syncthreads();
    int dg = dc * 256 + tid;
#pragma unroll
    for (int l = 0; l < Ln; l++) {
        float a0 = 0.f, a1 = 0.f, a2 = 0.f, a3 = 0.f;
#pragma unroll
        for (int s = 0; s < NPART; s += 4) {
            a0 += g_upart[(((size_t)(s + 0) * Bn + b) * Ln + l) * Dn + dg];
            a1 += g_upart[(((size_t)(s + 1) * Bn + b) * Ln + l) * Dn + dg];
            a2 += g_upart[(((size_t)(s + 2) * Bn + b) * Ln + l) * Dn + dg];
            a3 += g_upart[(((size_t)(s + 3) * Bn + b) * Ln + l) * Dn + dg];
        }
        g_U[((size_t)b * Ln + l) * Dn + dg] = ((a0 + a1) + (a2 + a3)) * inv[l];
    }
}

// ---------------- stage-2 scores + softmax over L=8 ----------------
__global__ void k_s2(int pl) {
    __shared__ float ks[Ln][Dn];
    int tid = threadIdx.x, b = blockIdx.y;
    for (int i = tid; i < Ln * Dn / 4; i += 256)
        ((float4*)ks)[i] = ((const float4*)(g_k2 + (size_t)b * Ln * Dn))[i];
    __syncthreads();
    int w = tid >> 5, lane = tid & 31;
    int p0 = blockIdx.x * 16 + w * 2;
    if (p0 > pl - 2) p0 = pl - 2;
    ull acc[2][Ln];
#pragma unroll
    for (int pp = 0; pp < 2; pp++)
#pragma unroll
        for (int l = 0; l < Ln; l++) acc[pp][l] = 0ULL;
#pragma unroll
    for (int i = 0; i < 8; i++) {
        int d = (lane + 32 * i) * 4;
        ulonglong2 q0 = *(const ulonglong2*)(g_qb2 + (size_t)p0 * Dn + d);
        ulonglong2 q1 = *(const ulonglong2*)(g_qb2 + (size_t)(p0 + 1) * Dn + d);
#pragma unroll
        for (int l = 0; l < Ln; l++) {
            ulonglong2 k = *(const ulonglong2*)&ks[l][d];
            fma2(acc[0][l], q0.x, k.x); fma2(acc[0][l], q0.y, k.y);
            fma2(acc[1][l], q1.x, k.x); fma2(acc[1][l], q1.y, k.y);
        }
    }
#pragma unroll
    for (int pp = 0; pp < 2; pp++) {
        float v[Ln];
#pragma unroll
        for (int l = 0; l < Ln; l++) {
            float2 f = u2f(acc[pp][l]);
            float s = f.x + f.y;
            for (int off = 16; off; off >>= 1)
                s += __shfl_xor_sync(0xffffffffu, s, off);
            v[l] = s;
        }
        if (lane == 0) {
            int p = p0 + pp;
            if (p < pl) {
                float m = v[0];
#pragma unroll
                for (int l = 1; l < Ln; l++) m = fmaxf(m, v[l]);
                float e[Ln], s = 0.f;
#pragma unroll
                for (int l = 0; l < Ln; l++) { e[l] = expf(v[l] - m); s += e[l]; }
                float inv = 1.0f / s;
#pragma unroll
                for (int l = 0; l < Ln; l++)
                    g_A2[((size_t)b * pl + p) * Ln + l] = e[l] * inv;
            }
        }
    }
}

// ---------------- gate select ----------------
__global__ void k_gatesel(const float* __restrict__ w2, const float* __restrict__ b2,
                          const float* __restrict__ b1, int pl) {
    extern __shared__ float sm[];
    float* lvws = sm;
    float* w2T  = lvws + Ln * Dn;
    float* hs   = w2T + 16 * 1026;
    float* a2s  = hs + Dn;
    float* part = a2s + 64;
    float* lg   = part + 272;
    int tid = threadIdx.x, b = blockIdx.y, p0 = blockIdx.x * 8;
    for (int i = tid; i < Ln * Dn / 4; i += 256)
        ((float4*)lvws)[i] = ((const float4*)(g_lvw + (size_t)b * Ln * Dn))[i];
    for (int i = tid; i < Dn * En; i += 256) {
        int d = i >> 4, e = i & 15;
        w2T[e * 1026 + d] = w2[i];
    }
    if (tid < 64) {
        int pi = tid >> 3, l = tid & 7;
        int p = p0 + pi;
        a2s[tid] = (p < pl) ? g_A2[((size_t)b * pl + p) * Ln + l] : 0.f;
    }
    float4 bh4[8];
#pragma unroll
    for (int pi = 0; pi < 8; pi++) {
        int p = p0 + pi;
        bh4[pi] = (p < pl) ? *(const float4*)(g_bh + (size_t)p * Dn + tid * 4)
                           : make_float4(0, 0, 0, 0);
    }
    float4 b1v = *(const float4*)(b1 + tid * 4);
    __syncthreads();
    int e_id = tid & 15, dseg = tid >> 4;
    for (int pi = 0; pi < 8; pi++) {
        int p = p0 + pi;
        if (p >= pl) break;
        float4 s4 = bh4[pi];
        s4.x += b1v.x; s4.y += b1v.y; s4.z += b1v.z; s4.w += b1v.w;
#pragma unroll
        for (int l = 0; l < Ln; l++) {
            float a = a2s[pi * 8 + l];
            float4 v = ((const float4*)lvws)[l * (Dn / 4) + tid];
            s4.x += a * v.x; s4.y += a * v.y; s4.z += a * v.z; s4.w += a * v.w;
        }
        float4 h4;
        h4.x = gelu_f(s4.x); h4.y = gelu_f(s4.y);
        h4.z = gelu_f(s4.z); h4.w = gelu_f(s4.w);
        ((float4*)hs)[tid] = h4;
        __syncthreads();
        ull lacc = 0ULL;
        int dbase = dseg * 64;
#pragma unroll
        for (int j = 0; j < 32; j++) {
            ull h2 = *(const ull*)&hs[dbase + 2 * j];
            ull wv = *(const ull*)&w2T[e_id * 1026 + dbase + 2 * j];
            fma2(lacc, h2, wv);
        }
        float2 lf = u2f(lacc);
        part[dseg * 17 + e_id] = lf.x + lf.y;
        __syncthreads();
        if (tid < En) {
            float L = b2[tid];
#pragma unroll
            for (int g = 0; g < 16; g++) L += part[g * 17 + tid];
            lg[tid] = L;
        }
        __syncthreads();
        if (tid == 0) {
            float b1s = lg[0]; int e1 = 0;
#pragma unroll
            for (int e = 1; e < En; e++) if (lg[e] > b1s) { b1s = lg[e]; e1 = e; }
            float b2s = -3.4e38f; int e2 = 0;
#pragma unroll
            for (int e = 0; e < En; e++)
                if (e != e1 && lg[e] > b2s) { b2s = lg[e]; e2 = e; }
            float x2 = expf(b2s - b1s);
            float s = 1.f + x2;
            g_sel[(size_t)b * pl + p] = make_float4(
                1.f / s, x2 / s, __int_as_float(e1), __int_as_float(e2));
        }
        __syncthreads();
    }
}

// ---------------- combine experts ----------------
__global__ void k_combine(const float* __restrict__ qexp, float* __restrict__ out,
                          int pl, int Pfull) {
    __shared__ float4 sel[Bn];
    int p = blockIdx.x, tid = threadIdx.x;
    if (tid < Bn) sel[tid] = g_sel[(size_t)tid * pl + p];
    __syncthreads();
#pragma unroll 4
    for (int b = 0; b < Bn; b++) {
        float4 s = sel[b];
        int eA = __float_as_int(s.z), eB = __float_as_int(s.w);
        float4 va = *(const float4*)(qexp + ((size_t)eA * Pfull + p) * Dn + tid * 4);
        float4 vb = *(const float4*)(qexp + ((size_t)eB * Pfull + p) * Dn + tid * 4);
        float4 o;
        o.x = s.x * va.x + s.y * vb.x;
        o.y = s.x * va.y + s.y * vb.y;
        o.z = s.x * va.z + s.y * vb.z;
        o.w = s.x * va.w + s.y * vb.w;
        *(float4*)(out + ((size_t)b * pl + p) * Dn + tid * 4) = o;
    }
}

// ---------------- launch ----------------
extern "C" void kernel_launch(void* const* d_in, const int* in_sizes, int n_in,
                              void* d_out, int out_size) {
    const float* ctx        = (const float*)d_in[0];
    const float* qexp       = (const float*)d_in[1];
    const float* qpos       = (const float*)d_in[2];
    const float* ptbl       = (const float*)d_in[3];
    const float* lats       = (const float*)d_in[4];
    const float* lat_q_w    = (const float*)d_in[5];
    const float* ctx_k_w    = (const float*)d_in[6];
    const float* ctx_v_w    = (const float*)d_in[7];
    const float* lat_out_w  = (const float*)d_in[8];
    const float* step_q_w   = (const float*)d_in[9];
    const float* lat_k_w    = (const float*)d_in[10];
    const float* lat_v_w    = (const float*)d_in[11];
    const float* step_out_w = (const float*)d_in[12];
    const float* gate_w1    = (const float*)d_in[13];
    const float* gate_b1    = (const float*)d_in[14];
    const float* gate_w2    = (const float*)d_in[15];
    const float* gate_b2    = (const float*)d_in[16];
    float* out = (float*)d_out;

    int pl = out_size / (Bn * Dn);
    int Pfull = in_sizes[2] / Dn;

    float *p_t1p, *p_qeffp, *p_qeff, *p_U;
    float *p_pA, *p_pLC, *p_pk2, *p_pB, *p_pC, *p_plvw;
    float *p_k2, *p_lvw, *p_sb, *p_bcat, *p_pcat;
    cudaGetSymbolAddress((void**)&p_t1p, g_t1p);
    cudaGetSymbolAddress((void**)&p_qeffp, g_qeffp);
    cudaGetSymbolAddress((void**)&p_qeff, g_qeff);
    cudaGetSymbolAddress((void**)&p_U, g_U);
    cudaGetSymbolAddress((void**)&p_pA, g_pA);
    cudaGetSymbolAddress((void**)&p_pLC, g_pLC);
    cudaGetSymbolAddress((void**)&p_pk2, g_pk2);
    cudaGetSymbolAddress((void**)&p_pB, g_pB);
    cudaGetSymbolAddress((void**)&p_pC, g_pC);
    cudaGetSymbolAddress((void**)&p_plvw, g_plvw);
    cudaGetSymbolAddress((void**)&p_k2, g_k2);
    cudaGetSymbolAddress((void**)&p_lvw, g_lvw);
    cudaGetSymbolAddress((void**)&p_sb, g_step_base);
    cudaGetSymbolAddress((void**)&p_bcat, g_bcat);
    cudaGetSymbolAddress((void**)&p_pcat, g_pcat);

    const float inv_sqrt_d = 0.03125f;
    const int S = Bn * Ln * Dn;
    const int smem_g128 = (2 * 16 * 264 + 2 * 16 * 136) * 4;
    cudaFuncSetAttribute(k_gemm128, cudaFuncAttributeMaxDynamicSharedMemorySize, smem_g128);

    // 0-2: batch-independent prep + first qeff GEMM
    k_stepbase<<<(pl * Dn + 255) / 256, 256>>>(qpos, ptbl, pl);
    k_pack<<<Dn * 2048 / 4 / 256, 256>>>(step_q_w, gate_w1, inv_sqrt_d);
    k_gemm<<<dim3(16, 1, 8), 256>>>(lats, lat_q_w, p_t1p, Ln, Dn, Dn, 0, nullptr, 1.f, 1, 0);

    // 3 (ncu-sampled): packed [720,2048,1024] P-GEMM with the new 128-tile kernel
    k_gemm128<<<dim3(16, (pl + 127) / 128, 2), 256, smem_g128>>>(
        p_sb, p_bcat, p_pcat, pl, 2048, Dn, 1.f, 1, 0);

    // qeff finish
    k_gemm<<<dim3(16, 1, 8), 256>>>(p_t1p, ctx_k_w, p_qeffp, Ln, Dn, Dn, 1, nullptr, inv_sqrt_d, 8, Ln * Dn);
    k_redN<<<8, 256>>>((float4*)p_qeff, (const float4*)p_qeffp, Ln * Dn / 4, 8, Ln * Dn / 4);

    // fused stage-1 (single DRAM pass over ctx)
    const int smem_f1 = (Ln * Dn + SUBSEG * Dn + SUBSEG * 16 + SUBSEG * 16) * 4;
    cudaFuncSetAttribute(k_fused1, cudaFuncAttributeMaxDynamicSharedMemorySize, smem_f1);
    k_fused1<<<dim3(NPART, Bn), 512, smem_f1>>>(ctx);
    k_comb1<<<dim3(4, Bn), 256>>>();

    // chain of [256,1024]x[1024,1024] GEMMs (128-tile, split-K x8)
    k_gemm128<<<dim3(8, 2, 8), 256, smem_g128>>>(p_U,   ctx_v_w,    p_pA,   Bn * Ln, Dn, Dn, 1.f, 1, 0);
    k_gemm128<<<dim3(8, 2, 8), 256, smem_g128>>>(p_pA,  lat_out_w,  p_pLC,  Bn * Ln, Dn, Dn, 1.f, 8, S);
    k_gemm128<<<dim3(8, 2, 8), 256, smem_g128>>>(p_pLC, lat_k_w,    p_pk2,  Bn * Ln, Dn, Dn, 1.f, 8, S);
    k_gemm128<<<dim3(8, 2, 8), 256, smem_g128>>>(p_pLC, lat_v_w,    p_pB,   Bn * Ln, Dn, Dn, 1.f, 8, S);
    k_gemm128<<<dim3(8, 2, 8), 256, smem_g128>>>(p_pB,  step_out_w, p_pC,   Bn * Ln, Dn, Dn, 1.f, 8, S);
    k_gemm128<<<dim3(8, 2, 8), 256, smem_g128>>>(p_pC,  gate_w1 + (size_t)Dn * Dn, p_plvw, Bn * Ln, Dn, Dn, 1.f, 8, S);
    k_redN<<<S / 4 / 256, 256>>>((float4*)p_k2,  (const float4*)p_pk2,  S / 4, 8, S / 4);
    k_redN<<<S / 4 / 256, 256>>>((float4*)p_lvw, (const float4*)p_plvw, S / 4, 8, S / 4);

    // P-path reduction
    k_redsplit<<<(pl * 256 + 255) / 256, 256>>>(pl);

    // stage-2 attention weights
    k_s2<<<dim3((pl + 15) / 16, Bn), 256>>>(pl);

    // gate select + streaming expert combine
    const int smem_gs = (Ln * Dn + 16 * 1026 + Dn + 64 + 272 + 16) * 4;
    cudaFuncSetAttribute(k_gatesel, cudaFuncAttributeMaxDynamicSharedMemorySize, smem_gs);
    k_gatesel<<<dim3((pl + 7) / 8, Bn), 256, smem_gs>>>(gate_w2, gate_b2, gate_b1, pl);
    k_combine<<<pl, 256>>>(qexp, out, pl, Pfull);
}

// round 8
// speedup vs baseline: 1.1514x; 1.1514x over previous
#include <cuda_runtime.h>
#include <math.h>
#include <stdint.h>

#define Bn 32
#define Tn 2048
#define Dn 1024
#define En 16
#define Ln 8
#define Pmax 720
#define SUBSEG 32
#define NSUB 4
#define NPART 16

typedef unsigned long long ull;

__device__ __forceinline__ void fma2(ull& d, ull a, ull b) {
    asm("fma.rn.f32x2 %0, %1, %2, %0;" : "+l"(d) : "l"(a), "l"(b));
}
__device__ __forceinline__ float2 u2f(ull v) {
    float2 f; asm("mov.b64 {%0,%1}, %2;" : "=f"(f.x), "=f"(f.y) : "l"(v)); return f;
}
__device__ __forceinline__ float gelu_f(float x) {
    return 0.5f * x * (1.0f + erff(x * 0.70710678118654752440f));
}

// ---------------- scratch ----------------
__device__ float g_step_base[Pmax * Dn];
__device__ float g_t1p[8 * Ln * Dn];
__device__ float g_qeffp[8 * Ln * Dn];
__device__ float g_qeff[Ln * Dn];
__device__ float g_ssum[Bn * Ln * NPART];
__device__ float g_upart[(size_t)NPART * Bn * Ln * Dn];
__device__ float g_U[Bn * Ln * Dn];
__device__ float g_pA[8 * Bn * Ln * Dn];
__device__ float g_pLC[8 * Bn * Ln * Dn];
__device__ float g_pk2[8 * Bn * Ln * Dn];
__device__ float g_pB[8 * Bn * Ln * Dn];
__device__ float g_pC[8 * Bn * Ln * Dn];
__device__ float g_plvw[8 * Bn * Ln * Dn];
__device__ float g_k2[Bn * Ln * Dn];
__device__ float g_lvw[Bn * Ln * Dn];
__device__ float g_bcat[Dn * 2048];
__device__ float g_pcat[2 * Pmax * 2048];
__device__ float g_qb2[Pmax * Dn];
__device__ float g_bh[Pmax * Dn];
__device__ float g_A2[Bn * Pmax * Ln];
__device__ float4 g_sel[Bn * Pmax];

// ---------------- step_base ----------------
__global__ void k_stepbase(const float* __restrict__ qpos,
                           const float* __restrict__ tbl, int pl) {
    int i = blockIdx.x * 256 + threadIdx.x;
    if (i < pl * Dn)
        g_step_base[i] = qpos[i] + tbl[(size_t)pl * Dn + (i & (Dn - 1))];
}

// ---------------- pack B for the fused P-GEMM ----------------
__global__ void k_pack(const float* __restrict__ sqw, const float* __restrict__ gw1,
                       float alpha) {
    int i = blockIdx.x * 256 + threadIdx.x;
    int row = i >> 9;
    int c4 = i & 511;
    float4 v;
    if (c4 < 256) {
        v = ((const float4*)sqw)[row * 256 + c4];
        v.x *= alpha; v.y *= alpha; v.z *= alpha; v.w *= alpha;
    } else {
        v = ((const float4*)gw1)[row * 256 + (c4 - 256)];
    }
    ((float4*)g_bcat)[i] = v;
}

// ---------------- 64x64 fp32x2 GEMM (known-good R6 class) ----------------
#define GEMM_PREFETCH(k0)                                                        \
    {                                                                            \
        for (int r = 0; r < 4; r++) {                                            \
            int i = tid + 256 * r;                                               \
            int row = i >> 4, col = i & 15;                                      \
            int gm = m0 + row;                                                   \
            float v = 0.f;                                                       \
            if (gm < M) {                                                        \
                size_t off = (size_t)gm * K + (k0) + col;                        \
                v = A[off];                                                      \
                for (int s = 1; s < nsumA; s++) v += A[off + (size_t)s * strideA]; \
            }                                                                    \
            ra[r] = v;                                                           \
        }                                                                        \
        if (!transB) {                                                           \
            for (int r = 0; r < 4; r++) {                                        \
                int i = tid + 256 * r;                                           \
                rb[r] = B[(size_t)((k0) + (i >> 6)) * N + n0 + (i & 63)];        \
            }                                                                    \
        } else {                                                                 \
            for (int r = 0; r < 4; r++) {                                        \
                int i = tid + 256 * r;                                           \
                rb[r] = B[(size_t)(n0 + (i >> 4)) * K + (k0) + (i & 15)];        \
            }                                                                    \
        }                                                                        \
    }

#define GEMM_STORE(bf)                                                           \
    {                                                                            \
        for (int r = 0; r < 4; r++) {                                            \
            int i = tid + 256 * r;                                               \
            *(float2*)&As2[bf][i & 15][2 * (i >> 4)] = make_float2(ra[r], ra[r]); \
        }                                                                        \
        if (!transB) {                                                           \
            for (int r = 0; r < 4; r++) {                                        \
                int i = tid + 256 * r;                                           \
                Bs[bf][i >> 6][i & 63] = rb[r];                                  \
            }                                                                    \
        } else {                                                                 \
            for (int r = 0; r < 4; r++) {                                        \
                int i = tid + 256 * r;                                           \
                Bs[bf][i & 15][i >> 4] = rb[r];                                  \
            }                                                                    \
        }                                                                        \
    }

#define GEMM_COMPUTE(bf)                                                         \
    {                                                                            \
        _Pragma("unroll")                                                        \
        for (int kk = 0; kk < 16; kk++) {                                        \
            ulonglong2 a01 = *(const ulonglong2*)&As2[bf][kk][ty * 8];           \
            ulonglong2 a23 = *(const ulonglong2*)&As2[bf][kk][ty * 8 + 4];       \
            ulonglong2 bb  = *(const ulonglong2*)&Bs[bf][kk][tx * 4];            \
            fma2(acc[0][0], a01.x, bb.x); fma2(acc[0][1], a01.x, bb.y);          \
            fma2(acc[1][0], a01.y, bb.x); fma2(acc[1][1], a01.y, bb.y);          \
            fma2(acc[2][0], a23.x, bb.x); fma2(acc[2][1], a23.x, bb.y);          \
            fma2(acc[3][0], a23.y, bb.x); fma2(acc[3][1], a23.y, bb.y);          \
        }                                                                        \
    }

__global__ void k_gemm(const float* __restrict__ A, const float* __restrict__ B,
                       float* __restrict__ C, int M, int N, int K,
                       int transB, const float* __restrict__ bias, float alpha,
                       int nsumA, int strideA) {
    __shared__ float As2[2][16][136];
    __shared__ float Bs[2][16][68];
    int tid = threadIdx.x;
    int tx = tid & 15, ty = tid >> 4;
    int m0 = blockIdx.y * 64, n0 = blockIdx.x * 64;
    int kper = K / gridDim.z;
    int kbeg = blockIdx.z * kper;
    C += (size_t)blockIdx.z * M * N;
    int nk = kper / 16;

    ull acc[4][2];
#pragma unroll
    for (int i = 0; i < 4; i++) { acc[i][0] = 0ULL; acc[i][1] = 0ULL; }

    float ra[4], rb[4];
    int buf = 0;
    GEMM_PREFETCH(kbeg);
    GEMM_STORE(0);
    __syncthreads();
    for (int kt = 0; kt < nk; kt++) {
        if (kt + 1 < nk) GEMM_PREFETCH(kbeg + (kt + 1) * 16);
        GEMM_COMPUTE(buf);
        if (kt + 1 < nk) {
            GEMM_STORE(buf ^ 1);
            __syncthreads();
            buf ^= 1;
        }
    }
#pragma unroll
    for (int i = 0; i < 4; i++) {
        int m = m0 + ty * 4 + i;
        if (m >= M) continue;
        float2 p0 = u2f(acc[i][0]), p1 = u2f(acc[i][1]);
        float4 o;
        o.x = alpha * p0.x; o.y = alpha * p0.y;
        o.z = alpha * p1.x; o.w = alpha * p1.y;
        if (bias) {
            o.x += bias[n0 + tx * 4];     o.y += bias[n0 + tx * 4 + 1];
            o.z += bias[n0 + tx * 4 + 2]; o.w += bias[n0 + tx * 4 + 3];
        }
        *(float4*)&C[(size_t)m * N + n0 + tx * 4] = o;
    }
}

// ---------------- generic partial reduction ----------------
__global__ void k_redN(float4* __restrict__ dst, const float4* __restrict__ src,
                       int n4, int nparts, int stride4) {
    int i = blockIdx.x * 256 + threadIdx.x;
    if (i >= n4) return;
    float4 s = src[i];
    for (int p = 1; p < nparts; p++) {
        float4 t = src[i + (size_t)p * stride4];
        s.x += t.x; s.y += t.y; s.z += t.z; s.w += t.w;
    }
    dst[i] = s;
}

// ---------------- de-interleave + reduce the packed P-GEMM ----------------
__global__ void k_redsplit(int pl) {
    int i = blockIdx.x * 256 + threadIdx.x;
    if (i >= pl * 256) return;
    int p = i >> 8, d4 = i & 255;
    const float4* s = (const float4*)g_pcat;
    size_t base = (size_t)p * 512 + d4;
    size_t part = (size_t)pl * 512;
    float4 a = s[base], b = s[base + part];
    float4 c = s[base + 256], d = s[base + 256 + part];
    float4 q, h;
    q.x = a.x + b.x; q.y = a.y + b.y; q.z = a.z + b.z; q.w = a.w + b.w;
    h.x = c.x + d.x; h.y = c.y + d.y; h.z = c.z + d.z; h.w = c.w + d.w;
    ((float4*)g_qb2)[i] = q;
    ((float4*)g_bh)[i] = h;
}

// ---------------- fused stage-1 (single DRAM pass, 512 threads) -------------------
__global__ void __launch_bounds__(512) k_fused1(const float* __restrict__ ctx) {
    extern __shared__ float smf[];
    float* qs  = smf;                    // 8*1024
    float* ck  = qs + Ln * Dn;           // 32*1024
    float* ps2 = ck + SUBSEG * Dn;       // [tt][2l] dup pairs: 32*16
    float* prt = ps2 + SUBSEG * 16;      // 32 tt * 16 (l*2+h)
    int tid = threadIdx.x;
    for (int i = tid; i < Ln * Dn / 4; i += 512)
        ((float4*)qs)[i] = ((const float4*)g_qeff)[i];
    int b = blockIdx.y;
    int w = tid >> 5, lane = tid & 31;
    int g = w >> 1, h = w & 1;

    ull uacc[Ln];
#pragma unroll
    for (int l = 0; l < Ln; l++) uacc[l] = 0ULL;
    float ssum = 0.f;

    for (int sub = 0; sub < NSUB; sub++) {
        int t0 = (blockIdx.x * NSUB + sub) * SUBSEG;
        const float* base = ctx + ((size_t)b * Tn + t0 + g * 4) * Dn + h * 512;
        __syncthreads();

        // phase A: 4 token rows x half-d per warp
        ull acc[4][Ln];
#pragma unroll
        for (int tt = 0; tt < 4; tt++)
#pragma unroll
            for (int l = 0; l < Ln; l++) acc[tt][l] = 0ULL;
#pragma unroll
        for (int i = 0; i < 4; i++) {
            int d = (lane + 32 * i) * 4;
            ulonglong2 c0 = *(const ulonglong2*)(base + d);
            ulonglong2 c1 = *(const ulonglong2*)(base + Dn + d);
            ulonglong2 c2 = *(const ulonglong2*)(base + 2 * Dn + d);
            ulonglong2 c3 = *(const ulonglong2*)(base + 3 * Dn + d);
            int ckd = h * 512 + d;
            *(ulonglong2*)&ck[(g * 4 + 0) * Dn + ckd] = c0;
            *(ulonglong2*)&ck[(g * 4 + 1) * Dn + ckd] = c1;
            *(ulonglong2*)&ck[(g * 4 + 2) * Dn + ckd] = c2;
            *(ulonglong2*)&ck[(g * 4 + 3) * Dn + ckd] = c3;
#pragma unroll
            for (int l = 0; l < Ln; l++) {
                ulonglong2 q = *(const ulonglong2*)&qs[l * Dn + ckd];
                fma2(acc[0][l], c0.x, q.x); fma2(acc[0][l], c0.y, q.y);
                fma2(acc[1][l], c1.x, q.x); fma2(acc[1][l], c1.y, q.y);
                fma2(acc[2][l], c2.x, q.x); fma2(acc[2][l], c2.y, q.y);
                fma2(acc[3][l], c3.x, q.x); fma2(acc[3][l], c3.y, q.y);
            }
        }
#pragma unroll
        for (int tt = 0; tt < 4; tt++)
#pragma unroll
            for (int l = 0; l < Ln; l++) {
                float2 f = u2f(acc[tt][l]);
                float v = f.x + f.y;
                for (int off = 16; off; off >>= 1)
                    v += __shfl_xor_sync(0xffffffffu, v, off);
                if (lane == 0)
                    prt[(g * 4 + tt) * 16 + l * 2 + h] = v;
            }
        __syncthreads();

        // finalize: exp (shift-free softmax; scores tiny, clamp for safety)
        if (tid < 256) {
            int tt = tid >> 3, l = tid & 7;
            float v = prt[tt * 16 + l * 2] + prt[tt * 16 + l * 2 + 1];
            float e = expf(fminf(v, 60.0f));
            ps2[tt * 16 + 2 * l] = e;
            ps2[tt * 16 + 2 * l + 1] = e;
        }
        __syncthreads();

        // phase B: warps 0-7 accumulate exp-sum for l = w (lane = tt)
        if (w < Ln) {
            float s = ps2[lane * 16 + 2 * w];
            for (int off = 16; off; off >>= 1)
                s += __shfl_xor_sync(0xffffffffu, s, off);
            ssum += s;
        }

        // phase C: U accumulation; probs as 4 broadcast LDS.128 per token
        int d2 = tid * 2;
#pragma unroll 2
        for (int tt = 0; tt < SUBSEG; tt++) {
            ull c = *(const ull*)&ck[tt * Dn + d2];
            ulonglong2 p01 = *(const ulonglong2*)&ps2[tt * 16];
            ulonglong2 p23 = *(const ulonglong2*)&ps2[tt * 16 + 4];
            ulonglong2 p45 = *(const ulonglong2*)&ps2[tt * 16 + 8];
            ulonglong2 p67 = *(const ulonglong2*)&ps2[tt * 16 + 12];
            fma2(uacc[0], p01.x, c); fma2(uacc[1], p01.y, c);
            fma2(uacc[2], p23.x, c); fma2(uacc[3], p23.y, c);
            fma2(uacc[4], p45.x, c); fma2(uacc[5], p45.y, c);
            fma2(uacc[6], p67.x, c); fma2(uacc[7], p67.y, c);
        }
    }
#pragma unroll
    for (int l = 0; l < Ln; l++) {
        float2 f = u2f(uacc[l]);
        *(float2*)&g_upart[(((size_t)blockIdx.x * Bn + b) * Ln + l) * Dn + tid * 2] = f;
    }
    if (w < Ln && lane == 0)
        g_ssum[((size_t)b * Ln + w) * NPART + blockIdx.x] = ssum;
}

// ---------------- combine stage-1 partials ----------------
__global__ void k_comb1() {
    __shared__ float inv[Ln];
    int b = blockIdx.y, dc = blockIdx.x;
    int tid = threadIdx.x;
    if (tid < Ln) {
        float s0 = 0.f, s1 = 0.f, s2 = 0.f, s3 = 0.f;
#pragma unroll
        for (int g = 0; g < NPART; g += 4) {
            s0 += g_ssum[((size_t)b * Ln + tid) * NPART + g];
            s1 += g_ssum[((size_t)b * Ln + tid) * NPART + g + 1];
            s2 += g_ssum[((size_t)b * Ln + tid) * NPART + g + 2];
            s3 += g_ssum[((size_t)b * Ln + tid) * NPART + g + 3];
        }
        inv[tid] = 1.0f / ((s0 + s1) + (s2 + s3));
    }
    __syncthreads();
    int dg = dc * 256 + tid;
#pragma unroll
    for (int l = 0; l < Ln; l++) {
        float a0 = 0.f, a1 = 0.f, a2 = 0.f, a3 = 0.f;
#pragma unroll
        for (int s = 0; s < NPART; s += 4) {
            a0 += g_upart[(((size_t)(s + 0) * Bn + b) * Ln + l) * Dn + dg];
            a1 += g_upart[(((size_t)(s + 1) * Bn + b) * Ln + l) * Dn + dg];
            a2 += g_upart[(((size_t)(s + 2) * Bn + b) * Ln + l) * Dn + dg];
            a3 += g_upart[(((size_t)(s + 3) * Bn + b) * Ln + l) * Dn + dg];
        }
        g_U[((size_t)b * Ln + l) * Dn + dg] = ((a0 + a1) + (a2 + a3)) * inv[l];
    }
}

// ---------------- stage-2 scores + softmax over L=8 ----------------
__global__ void k_s2(int pl) {
    __shared__ float ks[Ln][Dn];
    int tid = threadIdx.x, b = blockIdx.y;
    for (int i = tid; i < Ln * Dn / 4; i += 256)
        ((float4*)ks)[i] = ((const float4*)(g_k2 + (size_t)b * Ln * Dn))[i];
    __syncthreads();
    int w = tid >> 5, lane = tid & 31;
    int p0 = blockIdx.x * 16 + w * 2;
    if (p0 > pl - 2) p0 = pl - 2;
    ull acc[2][Ln];
#pragma unroll
    for (int pp = 0; pp < 2; pp++)
#pragma unroll
        for (int l = 0; l < Ln; l++) acc[pp][l] = 0ULL;
#pragma unroll
    for (int i = 0; i < 8; i++) {
        int d = (lane + 32 * i) * 4;
        ulonglong2 q0 = *(const ulonglong2*)(g_qb2 + (size_t)p0 * Dn + d);
        ulonglong2 q1 = *(const ulonglong2*)(g_qb2 + (size_t)(p0 + 1) * Dn + d);
#pragma unroll
        for (int l = 0; l < Ln; l++) {
            ulonglong2 k = *(const ulonglong2*)&ks[l][d];
            fma2(acc[0][l], q0.x, k.x); fma2(acc[0][l], q0.y, k.y);
            fma2(acc[1][l], q1.x, k.x); fma2(acc[1][l], q1.y, k.y);
        }
    }
#pragma unroll
    for (int pp = 0; pp < 2; pp++) {
        float v[Ln];
#pragma unroll
        for (int l = 0; l < Ln; l++) {
            float2 f = u2f(acc[pp][l]);
            float s = f.x + f.y;
            for (int off = 16; off; off >>= 1)
                s += __shfl_xor_sync(0xffffffffu, s, off);
            v[l] = s;
        }
        if (lane == 0) {
            int p = p0 + pp;
            if (p < pl) {
                float m = v[0];
#pragma unroll
                for (int l = 1; l < Ln; l++) m = fmaxf(m, v[l]);
                float e[Ln], s = 0.f;
#pragma unroll
                for (int l = 0; l < Ln; l++) { e[l] = expf(v[l] - m); s += e[l]; }
                float inv = 1.0f / s;
#pragma unroll
                for (int l = 0; l < Ln; l++)
                    g_A2[((size_t)b * pl + p) * Ln + l] = e[l] * inv;
            }
        }
    }
}

// ---------------- gate select ----------------
__global__ void k_gatesel(const float* __restrict__ w2, const float* __restrict__ b2,
                          const float* __restrict__ b1, int pl) {
    extern __shared__ float sm[];
    float* lvws = sm;
    float* w2T  = lvws + Ln * Dn;
    float* hs   = w2T + 16 * 1026;
    float* a2s  = hs + Dn;
    float* part = a2s + 64;
    float* lg   = part + 272;
    int tid = threadIdx.x, b = blockIdx.y, p0 = blockIdx.x * 8;
    for (int i = tid; i < Ln * Dn / 4; i += 256)
        ((float4*)lvws)[i] = ((const float4*)(g_lvw + (size_t)b * Ln * Dn))[i];
    for (int i = tid; i < Dn * En; i += 256) {
        int d = i >> 4, e = i & 15;
        w2T[e * 1026 + d] = w2[i];
    }
    if (tid < 64) {
        int pi = tid >> 3, l = tid & 7;
        int p = p0 + pi;
        a2s[tid] = (p < pl) ? g_A2[((size_t)b * pl + p) * Ln + l] : 0.f;
    }
    float4 bh4[8];
#pragma unroll
    for (int pi = 0; pi < 8; pi++) {
        int p = p0 + pi;
        bh4[pi] = (p < pl) ? *(const float4*)(g_bh + (size_t)p * Dn + tid * 4)
                           : make_float4(0, 0, 0, 0);
    }
    float4 b1v = *(const float4*)(b1 + tid * 4);
    __syncthreads();
    int e_id = tid & 15, dseg = tid >> 4;
    for (int pi = 0; pi < 8; pi++) {
        int p = p0 + pi;
        if (p >= pl) break;
        float4 s4 = bh4[pi];
        s4.x += b1v.x; s4.y += b1v.y; s4.z += b1v.z; s4.w += b1v.w;
#pragma unroll
        for (int l = 0; l < Ln; l++) {
            float a = a2s[pi * 8 + l];
            float4 v = ((const float4*)lvws)[l * (Dn / 4) + tid];
            s4.x += a * v.x; s4.y += a * v.y; s4.z += a * v.z; s4.w += a * v.w;
        }
        float4 h4;
        h4.x = gelu_f(s4.x); h4.y = gelu_f(s4.y);
        h4.z = gelu_f(s4.z); h4.w = gelu_f(s4.w);
        ((float4*)hs)[tid] = h4;
        __syncthreads();
        ull lacc = 0ULL;
        int dbase = dseg * 64;
#pragma unroll
        for (int j = 0; j < 32; j++) {
            ull h2 = *(const ull*)&hs[dbase + 2 * j];
            ull wv = *(const ull*)&w2T[e_id * 1026 + dbase + 2 * j];
            fma2(lacc, h2, wv);
        }
        float2 lf = u2f(lacc);
        part[dseg * 17 + e_id] = lf.x + lf.y;
        __syncthreads();
        if (tid < En) {
            float L = b2[tid];
#pragma unroll
            for (int g = 0; g < 16; g++) L += part[g * 17 + tid];
            lg[tid] = L;
        }
        __syncthreads();
        if (tid == 0) {
            float b1s = lg[0]; int e1 = 0;
#pragma unroll
            for (int e = 1; e < En; e++) if (lg[e] > b1s) { b1s = lg[e]; e1 = e; }
            float b2s = -3.4e38f; int e2 = 0;
#pragma unroll
            for (int e = 0; e < En; e++)
                if (e != e1 && lg[e] > b2s) { b2s = lg[e]; e2 = e; }
            float x2 = expf(b2s - b1s);
            float s = 1.f + x2;
            g_sel[(size_t)b * pl + p] = make_float4(
                1.f / s, x2 / s, __int_as_float(e1), __int_as_float(e2));
        }
        __syncthreads();
    }
}

// ---------------- combine experts ----------------
__global__ void k_combine(const float* __restrict__ qexp, float* __restrict__ out,
                          int pl, int Pfull) {
    __shared__ float4 sel[Bn];
    int p = blockIdx.x, tid = threadIdx.x;
    if (tid < Bn) sel[tid] = g_sel[(size_t)tid * pl + p];
    __syncthreads();
#pragma unroll 4
    for (int b = 0; b < Bn; b++) {
        float4 s = sel[b];
        int eA = __float_as_int(s.z), eB = __float_as_int(s.w);
        float4 va = *(const float4*)(qexp + ((size_t)eA * Pfull + p) * Dn + tid * 4);
        float4 vb = *(const float4*)(qexp + ((size_t)eB * Pfull + p) * Dn + tid * 4);
        float4 o;
        o.x = s.x * va.x + s.y * vb.x;
        o.y = s.x * va.y + s.y * vb.y;
        o.z = s.x * va.z + s.y * vb.z;
        o.w = s.x * va.w + s.y * vb.w;
        *(float4*)(out + ((size_t)b * pl + p) * Dn + tid * 4) = o;
    }
}

// ---------------- launch ----------------
extern "C" void kernel_launch(void* const* d_in, const int* in_sizes, int n_in,
                              void* d_out, int out_size) {
    const float* ctx        = (const float*)d_in[0];
    const float* qexp       = (const float*)d_in[1];
    const float* qpos       = (const float*)d_in[2];
    const float* ptbl       = (const float*)d_in[3];
    const float* lats       = (const float*)d_in[4];
    const float* lat_q_w    = (const float*)d_in[5];
    const float* ctx_k_w    = (const float*)d_in[6];
    const float* ctx_v_w    = (const float*)d_in[7];
    const float* lat_out_w  = (const float*)d_in[8];
    const float* step_q_w   = (const float*)d_in[9];
    const float* lat_k_w    = (const float*)d_in[10];
    const float* lat_v_w    = (const float*)d_in[11];
    const float* step_out_w = (const float*)d_in[12];
    const float* gate_w1    = (const float*)d_in[13];
    const float* gate_b1    = (const float*)d_in[14];
    const float* gate_w2    = (const float*)d_in[15];
    const float* gate_b2    = (const float*)d_in[16];
    float* out = (float*)d_out;

    int pl = out_size / (Bn * Dn);
    int Pfull = in_sizes[2] / Dn;

    float *p_t1p, *p_qeffp, *p_qeff, *p_U;
    float *p_pA, *p_pLC, *p_pk2, *p_pB, *p_pC, *p_plvw;
    float *p_k2, *p_lvw, *p_sb, *p_bcat, *p_pcat;
    cudaGetSymbolAddress((void**)&p_t1p, g_t1p);
    cudaGetSymbolAddress((void**)&p_qeffp, g_qeffp);
    cudaGetSymbolAddress((void**)&p_qeff, g_qeff);
    cudaGetSymbolAddress((void**)&p_U, g_U);
    cudaGetSymbolAddress((void**)&p_pA, g_pA);
    cudaGetSymbolAddress((void**)&p_pLC, g_pLC);
    cudaGetSymbolAddress((void**)&p_pk2, g_pk2);
    cudaGetSymbolAddress((void**)&p_pB, g_pB);
    cudaGetSymbolAddress((void**)&p_pC, g_pC);
    cudaGetSymbolAddress((void**)&p_plvw, g_plvw);
    cudaGetSymbolAddress((void**)&p_k2, g_k2);
    cudaGetSymbolAddress((void**)&p_lvw, g_lvw);
    cudaGetSymbolAddress((void**)&p_sb, g_step_base);
    cudaGetSymbolAddress((void**)&p_bcat, g_bcat);
    cudaGetSymbolAddress((void**)&p_pcat, g_pcat);

    const float inv_sqrt_d = 0.03125f;
    const int S = Bn * Ln * Dn;

    // 0-2: batch-independent prep + first qeff GEMM
    k_stepbase<<<(pl * Dn + 255) / 256, 256>>>(qpos, ptbl, pl);
    k_pack<<<Dn * 2048 / 4 / 256, 256>>>(step_q_w, gate_w1, inv_sqrt_d);
    k_gemm<<<dim3(16, 1, 8), 256>>>(lats, lat_q_w, p_t1p, Ln, Dn, Dn, 0, nullptr, 1.f, 1, 0);

    // 3 (ncu-sampled slot): packed [720,2048,1024] P-GEMM, 64-tile class, 768 blocks
    int gy = (pl + 63) / 64;
    k_gemm<<<dim3(32, gy, 2), 256>>>(p_sb, p_bcat, p_pcat, pl, 2048, Dn, 0, nullptr, 1.f, 1, 0);

    // qeff finish
    k_gemm<<<dim3(16, 1, 8), 256>>>(p_t1p, ctx_k_w, p_qeffp, Ln, Dn, Dn, 1, nullptr, inv_sqrt_d, 8, Ln * Dn);
    k_redN<<<8, 256>>>((float4*)p_qeff, (const float4*)p_qeffp, Ln * Dn / 4, 8, Ln * Dn / 4);

    // fused stage-1 (single DRAM pass over ctx)
    const int smem_f1 = (Ln * Dn + SUBSEG * Dn + SUBSEG * 16 + SUBSEG * 16) * 4;
    cudaFuncSetAttribute(k_fused1, cudaFuncAttributeMaxDynamicSharedMemorySize, smem_f1);
    k_fused1<<<dim3(NPART, Bn), 512, smem_f1>>>(ctx);
    k_comb1<<<dim3(4, Bn), 256>>>();

    // chain of [256,1024]x[1024,1024] GEMMs (64-tile, split-K x8, 512 blocks each)
    k_gemm<<<dim3(16, 4, 8), 256>>>(p_U,   ctx_v_w,    p_pA,   Bn * Ln, Dn, Dn, 0, nullptr, 1.f, 1, 0);
    k_gemm<<<dim3(16, 4, 8), 256>>>(p_pA,  lat_out_w,  p_pLC,  Bn * Ln, Dn, Dn, 0, nullptr, 1.f, 8, S);
    k_gemm<<<dim3(16, 4, 8), 256>>>(p_pLC, lat_k_w,    p_pk2,  Bn * Ln, Dn, Dn, 0, nullptr, 1.f, 8, S);
    k_gemm<<<dim3(16, 4, 8), 256>>>(p_pLC, lat_v_w,    p_pB,   Bn * Ln, Dn, Dn, 0, nullptr, 1.f, 8, S);
    k_gemm<<<dim3(16, 4, 8), 256>>>(p_pB,  step_out_w, p_pC,   Bn * Ln, Dn, Dn, 0, nullptr, 1.f, 8, S);
    k_gemm<<<dim3(16, 4, 8), 256>>>(p_pC,  gate_w1 + (size_t)Dn * Dn, p_plvw, Bn * Ln, Dn, Dn, 0, nullptr, 1.f, 8, S);
    k_redN<<<S / 4 / 256, 256>>>((float4*)p_k2,  (const float4*)p_pk2,  S / 4, 8, S / 4);
    k_redN<<<S / 4 / 256, 256>>>((float4*)p_lvw, (const float4*)p_plvw, S / 4, 8, S / 4);

    // P-path reduction
    k_redsplit<<<(pl * 256 + 255) / 256, 256>>>(pl);

    // stage-2 attention weights
    k_s2<<<dim3((pl + 15) / 16, Bn), 256>>>(pl);

    // gate select + streaming expert combine
    const int smem_gs = (Ln * Dn + 16 * 1026 + Dn + 64 + 272 + 16) * 4;
    cudaFuncSetAttribute(k_gatesel, cudaFuncAttributeMaxDynamicSharedMemorySize, smem_gs);
    k_gatesel<<<dim3((pl + 7) / 8, Bn), 256, smem_gs>>>(gate_w2, gate_b2, gate_b1, pl);
    k_combine<<<pl, 256>>>(qexp, out, pl, Pfull);
}

// round 9
// speedup vs baseline: 1.4027x; 1.2183x over previous
#include <cuda_runtime.h>
#include <math.h>
#include <stdint.h>

#define Bn 32
#define Tn 2048
#define Dn 1024
#define En 16
#define Ln 8
#define Pmax 720
#define SUBSEG 32
#define NSUB 4
#define NPART 16

typedef unsigned long long ull;

__device__ __forceinline__ void fma2(ull& d, ull a, ull b) {
    asm("fma.rn.f32x2 %0, %1, %2, %0;" : "+l"(d) : "l"(a), "l"(b));
}
__device__ __forceinline__ float2 u2f(ull v) {
    float2 f; asm("mov.b64 {%0,%1}, %2;" : "=f"(f.x), "=f"(f.y) : "l"(v)); return f;
}
__device__ __forceinline__ ull pack2(float s) {
    ull d; asm("mov.b64 %0, {%1,%1};" : "=l"(d) : "f"(s)); return d;
}
__device__ __forceinline__ float gelu_f(float x) {
    return 0.5f * x * (1.0f + erff(x * 0.70710678118654752440f));
}

// ---------------- scratch ----------------
__device__ float g_step_base[Pmax * Dn];
__device__ float g_t1p[8 * Ln * Dn];
__device__ float g_qeffp[8 * Ln * Dn];
__device__ float g_qeff[Ln * Dn];
__device__ float g_ssum[Bn * Ln * NPART];
__device__ float g_upart[(size_t)NPART * Bn * Ln * Dn];
__device__ float g_U[Bn * Ln * Dn];
__device__ float g_pA[8 * Bn * Ln * Dn];
__device__ float g_pLC[8 * Bn * Ln * Dn];
__device__ float g_pk2[8 * Bn * Ln * Dn];
__device__ float g_pB[8 * Bn * Ln * Dn];
__device__ float g_pC[8 * Bn * Ln * Dn];
__device__ float g_plvw[8 * Bn * Ln * Dn];
__device__ float g_k2[Bn * Ln * Dn];
__device__ float g_lvw[Bn * Ln * Dn];
__device__ float g_bcat[Dn * 2048];
__device__ float g_pcat[4 * Pmax * 2048];
__device__ float g_qb2[Pmax * Dn];
__device__ float g_bh[Pmax * Dn];
__device__ float g_A2[Bn * Pmax * Ln];
__device__ float4 g_sel[Bn * Pmax];

// ---------------- step_base ----------------
__global__ void k_stepbase(const float* __restrict__ qpos,
                           const float* __restrict__ tbl, int pl) {
    int i = blockIdx.x * 256 + threadIdx.x;
    if (i < pl * Dn)
        g_step_base[i] = qpos[i] + tbl[(size_t)pl * Dn + (i & (Dn - 1))];
}

// ---------------- pack B for the fused P-GEMM ----------------
__global__ void k_pack(const float* __restrict__ sqw, const float* __restrict__ gw1,
                       float alpha) {
    int i = blockIdx.x * 256 + threadIdx.x;
    int row = i >> 9;
    int c4 = i & 511;
    float4 v;
    if (c4 < 256) {
        v = ((const float4*)sqw)[row * 256 + c4];
        v.x *= alpha; v.y *= alpha; v.z *= alpha; v.w *= alpha;
    } else {
        v = ((const float4*)gw1)[row * 256 + (c4 - 256)];
    }
    ((float4*)g_bcat)[i] = v;
}

// ---------------- 64x64 fp32x2 GEMM v2: non-dup A, float4 prefetch ----------------
// smem As/Bs [2][16][68]. 256 threads, 4x4 microtile, A pairs built via mov.b64.
__global__ void k_gemm(const float* __restrict__ A, const float* __restrict__ B,
                       float* __restrict__ C, int M, int N, int K,
                       int transB, const float* __restrict__ bias, float alpha,
                       int nsumA, int strideA) {
    __shared__ float As[2][16][68];
    __shared__ float Bs[2][16][68];
    int tid = threadIdx.x;
    int tx = tid & 15, ty = tid >> 4;
    int m0 = blockIdx.y * 64, n0 = blockIdx.x * 64;
    int kper = K / gridDim.z;
    int kbeg = blockIdx.z * kper;
    C += (size_t)blockIdx.z * M * N;
    int nk = kper / 16;

    ull acc[4][2];
#pragma unroll
    for (int i = 0; i < 4; i++) { acc[i][0] = 0ULL; acc[i][1] = 0ULL; }

    // prefetch registers
    float4 va, vb4;          // vector path (!transB)
    float ra[4], rb[4];      // scalar path (transB)
    int am = tid >> 2, ak4 = tid & 3;       // A: one float4 (4 k) per thread
    int bk = tid >> 4, bn4 = tid & 15;      // B: one float4 (4 n) per thread

#define PREF_V(k0)                                                               \
    {                                                                            \
        int gm = m0 + am;                                                        \
        va = make_float4(0.f, 0.f, 0.f, 0.f);                                    \
        if (gm < M) {                                                            \
            const float* ap = A + (size_t)gm * K + (k0) + ak4 * 4;               \
            va = *(const float4*)ap;                                             \
            for (int s = 1; s < nsumA; s++) {                                    \
                float4 t = *(const float4*)(ap + (size_t)s * strideA);           \
                va.x += t.x; va.y += t.y; va.z += t.z; va.w += t.w;              \
            }                                                                    \
        }                                                                        \
        vb4 = *(const float4*)(B + (size_t)((k0) + bk) * N + n0 + bn4 * 4);      \
    }
#define STORE_V(bf)                                                              \
    {                                                                            \
        As[bf][ak4 * 4 + 0][am] = va.x;                                          \
        As[bf][ak4 * 4 + 1][am] = va.y;                                          \
        As[bf][ak4 * 4 + 2][am] = va.z;                                          \
        As[bf][ak4 * 4 + 3][am] = va.w;                                          \
        *(float4*)&Bs[bf][bk][bn4 * 4] = vb4;                                    \
    }
#define PREF_S(k0)                                                               \
    {                                                                            \
        for (int r = 0; r < 4; r++) {                                            \
            int i = tid + 256 * r;                                               \
            int row = i >> 4, col = i & 15;                                      \
            int gm = m0 + row;                                                   \
            float v = 0.f;                                                       \
            if (gm < M) {                                                        \
                size_t off = (size_t)gm * K + (k0) + col;                        \
                v = A[off];                                                      \
                for (int s = 1; s < nsumA; s++) v += A[off + (size_t)s * strideA]; \
            }                                                                    \
            ra[r] = v;                                                           \
        }                                                                        \
        for (int r = 0; r < 4; r++) {                                            \
            int i = tid + 256 * r;                                               \
            rb[r] = B[(size_t)(n0 + (i >> 4)) * K + (k0) + (i & 15)];            \
        }                                                                        \
    }
#define STORE_S(bf)                                                              \
    {                                                                            \
        for (int r = 0; r < 4; r++) {                                            \
            int i = tid + 256 * r;                                               \
            As[bf][i & 15][i >> 4] = ra[r];                                      \
        }                                                                        \
        for (int r = 0; r < 4; r++) {                                            \
            int i = tid + 256 * r;                                               \
            Bs[bf][i & 15][i >> 4] = rb[r];                                      \
        }                                                                        \
    }
#define COMPUTE(bf)                                                              \
    {                                                                            \
        _Pragma("unroll")                                                        \
        for (int kk = 0; kk < 16; kk++) {                                        \
            float4 a4 = *(const float4*)&As[bf][kk][ty * 4];                     \
            ulonglong2 bb = *(const ulonglong2*)&Bs[bf][kk][tx * 4];             \
            ull a0 = pack2(a4.x), a1 = pack2(a4.y);                              \
            ull a2 = pack2(a4.z), a3 = pack2(a4.w);                              \
            fma2(acc[0][0], a0, bb.x); fma2(acc[0][1], a0, bb.y);                \
            fma2(acc[1][0], a1, bb.x); fma2(acc[1][1], a1, bb.y);                \
            fma2(acc[2][0], a2, bb.x); fma2(acc[2][1], a2, bb.y);                \
            fma2(acc[3][0], a3, bb.x); fma2(acc[3][1], a3, bb.y);                \
        }                                                                        \
    }

    int buf = 0;
    if (!transB) {
        PREF_V(kbeg);
        STORE_V(0);
        __syncthreads();
        for (int kt = 0; kt < nk; kt++) {
            if (kt + 1 < nk) PREF_V(kbeg + (kt + 1) * 16);
            COMPUTE(buf);
            if (kt + 1 < nk) {
                STORE_V(buf ^ 1);
                __syncthreads();
                buf ^= 1;
            }
        }
    } else {
        PREF_S(kbeg);
        STORE_S(0);
        __syncthreads();
        for (int kt = 0; kt < nk; kt++) {
            if (kt + 1 < nk) PREF_S(kbeg + (kt + 1) * 16);
            COMPUTE(buf);
            if (kt + 1 < nk) {
                STORE_S(buf ^ 1);
                __syncthreads();
                buf ^= 1;
            }
        }
    }
#pragma unroll
    for (int i = 0; i < 4; i++) {
        int m = m0 + ty * 4 + i;
        if (m >= M) continue;
        float2 p0 = u2f(acc[i][0]), p1 = u2f(acc[i][1]);
        float4 o;
        o.x = alpha * p0.x; o.y = alpha * p0.y;
        o.z = alpha * p1.x; o.w = alpha * p1.y;
        if (bias) {
            o.x += bias[n0 + tx * 4];     o.y += bias[n0 + tx * 4 + 1];
            o.z += bias[n0 + tx * 4 + 2]; o.w += bias[n0 + tx * 4 + 3];
        }
        *(float4*)&C[(size_t)m * N + n0 + tx * 4] = o;
    }
}

// ---------------- generic partial reduction ----------------
__global__ void k_redN(float4* __restrict__ dst, const float4* __restrict__ src,
                       int n4, int nparts, int stride4) {
    int i = blockIdx.x * 256 + threadIdx.x;
    if (i >= n4) return;
    float4 s = src[i];
    for (int p = 1; p < nparts; p++) {
        float4 t = src[i + (size_t)p * stride4];
        s.x += t.x; s.y += t.y; s.z += t.z; s.w += t.w;
    }
    dst[i] = s;
}

// ---------------- de-interleave + reduce the packed P-GEMM (4 partials) ----------
__global__ void k_redsplit(int pl) {
    int i = blockIdx.x * 256 + threadIdx.x;
    if (i >= pl * 256) return;
    int p = i >> 8, d4 = i & 255;
    const float4* s = (const float4*)g_pcat;
    size_t base = (size_t)p * 512 + d4;
    size_t part = (size_t)pl * 512;
    float4 q = s[base], h = s[base + 256];
#pragma unroll
    for (int z = 1; z < 4; z++) {
        float4 tq = s[base + z * part], th = s[base + 256 + z * part];
        q.x += tq.x; q.y += tq.y; q.z += tq.z; q.w += tq.w;
        h.x += th.x; h.y += th.y; h.z += th.z; h.w += th.w;
    }
    ((float4*)g_qb2)[i] = q;
    ((float4*)g_bh)[i] = h;
}

// ---------------- fused stage-1 (single DRAM pass, 512 threads) -------------------
__global__ void __launch_bounds__(512) k_fused1(const float* __restrict__ ctx) {
    extern __shared__ float smf[];
    float* qs  = smf;                    // 8*1024
    float* ck  = qs + Ln * Dn;           // 32*1024
    float* ps2 = ck + SUBSEG * Dn;       // [tt][2l] dup pairs: 32*16
    float* prt = ps2 + SUBSEG * 16;      // 32 tt * 16 (l*2+h)
    int tid = threadIdx.x;
    for (int i = tid; i < Ln * Dn / 4; i += 512)
        ((float4*)qs)[i] = ((const float4*)g_qeff)[i];
    int b = blockIdx.y;
    int w = tid >> 5, lane = tid & 31;
    int g = w >> 1, h = w & 1;

    ull uacc[Ln];
#pragma unroll
    for (int l = 0; l < Ln; l++) uacc[l] = 0ULL;
    float ssum = 0.f;

    for (int sub = 0; sub < NSUB; sub++) {
        int t0 = (blockIdx.x * NSUB + sub) * SUBSEG;
        const float* base = ctx + ((size_t)b * Tn + t0 + g * 4) * Dn + h * 512;
        __syncthreads();

        ull acc[4][Ln];
#pragma unroll
        for (int tt = 0; tt < 4; tt++)
#pragma unroll
            for (int l = 0; l < Ln; l++) acc[tt][l] = 0ULL;
#pragma unroll
        for (int i = 0; i < 4; i++) {
            int d = (lane + 32 * i) * 4;
            ulonglong2 c0 = *(const ulonglong2*)(base + d);
            ulonglong2 c1 = *(const ulonglong2*)(base + Dn + d);
            ulonglong2 c2 = *(const ulonglong2*)(base + 2 * Dn + d);
            ulonglong2 c3 = *(const ulonglong2*)(base + 3 * Dn + d);
            int ckd = h * 512 + d;
            *(ulonglong2*)&ck[(g * 4 + 0) * Dn + ckd] = c0;
            *(ulonglong2*)&ck[(g * 4 + 1) * Dn + ckd] = c1;
            *(ulonglong2*)&ck[(g * 4 + 2) * Dn + ckd] = c2;
            *(ulonglong2*)&ck[(g * 4 + 3) * Dn + ckd] = c3;
#pragma unroll
            for (int l = 0; l < Ln; l++) {
                ulonglong2 q = *(const ulonglong2*)&qs[l * Dn + ckd];
                fma2(acc[0][l], c0.x, q.x); fma2(acc[0][l], c0.y, q.y);
                fma2(acc[1][l], c1.x, q.x); fma2(acc[1][l], c1.y, q.y);
                fma2(acc[2][l], c2.x, q.x); fma2(acc[2][l], c2.y, q.y);
                fma2(acc[3][l], c3.x, q.x); fma2(acc[3][l], c3.y, q.y);
            }
        }
#pragma unroll
        for (int tt = 0; tt < 4; tt++)
#pragma unroll
            for (int l = 0; l < Ln; l++) {
                float2 f = u2f(acc[tt][l]);
                float v = f.x + f.y;
                for (int off = 16; off; off >>= 1)
                    v += __shfl_xor_sync(0xffffffffu, v, off);
                if (lane == 0)
                    prt[(g * 4 + tt) * 16 + l * 2 + h] = v;
            }
        __syncthreads();

        if (tid < 256) {
            int tt = tid >> 3, l = tid & 7;
            float v = prt[tt * 16 + l * 2] + prt[tt * 16 + l * 2 + 1];
            float e = expf(fminf(v, 60.0f));  // shift-free softmax (scores tiny)
            ps2[tt * 16 + 2 * l] = e;
            ps2[tt * 16 + 2 * l + 1] = e;
        }
        __syncthreads();

        if (w < Ln) {
            float s = ps2[lane * 16 + 2 * w];
            for (int off = 16; off; off >>= 1)
                s += __shfl_xor_sync(0xffffffffu, s, off);
            ssum += s;
        }

        int d2 = tid * 2;
#pragma unroll 2
        for (int tt = 0; tt < SUBSEG; tt++) {
            ull c = *(const ull*)&ck[tt * Dn + d2];
            ulonglong2 p01 = *(const ulonglong2*)&ps2[tt * 16];
            ulonglong2 p23 = *(const ulonglong2*)&ps2[tt * 16 + 4];
            ulonglong2 p45 = *(const ulonglong2*)&ps2[tt * 16 + 8];
            ulonglong2 p67 = *(const ulonglong2*)&ps2[tt * 16 + 12];
            fma2(uacc[0], p01.x, c); fma2(uacc[1], p01.y, c);
            fma2(uacc[2], p23.x, c); fma2(uacc[3], p23.y, c);
            fma2(uacc[4], p45.x, c); fma2(uacc[5], p45.y, c);
            fma2(uacc[6], p67.x, c); fma2(uacc[7], p67.y, c);
        }
    }
#pragma unroll
    for (int l = 0; l < Ln; l++) {
        float2 f = u2f(uacc[l]);
        *(float2*)&g_upart[(((size_t)blockIdx.x * Bn + b) * Ln + l) * Dn + tid * 2] = f;
    }
    if (w < Ln && lane == 0)
        g_ssum[((size_t)b * Ln + w) * NPART + blockIdx.x] = ssum;
}

// ---------------- combine stage-1 partials ----------------
__global__ void k_comb1() {
    __shared__ float inv[Ln];
    int b = blockIdx.y, dc = blockIdx.x;
    int tid = threadIdx.x;
    if (tid < Ln) {
        float s0 = 0.f, s1 = 0.f, s2 = 0.f, s3 = 0.f;
#pragma unroll
        for (int g = 0; g < NPART; g += 4) {
            s0 += g_ssum[((size_t)b * Ln + tid) * NPART + g];
            s1 += g_ssum[((size_t)b * Ln + tid) * NPART + g + 1];
            s2 += g_ssum[((size_t)b * Ln + tid) * NPART + g + 2];
            s3 += g_ssum[((size_t)b * Ln + tid) * NPART + g + 3];
        }
        inv[tid] = 1.0f / ((s0 + s1) + (s2 + s3));
    }
    __syncthreads();
    int dg = dc * 256 + tid;
#pragma unroll
    for (int l = 0; l < Ln; l++) {
        float a0 = 0.f, a1 = 0.f, a2 = 0.f, a3 = 0.f;
#pragma unroll
        for (int s = 0; s < NPART; s += 4) {
            a0 += g_upart[(((size_t)(s + 0) * Bn + b) * Ln + l) * Dn + dg];
            a1 += g_upart[(((size_t)(s + 1) * Bn + b) * Ln + l) * Dn + dg];
            a2 += g_upart[(((size_t)(s + 2) * Bn + b) * Ln + l) * Dn + dg];
            a3 += g_upart[(((size_t)(s + 3) * Bn + b) * Ln + l) * Dn + dg];
        }
        g_U[((size_t)b * Ln + l) * Dn + dg] = ((a0 + a1) + (a2 + a3)) * inv[l];
    }
}

// ---------------- stage-2 scores + softmax over L=8 ----------------
__global__ void k_s2(int pl) {
    __shared__ float ks[Ln][Dn];
    int tid = threadIdx.x, b = blockIdx.y;
    for (int i = tid; i < Ln * Dn / 4; i += 256)
        ((float4*)ks)[i] = ((const float4*)(g_k2 + (size_t)b * Ln * Dn))[i];
    __syncthreads();
    int w = tid >> 5, lane = tid & 31;
    int p0 = blockIdx.x * 16 + w * 2;
    if (p0 > pl - 2) p0 = pl - 2;
    ull acc[2][Ln];
#pragma unroll
    for (int pp = 0; pp < 2; pp++)
#pragma unroll
        for (int l = 0; l < Ln; l++) acc[pp][l] = 0ULL;
#pragma unroll
    for (int i = 0; i < 8; i++) {
        int d = (lane + 32 * i) * 4;
        ulonglong2 q0 = *(const ulonglong2*)(g_qb2 + (size_t)p0 * Dn + d);
        ulonglong2 q1 = *(const ulonglong2*)(g_qb2 + (size_t)(p0 + 1) * Dn + d);
#pragma unroll
        for (int l = 0; l < Ln; l++) {
            ulonglong2 k = *(const ulonglong2*)&ks[l][d];
            fma2(acc[0][l], q0.x, k.x); fma2(acc[0][l], q0.y, k.y);
            fma2(acc[1][l], q1.x, k.x); fma2(acc[1][l], q1.y, k.y);
        }
    }
#pragma unroll
    for (int pp = 0; pp < 2; pp++) {
        float v[Ln];
#pragma unroll
        for (int l = 0; l < Ln; l++) {
            float2 f = u2f(acc[pp][l]);
            float s = f.x + f.y;
            for (int off = 16; off; off >>= 1)
                s += __shfl_xor_sync(0xffffffffu, s, off);
            v[l] = s;
        }
        if (lane == 0) {
            int p = p0 + pp;
            if (p < pl) {
                float m = v[0];
#pragma unroll
                for (int l = 1; l < Ln; l++) m = fmaxf(m, v[l]);
                float e[Ln], s = 0.f;
#pragma unroll
                for (int l = 0; l < Ln; l++) { e[l] = expf(v[l] - m); s += e[l]; }
                float inv = 1.0f / s;
#pragma unroll
                for (int l = 0; l < Ln; l++)
                    g_A2[((size_t)b * pl + p) * Ln + l] = e[l] * inv;
            }
        }
    }
}

// ---------------- gate select ----------------
__global__ void k_gatesel(const float* __restrict__ w2, const float* __restrict__ b2,
                          const float* __restrict__ b1, int pl) {
    extern __shared__ float sm[];
    float* lvws = sm;
    float* w2T  = lvws + Ln * Dn;
    float* hs   = w2T + 16 * 1026;
    float* a2s  = hs + Dn;
    float* part = a2s + 64;
    float* lg   = part + 272;
    int tid = threadIdx.x, b = blockIdx.y, p0 = blockIdx.x * 8;
    for (int i = tid; i < Ln * Dn / 4; i += 256)
        ((float4*)lvws)[i] = ((const float4*)(g_lvw + (size_t)b * Ln * Dn))[i];
    for (int i = tid; i < Dn * En; i += 256) {
        int d = i >> 4, e = i & 15;
        w2T[e * 1026 + d] = w2[i];
    }
    if (tid < 64) {
        int pi = tid >> 3, l = tid & 7;
        int p = p0 + pi;
        a2s[tid] = (p < pl) ? g_A2[((size_t)b * pl + p) * Ln + l] : 0.f;
    }
    float4 bh4[8];
#pragma unroll
    for (int pi = 0; pi < 8; pi++) {
        int p = p0 + pi;
        bh4[pi] = (p < pl) ? *(const float4*)(g_bh + (size_t)p * Dn + tid * 4)
                           : make_float4(0, 0, 0, 0);
    }
    float4 b1v = *(const float4*)(b1 + tid * 4);
    __syncthreads();
    int e_id = tid & 15, dseg = tid >> 4;
    for (int pi = 0; pi < 8; pi++) {
        int p = p0 + pi;
        if (p >= pl) break;
        float4 s4 = bh4[pi];
        s4.x += b1v.x; s4.y += b1v.y; s4.z += b1v.z; s4.w += b1v.w;
#pragma unroll
        for (int l = 0; l < Ln; l++) {
            float a = a2s[pi * 8 + l];
            float4 v = ((const float4*)lvws)[l * (Dn / 4) + tid];
            s4.x += a * v.x; s4.y += a * v.y; s4.z += a * v.z; s4.w += a * v.w;
        }
        float4 h4;
        h4.x = gelu_f(s4.x); h4.y = gelu_f(s4.y);
        h4.z = gelu_f(s4.z); h4.w = gelu_f(s4.w);
        ((float4*)hs)[tid] = h4;
        __syncthreads();
        ull lacc = 0ULL;
        int dbase = dseg * 64;
#pragma unroll
        for (int j = 0; j < 32; j++) {
            ull h2 = *(const ull*)&hs[dbase + 2 * j];
            ull wv = *(const ull*)&w2T[e_id * 1026 + dbase + 2 * j];
            fma2(lacc, h2, wv);
        }
        float2 lf = u2f(lacc);
        part[dseg * 17 + e_id] = lf.x + lf.y;
        __syncthreads();
        if (tid < En) {
            float L = b2[tid];
#pragma unroll
            for (int g = 0; g < 16; g++) L += part[g * 17 + tid];
            lg[tid] = L;
        }
        __syncthreads();
        if (tid == 0) {
            float b1s = lg[0]; int e1 = 0;
#pragma unroll
            for (int e = 1; e < En; e++) if (lg[e] > b1s) { b1s = lg[e]; e1 = e; }
            float b2s = -3.4e38f; int e2 = 0;
#pragma unroll
            for (int e = 0; e < En; e++)
                if (e != e1 && lg[e] > b2s) { b2s = lg[e]; e2 = e; }
            float x2 = expf(b2s - b1s);
            float s = 1.f + x2;
            g_sel[(size_t)b * pl + p] = make_float4(
                1.f / s, x2 / s, __int_as_float(e1), __int_as_float(e2));
        }
        __syncthreads();
    }
}

// ---------------- combine experts ----------------
__global__ void k_combine(const float* __restrict__ qexp, float* __restrict__ out,
                          int pl, int Pfull) {
    __shared__ float4 sel[Bn];
    int p = blockIdx.x, tid = threadIdx.x;
    if (tid < Bn) sel[tid] = g_sel[(size_t)tid * pl + p];
    __syncthreads();
#pragma unroll 4
    for (int b = 0; b < Bn; b++) {
        float4 s = sel[b];
        int eA = __float_as_int(s.z), eB = __float_as_int(s.w);
        float4 va = *(const float4*)(qexp + ((size_t)eA * Pfull + p) * Dn + tid * 4);
        float4 vb = *(const float4*)(qexp + ((size_t)eB * Pfull + p) * Dn + tid * 4);
        float4 o;
        o.x = s.x * va.x + s.y * vb.x;
        o.y = s.x * va.y + s.y * vb.y;
        o.z = s.x * va.z + s.y * vb.z;
        o.w = s.x * va.w + s.y * vb.w;
        *(float4*)(out + ((size_t)b * pl + p) * Dn + tid * 4) = o;
    }
}

// ---------------- launch ----------------
extern "C" void kernel_launch(void* const* d_in, const int* in_sizes, int n_in,
                              void* d_out, int out_size) {
    const float* ctx        = (const float*)d_in[0];
    const float* qexp       = (const float*)d_in[1];
    const float* qpos       = (const float*)d_in[2];
    const float* ptbl       = (const float*)d_in[3];
    const float* lats       = (const float*)d_in[4];
    const float* lat_q_w    = (const float*)d_in[5];
    const float* ctx_k_w    = (const float*)d_in[6];
    const float* ctx_v_w    = (const float*)d_in[7];
    const float* lat_out_w  = (const float*)d_in[8];
    const float* step_q_w   = (const float*)d_in[9];
    const float* lat_k_w    = (const float*)d_in[10];
    const float* lat_v_w    = (const float*)d_in[11];
    const float* step_out_w = (const float*)d_in[12];
    const float* gate_w1    = (const float*)d_in[13];
    const float* gate_b1    = (const float*)d_in[14];
    const float* gate_w2    = (const float*)d_in[15];
    const float* gate_b2    = (const float*)d_in[16];
    float* out = (float*)d_out;

    int pl = out_size / (Bn * Dn);
    int Pfull = in_sizes[2] / Dn;

    float *p_t1p, *p_qeffp, *p_qeff, *p_U;
    float *p_pA, *p_pLC, *p_pk2, *p_pB, *p_pC, *p_plvw;
    float *p_k2, *p_lvw, *p_sb, *p_bcat, *p_pcat;
    cudaGetSymbolAddress((void**)&p_t1p, g_t1p);
    cudaGetSymbolAddress((void**)&p_qeffp, g_qeffp);
    cudaGetSymbolAddress((void**)&p_qeff, g_qeff);
    cudaGetSymbolAddress((void**)&p_U, g_U);
    cudaGetSymbolAddress((void**)&p_pA, g_pA);
    cudaGetSymbolAddress((void**)&p_pLC, g_pLC);
    cudaGetSymbolAddress((void**)&p_pk2, g_pk2);
    cudaGetSymbolAddress((void**)&p_pB, g_pB);
    cudaGetSymbolAddress((void**)&p_pC, g_pC);
    cudaGetSymbolAddress((void**)&p_plvw, g_plvw);
    cudaGetSymbolAddress((void**)&p_k2, g_k2);
    cudaGetSymbolAddress((void**)&p_lvw, g_lvw);
    cudaGetSymbolAddress((void**)&p_sb, g_step_base);
    cudaGetSymbolAddress((void**)&p_bcat, g_bcat);
    cudaGetSymbolAddress((void**)&p_pcat, g_pcat);

    const float inv_sqrt_d = 0.03125f;
    const int S = Bn * Ln * Dn;

    // 0-2: batch-independent prep + first qeff GEMM
    k_stepbase<<<(pl * Dn + 255) / 256, 256>>>(qpos, ptbl, pl);
    k_pack<<<Dn * 2048 / 4 / 256, 256>>>(step_q_w, gate_w1, inv_sqrt_d);
    k_gemm<<<dim3(16, 1, 8), 256>>>(lats, lat_q_w, p_t1p, Ln, Dn, Dn, 0, nullptr, 1.f, 1, 0);

    // 3 (ncu-sampled slot): packed [720,2048,1024] P-GEMM v2, split-K x4
    int gy = (pl + 63) / 64;
    k_gemm<<<dim3(32, gy, 4), 256>>>(p_sb, p_bcat, p_pcat, pl, 2048, Dn, 0, nullptr, 1.f, 1, 0);

    // qeff finish
    k_gemm<<<dim3(16, 1, 8), 256>>>(p_t1p, ctx_k_w, p_qeffp, Ln, Dn, Dn, 1, nullptr, inv_sqrt_d, 8, Ln * Dn);
    k_redN<<<8, 256>>>((float4*)p_qeff, (const float4*)p_qeffp, Ln * Dn / 4, 8, Ln * Dn / 4);

    // fused stage-1 (single DRAM pass over ctx)
    const int smem_f1 = (Ln * Dn + SUBSEG * Dn + SUBSEG * 16 + SUBSEG * 16) * 4;
    cudaFuncSetAttribute(k_fused1, cudaFuncAttributeMaxDynamicSharedMemorySize, smem_f1);
    k_fused1<<<dim3(NPART, Bn), 512, smem_f1>>>(ctx);
    k_comb1<<<dim3(4, Bn), 256>>>();

    // chain of [256,1024]x[1024,1024] GEMMs (v2, split-K x8, 512 blocks each)
    k_gemm<<<dim3(16, 4, 8), 256>>>(p_U,   ctx_v_w,    p_pA,   Bn * Ln, Dn, Dn, 0, nullptr, 1.f, 1, 0);
    k_gemm<<<dim3(16, 4, 8), 256>>>(p_pA,  lat_out_w,  p_pLC,  Bn * Ln, Dn, Dn, 0, nullptr, 1.f, 8, S);
    k_gemm<<<dim3(16, 4, 8), 256>>>(p_pLC, lat_k_w,    p_pk2,  Bn * Ln, Dn, Dn, 0, nullptr, 1.f, 8, S);
    k_gemm<<<dim3(16, 4, 8), 256>>>(p_pLC, lat_v_w,    p_pB,   Bn * Ln, Dn, Dn, 0, nullptr, 1.f, 8, S);
    k_gemm<<<dim3(16, 4, 8), 256>>>(p_pB,  step_out_w, p_pC,   Bn * Ln, Dn, Dn, 0, nullptr, 1.f, 8, S);
    k_gemm<<<dim3(16, 4, 8), 256>>>(p_pC,  gate_w1 + (size_t)Dn * Dn, p_plvw, Bn * Ln, Dn, Dn, 0, nullptr, 1.f, 8, S);
    k_redN<<<S / 4 / 256, 256>>>((float4*)p_k2,  (const float4*)p_pk2,  S / 4, 8, S / 4);
    k_redN<<<S / 4 / 256, 256>>>((float4*)p_lvw, (const float4*)p_plvw, S / 4, 8, S / 4);

    // P-path reduction
    k_redsplit<<<(pl * 256 + 255) / 256, 256>>>(pl);

    // stage-2 attention weights
    k_s2<<<dim3((pl + 15) / 16, Bn), 256>>>(pl);

    // gate select + streaming expert combine
    const int smem_gs = (Ln * Dn + 16 * 1026 + Dn + 64 + 272 + 16) * 4;
    cudaFuncSetAttribute(k_gatesel, cudaFuncAttributeMaxDynamicSharedMemorySize, smem_gs);
    k_gatesel<<<dim3((pl + 7) / 8, Bn), 256, smem_gs>>>(gate_w2, gate_b2, gate_b1, pl);
    k_combine<<<pl, 256>>>(qexp, out, pl, Pfull);
}

// round 10
// speedup vs baseline: 1.4756x; 1.0520x over previous
#include <cuda_runtime.h>
#include <math.h>
#include <stdint.h>

#define Bn 32
#define Tn 2048
#define Dn 1024
#define En 16
#define Ln 8
#define Pmax 720
#define SUBSEG 32
#define NSUB 4
#define NPART 16

typedef unsigned long long ull;

__device__ __forceinline__ void fma2(ull& d, ull a, ull b) {
    asm("fma.rn.f32x2 %0, %1, %2, %0;" : "+l"(d) : "l"(a), "l"(b));
}
__device__ __forceinline__ float2 u2f(ull v) {
    float2 f; asm("mov.b64 {%0,%1}, %2;" : "=f"(f.x), "=f"(f.y) : "l"(v)); return f;
}
__device__ __forceinline__ ull pack2(float s) {
    ull d; asm("mov.b64 %0, {%1,%1};" : "=l"(d) : "f"(s)); return d;
}
__device__ __forceinline__ float gelu_f(float x) {
    return 0.5f * x * (1.0f + erff(x * 0.70710678118654752440f));
}

// ---------------- scratch ----------------
__device__ float g_step_base[Pmax * Dn];
__device__ float g_t1p[8 * Ln * Dn];
__device__ float g_qeffp[8 * Ln * Dn];
__device__ float g_qeff[Ln * Dn];
__device__ float g_ssum[Bn * Ln * NPART];
__device__ float g_upart[(size_t)NPART * Bn * Ln * Dn];
__device__ float g_U[Bn * Ln * Dn];
__device__ float g_pA[8 * Bn * Ln * Dn];
__device__ float g_pLC[8 * Bn * Ln * Dn];
__device__ float g_pk2[8 * Bn * Ln * Dn];
__device__ float g_pB[8 * Bn * Ln * Dn];
__device__ float g_pC[8 * Bn * Ln * Dn];
__device__ float g_plvw[8 * Bn * Ln * Dn];
__device__ float g_k2[Bn * Ln * Dn];
__device__ float g_lvw[Bn * Ln * Dn];
__device__ float g_bcat[Dn * 2048];
__device__ float g_pcat[4 * Pmax * 2048];
__device__ float g_qb2[Pmax * Dn];
__device__ float g_bh[Pmax * Dn];
__device__ float g_A2[Bn * Pmax * Ln];
__device__ float4 g_sel[Bn * Pmax];

// ---------------- step_base ----------------
__global__ void k_stepbase(const float* __restrict__ qpos,
                           const float* __restrict__ tbl, int pl) {
    int i = blockIdx.x * 256 + threadIdx.x;
    if (i < pl * Dn)
        g_step_base[i] = qpos[i] + tbl[(size_t)pl * Dn + (i & (Dn - 1))];
}

// ---------------- pack B for the fused P-GEMM ----------------
__global__ void k_pack(const float* __restrict__ sqw, const float* __restrict__ gw1,
                       float alpha) {
    int i = blockIdx.x * 256 + threadIdx.x;
    int row = i >> 9;
    int c4 = i & 511;
    float4 v;
    if (c4 < 256) {
        v = ((const float4*)sqw)[row * 256 + c4];
        v.x *= alpha; v.y *= alpha; v.z *= alpha; v.w *= alpha;
    } else {
        v = ((const float4*)gw1)[row * 256 + (c4 - 256)];
    }
    ((float4*)g_bcat)[i] = v;
}

// ---------------- 64x64 fp32x2 GEMM v2 (kept for thin M=8 qeff GEMMs) ------------
__global__ void k_gemm(const float* __restrict__ A, const float* __restrict__ B,
                       float* __restrict__ C, int M, int N, int K,
                       int transB, const float* __restrict__ bias, float alpha,
                       int nsumA, int strideA) {
    __shared__ float As[2][16][68];
    __shared__ float Bs[2][16][68];
    int tid = threadIdx.x;
    int tx = tid & 15, ty = tid >> 4;
    int m0 = blockIdx.y * 64, n0 = blockIdx.x * 64;
    int kper = K / gridDim.z;
    int kbeg = blockIdx.z * kper;
    C += (size_t)blockIdx.z * M * N;
    int nk = kper / 16;

    ull acc[4][2];
#pragma unroll
    for (int i = 0; i < 4; i++) { acc[i][0] = 0ULL; acc[i][1] = 0ULL; }

    float4 va, vb4;
    float ra[4], rb[4];
    int am = tid >> 2, ak4 = tid & 3;
    int bk = tid >> 4, bn4 = tid & 15;

#define PREF_V(k0)                                                               \
    {                                                                            \
        int gm = m0 + am;                                                        \
        va = make_float4(0.f, 0.f, 0.f, 0.f);                                    \
        if (gm < M) {                                                            \
            const float* ap = A + (size_t)gm * K + (k0) + ak4 * 4;               \
            va = *(const float4*)ap;                                             \
            for (int s = 1; s < nsumA; s++) {                                    \
                float4 t = *(const float4*)(ap + (size_t)s * strideA);           \
                va.x += t.x; va.y += t.y; va.z += t.z; va.w += t.w;              \
            }                                                                    \
        }                                                                        \
        vb4 = *(const float4*)(B + (size_t)((k0) + bk) * N + n0 + bn4 * 4);      \
    }
#define STORE_V(bf)                                                              \
    {                                                                            \
        As[bf][ak4 * 4 + 0][am] = va.x;                                          \
        As[bf][ak4 * 4 + 1][am] = va.y;                                          \
        As[bf][ak4 * 4 + 2][am] = va.z;                                          \
        As[bf][ak4 * 4 + 3][am] = va.w;                                          \
        *(float4*)&Bs[bf][bk][bn4 * 4] = vb4;                                    \
    }
#define PREF_S(k0)                                                               \
    {                                                                            \
        for (int r = 0; r < 4; r++) {                                            \
            int i = tid + 256 * r;                                               \
            int row = i >> 4, col = i & 15;                                      \
            int gm = m0 + row;                                                   \
            float v = 0.f;                                                       \
            if (gm < M) {                                                        \
                size_t off = (size_t)gm * K + (k0) + col;                        \
                v = A[off];                                                      \
                for (int s = 1; s < nsumA; s++) v += A[off + (size_t)s * strideA]; \
            }                                                                    \
            ra[r] = v;                                                           \
        }                                                                        \
        for (int r = 0; r < 4; r++) {                                            \
            int i = tid + 256 * r;                                               \
            rb[r] = B[(size_t)(n0 + (i >> 4)) * K + (k0) + (i & 15)];            \
        }                                                                        \
    }
#define STORE_S(bf)                                                              \
    {                                                                            \
        for (int r = 0; r < 4; r++) {                                            \
            int i = tid + 256 * r;                                               \
            As[bf][i & 15][i >> 4] = ra[r];                                      \
        }                                                                        \
        for (int r = 0; r < 4; r++) {                                            \
            int i = tid + 256 * r;                                               \
            Bs[bf][i & 15][i >> 4] = rb[r];                                      \
        }                                                                        \
    }
#define COMPUTE(bf)                                                              \
    {                                                                            \
        _Pragma("unroll")                                                        \
        for (int kk = 0; kk < 16; kk++) {                                        \
            float4 a4 = *(const float4*)&As[bf][kk][ty * 4];                     \
            ulonglong2 bb = *(const ulonglong2*)&Bs[bf][kk][tx * 4];             \
            ull a0 = pack2(a4.x), a1 = pack2(a4.y);                              \
            ull a2 = pack2(a4.z), a3 = pack2(a4.w);                              \
            fma2(acc[0][0], a0, bb.x); fma2(acc[0][1], a0, bb.y);                \
            fma2(acc[1][0], a1, bb.x); fma2(acc[1][1], a1, bb.y);                \
            fma2(acc[2][0], a2, bb.x); fma2(acc[2][1], a2, bb.y);                \
            fma2(acc[3][0], a3, bb.x); fma2(acc[3][1], a3, bb.y);                \
        }                                                                        \
    }

    int buf = 0;
    if (!transB) {
        PREF_V(kbeg);
        STORE_V(0);
        __syncthreads();
        for (int kt = 0; kt < nk; kt++) {
            if (kt + 1 < nk) PREF_V(kbeg + (kt + 1) * 16);
            COMPUTE(buf);
            if (kt + 1 < nk) {
                STORE_V(buf ^ 1);
                __syncthreads();
                buf ^= 1;
            }
        }
    } else {
        PREF_S(kbeg);
        STORE_S(0);
        __syncthreads();
        for (int kt = 0; kt < nk; kt++) {
            if (kt + 1 < nk) PREF_S(kbeg + (kt + 1) * 16);
            COMPUTE(buf);
            if (kt + 1 < nk) {
                STORE_S(buf ^ 1);
                __syncthreads();
                buf ^= 1;
            }
        }
    }
#pragma unroll
    for (int i = 0; i < 4; i++) {
        int m = m0 + ty * 4 + i;
        if (m >= M) continue;
        float2 p0 = u2f(acc[i][0]), p1 = u2f(acc[i][1]);
        float4 o;
        o.x = alpha * p0.x; o.y = alpha * p0.y;
        o.z = alpha * p1.x; o.w = alpha * p1.y;
        if (bias) {
            o.x += bias[n0 + tx * 4];     o.y += bias[n0 + tx * 4 + 1];
            o.z += bias[n0 + tx * 4 + 2]; o.w += bias[n0 + tx * 4 + 3];
        }
        *(float4*)&C[(size_t)m * N + n0 + tx * 4] = o;
    }
}

// ---------------- 128x64 fp32x2 GEMM v3: 8x4 microtile, 25.6KB smem --------------
__global__ void __launch_bounds__(256) k_gemm_v3(
    const float* __restrict__ A, const float* __restrict__ B,
    float* __restrict__ C, int M, int N, int K,
    float alpha, int nsumA, int strideA) {
    __shared__ float As[2][16][132];
    __shared__ float Bs[2][16][68];
    int tid = threadIdx.x;
    int tx = tid & 15, ty = tid >> 4;
    int m0 = blockIdx.y * 128, n0 = blockIdx.x * 64;
    int kper = K / gridDim.z;
    int kbeg = blockIdx.z * kper;
    C += (size_t)blockIdx.z * M * N;
    int nk = kper / 16;

    ull acc[8][2];
#pragma unroll
    for (int i = 0; i < 8; i++) { acc[i][0] = 0ULL; acc[i][1] = 0ULL; }

    float4 va0, va1, vb4;
    int ar = tid >> 2, ak4 = tid & 3;   // A: rows ar and ar+64, k-quad ak4
    int bk = tid >> 4, bn4 = tid & 15;

#define V3_PREF(k0)                                                              \
    {                                                                            \
        int gm0 = m0 + ar, gm1 = m0 + 64 + ar;                                   \
        va0 = make_float4(0.f, 0.f, 0.f, 0.f);                                   \
        va1 = va0;                                                               \
        if (gm0 < M) {                                                           \
            const float* ap = A + (size_t)gm0 * K + (k0) + ak4 * 4;              \
            va0 = *(const float4*)ap;                                            \
            for (int s = 1; s < nsumA; s++) {                                    \
                float4 t = *(const float4*)(ap + (size_t)s * strideA);           \
                va0.x += t.x; va0.y += t.y; va0.z += t.z; va0.w += t.w;          \
            }                                                                    \
        }                                                                        \
        if (gm1 < M) {                                                           \
            const float* ap = A + (size_t)gm1 * K + (k0) + ak4 * 4;              \
            va1 = *(const float4*)ap;                                            \
            for (int s = 1; s < nsumA; s++) {                                    \
                float4 t = *(const float4*)(ap + (size_t)s * strideA);           \
                va1.x += t.x; va1.y += t.y; va1.z += t.z; va1.w += t.w;          \
            }                                                                    \
        }                                                                        \
        vb4 = *(const float4*)(B + (size_t)((k0) + bk) * N + n0 + bn4 * 4);      \
    }
#define V3_STORE(bf)                                                             \
    {                                                                            \
        As[bf][ak4 * 4 + 0][ar] = va0.x;                                         \
        As[bf][ak4 * 4 + 1][ar] = va0.y;                                         \
        As[bf][ak4 * 4 + 2][ar] = va0.z;                                         \
        As[bf][ak4 * 4 + 3][ar] = va0.w;                                         \
        As[bf][ak4 * 4 + 0][64 + ar] = va1.x;                                    \
        As[bf][ak4 * 4 + 1][64 + ar] = va1.y;                                    \
        As[bf][ak4 * 4 + 2][64 + ar] = va1.z;                                    \
        As[bf][ak4 * 4 + 3][64 + ar] = va1.w;                                    \
        *(float4*)&Bs[bf][bk][bn4 * 4] = vb4;                                    \
    }
#define V3_COMP(bf)                                                              \
    {                                                                            \
        _Pragma("unroll")                                                        \
        for (int kk = 0; kk < 16; kk++) {                                        \
            float4 a0 = *(const float4*)&As[bf][kk][ty * 8];                     \
            float4 a1 = *(const float4*)&As[bf][kk][ty * 8 + 4];                 \
            ulonglong2 bb = *(const ulonglong2*)&Bs[bf][kk][tx * 4];             \
            ull p0 = pack2(a0.x), p1 = pack2(a0.y);                              \
            ull p2 = pack2(a0.z), p3 = pack2(a0.w);                              \
            ull p4 = pack2(a1.x), p5 = pack2(a1.y);                              \
            ull p6 = pack2(a1.z), p7 = pack2(a1.w);                              \
            fma2(acc[0][0], p0, bb.x); fma2(acc[0][1], p0, bb.y);                \
            fma2(acc[1][0], p1, bb.x); fma2(acc[1][1], p1, bb.y);                \
            fma2(acc[2][0], p2, bb.x); fma2(acc[2][1], p2, bb.y);                \
            fma2(acc[3][0], p3, bb.x); fma2(acc[3][1], p3, bb.y);                \
            fma2(acc[4][0], p4, bb.x); fma2(acc[4][1], p4, bb.y);                \
            fma2(acc[5][0], p5, bb.x); fma2(acc[5][1], p5, bb.y);                \
            fma2(acc[6][0], p6, bb.x); fma2(acc[6][1], p6, bb.y);                \
            fma2(acc[7][0], p7, bb.x); fma2(acc[7][1], p7, bb.y);                \
        }                                                                        \
    }

    int buf = 0;
    V3_PREF(kbeg);
    V3_STORE(0);
    __syncthreads();
    for (int kt = 0; kt < nk; kt++) {
        if (kt + 1 < nk) V3_PREF(kbeg + (kt + 1) * 16);
        V3_COMP(buf);
        if (kt + 1 < nk) {
            V3_STORE(buf ^ 1);
            __syncthreads();
            buf ^= 1;
        }
    }
#pragma unroll
    for (int i = 0; i < 8; i++) {
        int m = m0 + ty * 8 + i;
        if (m >= M) continue;
        float2 p0 = u2f(acc[i][0]), p1 = u2f(acc[i][1]);
        float4 o;
        o.x = alpha * p0.x; o.y = alpha * p0.y;
        o.z = alpha * p1.x; o.w = alpha * p1.y;
        *(float4*)&C[(size_t)m * N + n0 + tx * 4] = o;
    }
}

// ---------------- generic partial reduction ----------------
__global__ void k_redN(float4* __restrict__ dst, const float4* __restrict__ src,
                       int n4, int nparts, int stride4) {
    int i = blockIdx.x * 256 + threadIdx.x;
    if (i >= n4) return;
    float4 s = src[i];
    for (int p = 1; p < nparts; p++) {
        float4 t = src[i + (size_t)p * stride4];
        s.x += t.x; s.y += t.y; s.z += t.z; s.w += t.w;
    }
    dst[i] = s;
}

// ---------------- de-interleave + reduce the packed P-GEMM (4 partials) ----------
__global__ void k_redsplit(int pl) {
    int i = blockIdx.x * 256 + threadIdx.x;
    if (i >= pl * 256) return;
    int p = i >> 8, d4 = i & 255;
    const float4* s = (const float4*)g_pcat;
    size_t base = (size_t)p * 512 + d4;
    size_t part = (size_t)pl * 512;
    float4 q = s[base], h = s[base + 256];
#pragma unroll
    for (int z = 1; z < 4; z++) {
        float4 tq = s[base + z * part], th = s[base + 256 + z * part];
        q.x += tq.x; q.y += tq.y; q.z += tq.z; q.w += tq.w;
        h.x += th.x; h.y += th.y; h.z += th.z; h.w += th.w;
    }
    ((float4*)g_qb2)[i] = q;
    ((float4*)g_bh)[i] = h;
}

// ---------------- fused stage-1 (single DRAM pass, 512 threads) -------------------
__global__ void __launch_bounds__(512) k_fused1(const float* __restrict__ ctx) {
    extern __shared__ float smf[];
    float* qs  = smf;
    float* ck  = qs + Ln * Dn;
    float* ps2 = ck + SUBSEG * Dn;
    float* prt = ps2 + SUBSEG * 16;
    int tid = threadIdx.x;
    for (int i = tid; i < Ln * Dn / 4; i += 512)
        ((float4*)qs)[i] = ((const float4*)g_qeff)[i];
    int b = blockIdx.y;
    int w = tid >> 5, lane = tid & 31;
    int g = w >> 1, h = w & 1;

    ull uacc[Ln];
#pragma unroll
    for (int l = 0; l < Ln; l++) uacc[l] = 0ULL;
    float ssum = 0.f;

    for (int sub = 0; sub < NSUB; sub++) {
        int t0 = (blockIdx.x * NSUB + sub) * SUBSEG;
        const float* base = ctx + ((size_t)b * Tn + t0 + g * 4) * Dn + h * 512;
        __syncthreads();

        ull acc[4][Ln];
#pragma unroll
        for (int tt = 0; tt < 4; tt++)
#pragma unroll
            for (int l = 0; l < Ln; l++) acc[tt][l] = 0ULL;
#pragma unroll
        for (int i = 0; i < 4; i++) {
            int d = (lane + 32 * i) * 4;
            ulonglong2 c0 = *(const ulonglong2*)(base + d);
            ulonglong2 c1 = *(const ulonglong2*)(base + Dn + d);
            ulonglong2 c2 = *(const ulonglong2*)(base + 2 * Dn + d);
            ulonglong2 c3 = *(const ulonglong2*)(base + 3 * Dn + d);
            int ckd = h * 512 + d;
            *(ulonglong2*)&ck[(g * 4 + 0) * Dn + ckd] = c0;
            *(ulonglong2*)&ck[(g * 4 + 1) * Dn + ckd] = c1;
            *(ulonglong2*)&ck[(g * 4 + 2) * Dn + ckd] = c2;
            *(ulonglong2*)&ck[(g * 4 + 3) * Dn + ckd] = c3;
#pragma unroll
            for (int l = 0; l < Ln; l++) {
                ulonglong2 q = *(const ulonglong2*)&qs[l * Dn + ckd];
                fma2(acc[0][l], c0.x, q.x); fma2(acc[0][l], c0.y, q.y);
                fma2(acc[1][l], c1.x, q.x); fma2(acc[1][l], c1.y, q.y);
                fma2(acc[2][l], c2.x, q.x); fma2(acc[2][l], c2.y, q.y);
                fma2(acc[3][l], c3.x, q.x); fma2(acc[3][l], c3.y, q.y);
            }
        }
#pragma unroll
        for (int tt = 0; tt < 4; tt++)
#pragma unroll
            for (int l = 0; l < Ln; l++) {
                float2 f = u2f(acc[tt][l]);
                float v = f.x + f.y;
                for (int off = 16; off; off >>= 1)
                    v += __shfl_xor_sync(0xffffffffu, v, off);
                if (lane == 0)
                    prt[(g * 4 + tt) * 16 + l * 2 + h] = v;
            }
        __syncthreads();

        if (tid < 256) {
            int tt = tid >> 3, l = tid & 7;
            float v = prt[tt * 16 + l * 2] + prt[tt * 16 + l * 2 + 1];
            float e = expf(fminf(v, 60.0f));  // shift-free softmax (scores tiny)
            ps2[tt * 16 + 2 * l] = e;
            ps2[tt * 16 + 2 * l + 1] = e;
        }
        __syncthreads();

        if (w < Ln) {
            float s = ps2[lane * 16 + 2 * w];
            for (int off = 16; off; off >>= 1)
                s += __shfl_xor_sync(0xffffffffu, s, off);
            ssum += s;
        }

        int d2 = tid * 2;
#pragma unroll 2
        for (int tt = 0; tt < SUBSEG; tt++) {
            ull c = *(const ull*)&ck[tt * Dn + d2];
            ulonglong2 p01 = *(const ulonglong2*)&ps2[tt * 16];
            ulonglong2 p23 = *(const ulonglong2*)&ps2[tt * 16 + 4];
            ulonglong2 p45 = *(const ulonglong2*)&ps2[tt * 16 + 8];
            ulonglong2 p67 = *(const ulonglong2*)&ps2[tt * 16 + 12];
            fma2(uacc[0], p01.x, c); fma2(uacc[1], p01.y, c);
            fma2(uacc[2], p23.x, c); fma2(uacc[3], p23.y, c);
            fma2(uacc[4], p45.x, c); fma2(uacc[5], p45.y, c);
            fma2(uacc[6], p67.x, c); fma2(uacc[7], p67.y, c);
        }
    }
#pragma unroll
    for (int l = 0; l < Ln; l++) {
        float2 f = u2f(uacc[l]);
        *(float2*)&g_upart[(((size_t)blockIdx.x * Bn + b) * Ln + l) * Dn + tid * 2] = f;
    }
    if (w < Ln && lane == 0)
        g_ssum[((size_t)b * Ln + w) * NPART + blockIdx.x] = ssum;
}

// ---------------- combine stage-1 partials ----------------
__global__ void k_comb1() {
    __shared__ float inv[Ln];
    int b = blockIdx.y, dc = blockIdx.x;
    int tid = threadIdx.x;
    if (tid < Ln) {
        float s0 = 0.f, s1 = 0.f, s2 = 0.f, s3 = 0.f;
#pragma unroll
        for (int g = 0; g < NPART; g += 4) {
            s0 += g_ssum[((size_t)b * Ln + tid) * NPART + g];
            s1 += g_ssum[((size_t)b * Ln + tid) * NPART + g + 1];
            s2 += g_ssum[((size_t)b * Ln + tid) * NPART + g + 2];
            s3 += g_ssum[((size_t)b * Ln + tid) * NPART + g + 3];
        }
        inv[tid] = 1.0f / ((s0 + s1) + (s2 + s3));
    }
    __syncthreads();
    int dg = dc * 256 + tid;
#pragma unroll
    for (int l = 0; l < Ln; l++) {
        float a0 = 0.f, a1 = 0.f, a2 = 0.f, a3 = 0.f;
#pragma unroll
        for (int s = 0; s < NPART; s += 4) {
            a0 += g_upart[(((size_t)(s + 0) * Bn + b) * Ln + l) * Dn + dg];
            a1 += g_upart[(((size_t)(s + 1) * Bn + b) * Ln + l) * Dn + dg];
            a2 += g_upart[(((size_t)(s + 2) * Bn + b) * Ln + l) * Dn + dg];
            a3 += g_upart[(((size_t)(s + 3) * Bn + b) * Ln + l) * Dn + dg];
        }
        g_U[((size_t)b * Ln + l) * Dn + dg] = ((a0 + a1) + (a2 + a3)) * inv[l];
    }
}

// ---------------- stage-2 scores + softmax over L=8 ----------------
__global__ void k_s2(int pl) {
    __shared__ float ks[Ln][Dn];
    int tid = threadIdx.x, b = blockIdx.y;
    for (int i = tid; i < Ln * Dn / 4; i += 256)
        ((float4*)ks)[i] = ((const float4*)(g_k2 + (size_t)b * Ln * Dn))[i];
    __syncthreads();
    int w = tid >> 5, lane = tid & 31;
    int p0 = blockIdx.x * 16 + w * 2;
    if (p0 > pl - 2) p0 = pl - 2;
    ull acc[2][Ln];
#pragma unroll
    for (int pp = 0; pp < 2; pp++)
#pragma unroll
        for (int l = 0; l < Ln; l++) acc[pp][l] = 0ULL;
#pragma unroll
    for (int i = 0; i < 8; i++) {
        int d = (lane + 32 * i) * 4;
        ulonglong2 q0 = *(const ulonglong2*)(g_qb2 + (size_t)p0 * Dn + d);
        ulonglong2 q1 = *(const ulonglong2*)(g_qb2 + (size_t)(p0 + 1) * Dn + d);
#pragma unroll
        for (int l = 0; l < Ln; l++) {
            ulonglong2 k = *(const ulonglong2*)&ks[l][d];
            fma2(acc[0][l], q0.x, k.x); fma2(acc[0][l], q0.y, k.y);
            fma2(acc[1][l], q1.x, k.x); fma2(acc[1][l], q1.y, k.y);
        }
    }
#pragma unroll
    for (int pp = 0; pp < 2; pp++) {
        float v[Ln];
#pragma unroll
        for (int l = 0; l < Ln; l++) {
            float2 f = u2f(acc[pp][l]);
            float s = f.x + f.y;
            for (int off = 16; off; off >>= 1)
                s += __shfl_xor_sync(0xffffffffu, s, off);
            v[l] = s;
        }
        if (lane == 0) {
            int p = p0 + pp;
            if (p < pl) {
                float m = v[0];
#pragma unroll
                for (int l = 1; l < Ln; l++) m = fmaxf(m, v[l]);
                float e[Ln], s = 0.f;
#pragma unroll
                for (int l = 0; l < Ln; l++) { e[l] = expf(v[l] - m); s += e[l]; }
                float inv = 1.0f / s;
#pragma unroll
                for (int l = 0; l < Ln; l++)
                    g_A2[((size_t)b * pl + p) * Ln + l] = e[l] * inv;
            }
        }
    }
}

// ---------------- gate select ----------------
__global__ void k_gatesel(const float* __restrict__ w2, const float* __restrict__ b2,
                          const float* __restrict__ b1, int pl) {
    extern __shared__ float sm[];
    float* lvws = sm;
    float* w2T  = lvws + Ln * Dn;
    float* hs   = w2T + 16 * 1026;
    float* a2s  = hs + Dn;
    float* part = a2s + 64;
    float* lg   = part + 272;
    int tid = threadIdx.x, b = blockIdx.y, p0 = blockIdx.x * 8;
    for (int i = tid; i < Ln * Dn / 4; i += 256)
        ((float4*)lvws)[i] = ((const float4*)(g_lvw + (size_t)b * Ln * Dn))[i];
    for (int i = tid; i < Dn * En; i += 256) {
        int d = i >> 4, e = i & 15;
        w2T[e * 1026 + d] = w2[i];
    }
    if (tid < 64) {
        int pi = tid >> 3, l = tid & 7;
        int p = p0 + pi;
        a2s[tid] = (p < pl) ? g_A2[((size_t)b * pl + p) * Ln + l] : 0.f;
    }
    float4 bh4[8];
#pragma unroll
    for (int pi = 0; pi < 8; pi++) {
        int p = p0 + pi;
        bh4[pi] = (p < pl) ? *(const float4*)(g_bh + (size_t)p * Dn + tid * 4)
                           : make_float4(0, 0, 0, 0);
    }
    float4 b1v = *(const float4*)(b1 + tid * 4);
    __syncthreads();
    int e_id = tid & 15, dseg = tid >> 4;
    for (int pi = 0; pi < 8; pi++) {
        int p = p0 + pi;
        if (p >= pl) break;
        float4 s4 = bh4[pi];
        s4.x += b1v.x; s4.y += b1v.y; s4.z += b1v.z; s4.w += b1v.w;
#pragma unroll
        for (int l = 0; l < Ln; l++) {
            float a = a2s[pi * 8 + l];
            float4 v = ((const float4*)lvws)[l * (Dn / 4) + tid];
            s4.x += a * v.x; s4.y += a * v.y; s4.z += a * v.z; s4.w += a * v.w;
        }
        float4 h4;
        h4.x = gelu_f(s4.x); h4.y = gelu_f(s4.y);
        h4.z = gelu_f(s4.z); h4.w = gelu_f(s4.w);
        ((float4*)hs)[tid] = h4;
        __syncthreads();
        ull lacc = 0ULL;
        int dbase = dseg * 64;
#pragma unroll
        for (int j = 0; j < 32; j++) {
            ull h2 = *(const ull*)&hs[dbase + 2 * j];
            ull wv = *(const ull*)&w2T[e_id * 1026 + dbase + 2 * j];
            fma2(lacc, h2, wv);
        }
        float2 lf = u2f(lacc);
        part[dseg * 17 + e_id] = lf.x + lf.y;
        __syncthreads();
        if (tid < En) {
            float L = b2[tid];
#pragma unroll
            for (int g = 0; g < 16; g++) L += part[g * 17 + tid];
            lg[tid] = L;
        }
        __syncthreads();
        if (tid == 0) {
            float b1s = lg[0]; int e1 = 0;
#pragma unroll
            for (int e = 1; e < En; e++) if (lg[e] > b1s) { b1s = lg[e]; e1 = e; }
            float b2s = -3.4e38f; int e2 = 0;
#pragma unroll
            for (int e = 0; e < En; e++)
                if (e != e1 && lg[e] > b2s) { b2s = lg[e]; e2 = e; }
            float x2 = expf(b2s - b1s);
            float s = 1.f + x2;
            g_sel[(size_t)b * pl + p] = make_float4(
                1.f / s, x2 / s, __int_as_float(e1), __int_as_float(e2));
        }
        __syncthreads();
    }
}

// ---------------- combine experts ----------------
__global__ void k_combine(const float* __restrict__ qexp, float* __restrict__ out,
                          int pl, int Pfull) {
    __shared__ float4 sel[Bn];
    int p = blockIdx.x, tid = threadIdx.x;
    if (tid < Bn) sel[tid] = g_sel[(size_t)tid * pl + p];
    __syncthreads();
#pragma unroll 4
    for (int b = 0; b < Bn; b++) {
        float4 s = sel[b];
        int eA = __float_as_int(s.z), eB = __float_as_int(s.w);
        float4 va = *(const float4*)(qexp + ((size_t)eA * Pfull + p) * Dn + tid * 4);
        float4 vb = *(const float4*)(qexp + ((size_t)eB * Pfull + p) * Dn + tid * 4);
        float4 o;
        o.x = s.x * va.x + s.y * vb.x;
        o.y = s.x * va.y + s.y * vb.y;
        o.z = s.x * va.z + s.y * vb.z;
        o.w = s.x * va.w + s.y * vb.w;
        *(float4*)(out + ((size_t)b * pl + p) * Dn + tid * 4) = o;
    }
}

// ---------------- launch ----------------
extern "C" void kernel_launch(void* const* d_in, const int* in_sizes, int n_in,
                              void* d_out, int out_size) {
    const float* ctx        = (const float*)d_in[0];
    const float* qexp       = (const float*)d_in[1];
    const float* qpos       = (const float*)d_in[2];
    const float* ptbl       = (const float*)d_in[3];
    const float* lats       = (const float*)d_in[4];
    const float* lat_q_w    = (const float*)d_in[5];
    const float* ctx_k_w    = (const float*)d_in[6];
    const float* ctx_v_w    = (const float*)d_in[7];
    const float* lat_out_w  = (const float*)d_in[8];
    const float* step_q_w   = (const float*)d_in[9];
    const float* lat_k_w    = (const float*)d_in[10];
    const float* lat_v_w    = (const float*)d_in[11];
    const float* step_out_w = (const float*)d_in[12];
    const float* gate_w1    = (const float*)d_in[13];
    const float* gate_b1    = (const float*)d_in[14];
    const float* gate_w2    = (const float*)d_in[15];
    const float* gate_b2    = (const float*)d_in[16];
    float* out = (float*)d_out;

    int pl = out_size / (Bn * Dn);
    int Pfull = in_sizes[2] / Dn;

    float *p_t1p, *p_qeffp, *p_qeff, *p_U;
    float *p_pA, *p_pLC, *p_pk2, *p_pB, *p_pC, *p_plvw;
    float *p_k2, *p_lvw, *p_sb, *p_bcat, *p_pcat;
    cudaGetSymbolAddress((void**)&p_t1p, g_t1p);
    cudaGetSymbolAddress((void**)&p_qeffp, g_qeffp);
    cudaGetSymbolAddress((void**)&p_qeff, g_qeff);
    cudaGetSymbolAddress((void**)&p_U, g_U);
    cudaGetSymbolAddress((void**)&p_pA, g_pA);
    cudaGetSymbolAddress((void**)&p_pLC, g_pLC);
    cudaGetSymbolAddress((void**)&p_pk2, g_pk2);
    cudaGetSymbolAddress((void**)&p_pB, g_pB);
    cudaGetSymbolAddress((void**)&p_pC, g_pC);
    cudaGetSymbolAddress((void**)&p_plvw, g_plvw);
    cudaGetSymbolAddress((void**)&p_k2, g_k2);
    cudaGetSymbolAddress((void**)&p_lvw, g_lvw);
    cudaGetSymbolAddress((void**)&p_sb, g_step_base);
    cudaGetSymbolAddress((void**)&p_bcat, g_bcat);
    cudaGetSymbolAddress((void**)&p_pcat, g_pcat);

    const float inv_sqrt_d = 0.03125f;
    const int S = Bn * Ln * Dn;

    // 0-2: batch-independent prep + first qeff GEMM
    k_stepbase<<<(pl * Dn + 255) / 256, 256>>>(qpos, ptbl, pl);
    k_pack<<<Dn * 2048 / 4 / 256, 256>>>(step_q_w, gate_w1, inv_sqrt_d);
    k_gemm<<<dim3(16, 1, 8), 256>>>(lats, lat_q_w, p_t1p, Ln, Dn, Dn, 0, nullptr, 1.f, 1, 0);

    // 3 (ncu-sampled slot): packed [720,2048,1024] P-GEMM v3, split-K x4
    int gy2 = (pl + 127) / 128;
    k_gemm_v3<<<dim3(32, gy2, 4), 256>>>(p_sb, p_bcat, p_pcat, pl, 2048, Dn, 1.f, 1, 0);

    // qeff finish
    k_gemm<<<dim3(16, 1, 8), 256>>>(p_t1p, ctx_k_w, p_qeffp, Ln, Dn, Dn, 1, nullptr, inv_sqrt_d, 8, Ln * Dn);
    k_redN<<<8, 256>>>((float4*)p_qeff, (const float4*)p_qeffp, Ln * Dn / 4, 8, Ln * Dn / 4);

    // fused stage-1 (single DRAM pass over ctx)
    const int smem_f1 = (Ln * Dn + SUBSEG * Dn + SUBSEG * 16 + SUBSEG * 16) * 4;
    cudaFuncSetAttribute(k_fused1, cudaFuncAttributeMaxDynamicSharedMemorySize, smem_f1);
    k_fused1<<<dim3(NPART, Bn), 512, smem_f1>>>(ctx);
    k_comb1<<<dim3(4, Bn), 256>>>();

    // chain of [256,1024]x[1024,1024] GEMMs (v3, split-K x8, 256 blocks each)
    k_gemm_v3<<<dim3(16, 2, 8), 256>>>(p_U,   ctx_v_w,    p_pA,   Bn * Ln, Dn, Dn, 1.f, 1, 0);
    k_gemm_v3<<<dim3(16, 2, 8), 256>>>(p_pA,  lat_out_w,  p_pLC,  Bn * Ln, Dn, Dn, 1.f, 8, S);
    k_gemm_v3<<<dim3(16, 2, 8), 256>>>(p_pLC, lat_k_w,    p_pk2,  Bn * Ln, Dn, Dn, 1.f, 8, S);
    k_gemm_v3<<<dim3(16, 2, 8), 256>>>(p_pLC, lat_v_w,    p_pB,   Bn * Ln, Dn, Dn, 1.f, 8, S);
    k_gemm_v3<<<dim3(16, 2, 8), 256>>>(p_pB,  step_out_w, p_pC,   Bn * Ln, Dn, Dn, 1.f, 8, S);
    k_gemm_v3<<<dim3(16, 2, 8), 256>>>(p_pC,  gate_w1 + (size_t)Dn * Dn, p_plvw, Bn * Ln, Dn, Dn, 1.f, 8, S);
    k_redN<<<S / 4 / 256, 256>>>((float4*)p_k2,  (const float4*)p_pk2,  S / 4, 8, S / 4);
    k_redN<<<S / 4 / 256, 256>>>((float4*)p_lvw, (const float4*)p_plvw, S / 4, 8, S / 4);

    // P-path reduction
    k_redsplit<<<(pl * 256 + 255) / 256, 256>>>(pl);

    // stage-2 attention weights
    k_s2<<<dim3((pl + 15) / 16, Bn), 256>>>(pl);

    // gate select + streaming expert combine
    const int smem_gs = (Ln * Dn + 16 * 1026 + Dn + 64 + 272 + 16) * 4;
    cudaFuncSetAttribute(k_gatesel, cudaFuncAttributeMaxDynamicSharedMemorySize, smem_gs);
    k_gatesel<<<dim3((pl + 7) / 8, Bn), 256, smem_gs>>>(gate_w2, gate_b2, gate_b1, pl);
    k_combine<<<pl, 256>>>(qexp, out, pl, Pfull);
}

// round 11
// speedup vs baseline: 1.5660x; 1.0612x over previous
#include <cuda_runtime.h>
#include <math.h>
#include <stdint.h>

#define Bn 32
#define Tn 2048
#define Dn 1024
#define En 16
#define Ln 8
#define Pmax 720
#define SUBSEG 32
#define NSUB 4
#define NPART 16

typedef unsigned long long ull;

__device__ __forceinline__ void fma2(ull& d, ull a, ull b) {
    asm("fma.rn.f32x2 %0, %1, %2, %0;" : "+l"(d) : "l"(a), "l"(b));
}
__device__ __forceinline__ float2 u2f(ull v) {
    float2 f; asm("mov.b64 {%0,%1}, %2;" : "=f"(f.x), "=f"(f.y) : "l"(v)); return f;
}
__device__ __forceinline__ ull pack2(float s) {
    ull d; asm("mov.b64 %0, {%1,%1};" : "=l"(d) : "f"(s)); return d;
}
__device__ __forceinline__ float gelu_f(float x) {
    return 0.5f * x * (1.0f + erff(x * 0.70710678118654752440f));
}

// ---------------- scratch ----------------
__device__ float g_step_base[Pmax * Dn];
__device__ float g_t1p[8 * Ln * Dn];
__device__ float g_qeffp[8 * Ln * Dn];
__device__ float g_qeff[Ln * Dn];
__device__ float g_ssum[Bn * Ln * NPART];
__device__ float g_upart[(size_t)NPART * Bn * Ln * Dn];
__device__ float g_U[Bn * Ln * Dn];
__device__ float g_pA[8 * Bn * Ln * Dn];
__device__ float g_pLC[8 * Bn * Ln * Dn];
__device__ float g_pkv[8 * Bn * Ln * 2048];   // merged [k2-half | v-half] partials
__device__ float g_pC[8 * Bn * Ln * Dn];
__device__ float g_plvw[8 * Bn * Ln * Dn];
__device__ float g_k2[Bn * Ln * Dn];
__device__ float g_lvw[Bn * Ln * Dn];
__device__ float g_bcat[Dn * 2048];
__device__ float g_bkv[Dn * 2048];            // [lat_k_w | lat_v_w]
__device__ float g_pcat[4 * Pmax * 2048];
__device__ float g_qb2[Pmax * Dn];
__device__ float g_bh[Pmax * Dn];
__device__ float g_A2[Bn * Pmax * Ln];
__device__ float4 g_sel[Bn * Pmax];

// ---------------- step_base ----------------
__global__ void k_stepbase(const float* __restrict__ qpos,
                           const float* __restrict__ tbl, int pl) {
    int i = blockIdx.x * 256 + threadIdx.x;
    if (i < pl * Dn)
        g_step_base[i] = qpos[i] + tbl[(size_t)pl * Dn + (i & (Dn - 1))];
}

// ---------------- pack two [1024,1024] B's side by side ----------------
__global__ void k_pack2(const float* __restrict__ w_left, const float* __restrict__ w_right,
                        float* __restrict__ dst, float alphaL) {
    int i = blockIdx.x * 256 + threadIdx.x;   // over 1024*2048/4 float4
    int row = i >> 9;
    int c4 = i & 511;
    float4 v;
    if (c4 < 256) {
        v = ((const float4*)w_left)[row * 256 + c4];
        v.x *= alphaL; v.y *= alphaL; v.z *= alphaL; v.w *= alphaL;
    } else {
        v = ((const float4*)w_right)[row * 256 + (c4 - 256)];
    }
    ((float4*)dst)[i] = v;
}

// ---------------- 64x64 fp32x2 GEMM v2 (thin M=8 qeff GEMMs) ----------------
__global__ void k_gemm(const float* __restrict__ A, const float* __restrict__ B,
                       float* __restrict__ C, int M, int N, int K,
                       int transB, const float* __restrict__ bias, float alpha,
                       int nsumA, int strideA) {
    __shared__ float As[2][16][68];
    __shared__ float Bs[2][16][68];
    int tid = threadIdx.x;
    int tx = tid & 15, ty = tid >> 4;
    int m0 = blockIdx.y * 64, n0 = blockIdx.x * 64;
    int kper = K / gridDim.z;
    int kbeg = blockIdx.z * kper;
    C += (size_t)blockIdx.z * M * N;
    int nk = kper / 16;

    ull acc[4][2];
#pragma unroll
    for (int i = 0; i < 4; i++) { acc[i][0] = 0ULL; acc[i][1] = 0ULL; }

    float4 va, vb4;
    float ra[4], rb[4];
    int am = tid >> 2, ak4 = tid & 3;
    int bk = tid >> 4, bn4 = tid & 15;

#define PREF_V(k0)                                                               \
    {                                                                            \
        int gm = m0 + am;                                                        \
        va = make_float4(0.f, 0.f, 0.f, 0.f);                                    \
        if (gm < M) {                                                            \
            const float* ap = A + (size_t)gm * K + (k0) + ak4 * 4;               \
            va = *(const float4*)ap;                                             \
            for (int s = 1; s < nsumA; s++) {                                    \
                float4 t = *(const float4*)(ap + (size_t)s * strideA);           \
                va.x += t.x; va.y += t.y; va.z += t.z; va.w += t.w;              \
            }                                                                    \
        }                                                                        \
        vb4 = *(const float4*)(B + (size_t)((k0) + bk) * N + n0 + bn4 * 4);      \
    }
#define STORE_V(bf)                                                              \
    {                                                                            \
        As[bf][ak4 * 4 + 0][am] = va.x;                                          \
        As[bf][ak4 * 4 + 1][am] = va.y;                                          \
        As[bf][ak4 * 4 + 2][am] = va.z;                                          \
        As[bf][ak4 * 4 + 3][am] = va.w;                                          \
        *(float4*)&Bs[bf][bk][bn4 * 4] = vb4;                                    \
    }
#define PREF_S(k0)                                                               \
    {                                                                            \
        for (int r = 0; r < 4; r++) {                                            \
            int i = tid + 256 * r;                                               \
            int row = i >> 4, col = i & 15;                                      \
            int gm = m0 + row;                                                   \
            float v = 0.f;                                                       \
            if (gm < M) {                                                        \
                size_t off = (size_t)gm * K + (k0) + col;                        \
                v = A[off];                                                      \
                for (int s = 1; s < nsumA; s++) v += A[off + (size_t)s * strideA]; \
            }                                                                    \
            ra[r] = v;                                                           \
        }                                                                        \
        for (int r = 0; r < 4; r++) {                                            \
            int i = tid + 256 * r;                                               \
            rb[r] = B[(size_t)(n0 + (i >> 4)) * K + (k0) + (i & 15)];            \
        }                                                                        \
    }
#define STORE_S(bf)                                                              \
    {                                                                            \
        for (int r = 0; r < 4; r++) {                                            \
            int i = tid + 256 * r;                                               \
            As[bf][i & 15][i >> 4] = ra[r];                                      \
        }                                                                        \
        for (int r = 0; r < 4; r++) {                                            \
            int i = tid + 256 * r;                                               \
            Bs[bf][i & 15][i >> 4] = rb[r];                                      \
        }                                                                        \
    }
#define COMPUTE(bf)                                                              \
    {                                                                            \
        _Pragma("unroll")                                                        \
        for (int kk = 0; kk < 16; kk++) {                                        \
            float4 a4 = *(const float4*)&As[bf][kk][ty * 4];                     \
            ulonglong2 bb = *(const ulonglong2*)&Bs[bf][kk][tx * 4];             \
            ull a0 = pack2(a4.x), a1 = pack2(a4.y);                              \
            ull a2 = pack2(a4.z), a3 = pack2(a4.w);                              \
            fma2(acc[0][0], a0, bb.x); fma2(acc[0][1], a0, bb.y);                \
            fma2(acc[1][0], a1, bb.x); fma2(acc[1][1], a1, bb.y);                \
            fma2(acc[2][0], a2, bb.x); fma2(acc[2][1], a2, bb.y);                \
            fma2(acc[3][0], a3, bb.x); fma2(acc[3][1], a3, bb.y);                \
        }                                                                        \
    }

    int buf = 0;
    if (!transB) {
        PREF_V(kbeg);
        STORE_V(0);
        __syncthreads();
        for (int kt = 0; kt < nk; kt++) {
            if (kt + 1 < nk) PREF_V(kbeg + (kt + 1) * 16);
            COMPUTE(buf);
            if (kt + 1 < nk) {
                STORE_V(buf ^ 1);
                __syncthreads();
                buf ^= 1;
            }
        }
    } else {
        PREF_S(kbeg);
        STORE_S(0);
        __syncthreads();
        for (int kt = 0; kt < nk; kt++) {
            if (kt + 1 < nk) PREF_S(kbeg + (kt + 1) * 16);
            COMPUTE(buf);
            if (kt + 1 < nk) {
                STORE_S(buf ^ 1);
                __syncthreads();
                buf ^= 1;
            }
        }
    }
#pragma unroll
    for (int i = 0; i < 4; i++) {
        int m = m0 + ty * 4 + i;
        if (m >= M) continue;
        float2 p0 = u2f(acc[i][0]), p1 = u2f(acc[i][1]);
        float4 o;
        o.x = alpha * p0.x; o.y = alpha * p0.y;
        o.z = alpha * p1.x; o.w = alpha * p1.y;
        if (bias) {
            o.x += bias[n0 + tx * 4];     o.y += bias[n0 + tx * 4 + 1];
            o.z += bias[n0 + tx * 4 + 2]; o.w += bias[n0 + tx * 4 + 3];
        }
        *(float4*)&C[(size_t)m * N + n0 + tx * 4] = o;
    }
}

// ---------------- 128x64 fp32x2 GEMM v3 (lda-aware) ----------------
__global__ void __launch_bounds__(256) k_gemm_v3(
    const float* __restrict__ A, const float* __restrict__ B,
    float* __restrict__ C, int M, int N, int K, int lda,
    float alpha, int nsumA, int strideA) {
    __shared__ float As[2][16][132];
    __shared__ float Bs[2][16][68];
    int tid = threadIdx.x;
    int tx = tid & 15, ty = tid >> 4;
    int m0 = blockIdx.y * 128, n0 = blockIdx.x * 64;
    int kper = K / gridDim.z;
    int kbeg = blockIdx.z * kper;
    C += (size_t)blockIdx.z * M * N;
    int nk = kper / 16;

    ull acc[8][2];
#pragma unroll
    for (int i = 0; i < 8; i++) { acc[i][0] = 0ULL; acc[i][1] = 0ULL; }

    float4 va0, va1, vb4;
    int ar = tid >> 2, ak4 = tid & 3;
    int bk = tid >> 4, bn4 = tid & 15;

#define V3_PREF(k0)                                                              \
    {                                                                            \
        int gm0 = m0 + ar, gm1 = m0 + 64 + ar;                                   \
        va0 = make_float4(0.f, 0.f, 0.f, 0.f);                                   \
        va1 = va0;                                                               \
        if (gm0 < M) {                                                           \
            const float* ap = A + (size_t)gm0 * lda + (k0) + ak4 * 4;            \
            va0 = *(const float4*)ap;                                            \
            for (int s = 1; s < nsumA; s++) {                                    \
                float4 t = *(const float4*)(ap + (size_t)s * strideA);           \
                va0.x += t.x; va0.y += t.y; va0.z += t.z; va0.w += t.w;          \
            }                                                                    \
        }                                                                        \
        if (gm1 < M) {                                                           \
            const float* ap = A + (size_t)gm1 * lda + (k0) + ak4 * 4;            \
            va1 = *(const float4*)ap;                                            \
            for (int s = 1; s < nsumA; s++) {                                    \
                float4 t = *(const float4*)(ap + (size_t)s * strideA);           \
                va1.x += t.x; va1.y += t.y; va1.z += t.z; va1.w += t.w;          \
            }                                                                    \
        }                                                                        \
        vb4 = *(const float4*)(B + (size_t)((k0) + bk) * N + n0 + bn4 * 4);      \
    }
#define V3_STORE(bf)                                                             \
    {                                                                            \
        As[bf][ak4 * 4 + 0][ar] = va0.x;                                         \
        As[bf][ak4 * 4 + 1][ar] = va0.y;                                         \
        As[bf][ak4 * 4 + 2][ar] = va0.z;                                         \
        As[bf][ak4 * 4 + 3][ar] = va0.w;                                         \
        As[bf][ak4 * 4 + 0][64 + ar] = va1.x;                                    \
        As[bf][ak4 * 4 + 1][64 + ar] = va1.y;                                    \
        As[bf][ak4 * 4 + 2][64 + ar] = va1.z;                                    \
        As[bf][ak4 * 4 + 3][64 + ar] = va1.w;                                    \
        *(float4*)&Bs[bf][bk][bn4 * 4] = vb4;                                    \
    }
#define V3_COMP(bf)                                                              \
    {                                                                            \
        _Pragma("unroll")                                                        \
        for (int kk = 0; kk < 16; kk++) {                                        \
            float4 a0 = *(const float4*)&As[bf][kk][ty * 8];                     \
            float4 a1 = *(const float4*)&As[bf][kk][ty * 8 + 4];                 \
            ulonglong2 bb = *(const ulonglong2*)&Bs[bf][kk][tx * 4];             \
            ull p0 = pack2(a0.x), p1 = pack2(a0.y);                              \
            ull p2 = pack2(a0.z), p3 = pack2(a0.w);                              \
            ull p4 = pack2(a1.x), p5 = pack2(a1.y);                              \
            ull p6 = pack2(a1.z), p7 = pack2(a1.w);                              \
            fma2(acc[0][0], p0, bb.x); fma2(acc[0][1], p0, bb.y);                \
            fma2(acc[1][0], p1, bb.x); fma2(acc[1][1], p1, bb.y);                \
            fma2(acc[2][0], p2, bb.x); fma2(acc[2][1], p2, bb.y);                \
            fma2(acc[3][0], p3, bb.x); fma2(acc[3][1], p3, bb.y);                \
            fma2(acc[4][0], p4, bb.x); fma2(acc[4][1], p4, bb.y);                \
            fma2(acc[5][0], p5, bb.x); fma2(acc[5][1], p5, bb.y);                \
            fma2(acc[6][0], p6, bb.x); fma2(acc[6][1], p6, bb.y);                \
            fma2(acc[7][0], p7, bb.x); fma2(acc[7][1], p7, bb.y);                \
        }                                                                        \
    }

    int buf = 0;
    V3_PREF(kbeg);
    V3_STORE(0);
    __syncthreads();
    for (int kt = 0; kt < nk; kt++) {
        if (kt + 1 < nk) V3_PREF(kbeg + (kt + 1) * 16);
        V3_COMP(buf);
        if (kt + 1 < nk) {
            V3_STORE(buf ^ 1);
            __syncthreads();
            buf ^= 1;
        }
    }
#pragma unroll
    for (int i = 0; i < 8; i++) {
        int m = m0 + ty * 8 + i;
        if (m >= M) continue;
        float2 p0 = u2f(acc[i][0]), p1 = u2f(acc[i][1]);
        float4 o;
        o.x = alpha * p0.x; o.y = alpha * p0.y;
        o.z = alpha * p1.x; o.w = alpha * p1.y;
        *(float4*)&C[(size_t)m * N + n0 + tx * 4] = o;
    }
}

// ---------------- generic partial reduction ----------------
__global__ void k_redN(float4* __restrict__ dst, const float4* __restrict__ src,
                       int n4, int nparts, int stride4) {
    int i = blockIdx.x * 256 + threadIdx.x;
    if (i >= n4) return;
    float4 s = src[i];
    for (int p = 1; p < nparts; p++) {
        float4 t = src[i + (size_t)p * stride4];
        s.x += t.x; s.y += t.y; s.z += t.z; s.w += t.w;
    }
    dst[i] = s;
}

// ---------------- reduce k2 half of merged pkv partials ----------------
__global__ void k_redk2() {
    int i = blockIdx.x * 256 + threadIdx.x;   // over Bn*Ln*Dn/4
    int m = i >> 8, d4 = i & 255;
    const float4* s = (const float4*)g_pkv;
    size_t base = (size_t)m * 512 + d4;       // 512 float4 per merged row
    size_t part = (size_t)Bn * Ln * 512;
    float4 a = s[base];
#pragma unroll
    for (int z = 1; z < 8; z++) {
        float4 t = s[base + z * part];
        a.x += t.x; a.y += t.y; a.z += t.z; a.w += t.w;
    }
    ((float4*)g_k2)[i] = a;
}

// ---------------- de-interleave + reduce the packed P-GEMM (4 partials) ----------
__global__ void k_redsplit(int pl) {
    int i = blockIdx.x * 256 + threadIdx.x;
    if (i >= pl * 256) return;
    int p = i >> 8, d4 = i & 255;
    const float4* s = (const float4*)g_pcat;
    size_t base = (size_t)p * 512 + d4;
    size_t part = (size_t)pl * 512;
    float4 q = s[base], h = s[base + 256];
#pragma unroll
    for (int z = 1; z < 4; z++) {
        float4 tq = s[base + z * part], th = s[base + 256 + z * part];
        q.x += tq.x; q.y += tq.y; q.z += tq.z; q.w += tq.w;
        h.x += th.x; h.y += th.y; h.z += th.z; h.w += th.w;
    }
    ((float4*)g_qb2)[i] = q;
    ((float4*)g_bh)[i] = h;
}

// ---------------- fused stage-1 (single DRAM pass, 512 threads) -------------------
__global__ void __launch_bounds__(512) k_fused1(const float* __restrict__ ctx) {
    extern __shared__ float smf[];
    float* qs  = smf;
    float* ck  = qs + Ln * Dn;
    float* ps2 = ck + SUBSEG * Dn;
    float* prt = ps2 + SUBSEG * 16;
    int tid = threadIdx.x;
    for (int i = tid; i < Ln * Dn / 4; i += 512)
        ((float4*)qs)[i] = ((const float4*)g_qeff)[i];
    int b = blockIdx.y;
    int w = tid >> 5, lane = tid & 31;
    int g = w >> 1, h = w & 1;

    ull uacc[Ln];
#pragma unroll
    for (int l = 0; l < Ln; l++) uacc[l] = 0ULL;
    float ssum = 0.f;

    for (int sub = 0; sub < NSUB; sub++) {
        int t0 = (blockIdx.x * NSUB + sub) * SUBSEG;
        const float* base = ctx + ((size_t)b * Tn + t0 + g * 4) * Dn + h * 512;
        __syncthreads();

        ull acc[4][Ln];
#pragma unroll
        for (int tt = 0; tt < 4; tt++)
#pragma unroll
            for (int l = 0; l < Ln; l++) acc[tt][l] = 0ULL;
#pragma unroll
        for (int i = 0; i < 4; i++) {
            int d = (lane + 32 * i) * 4;
            ulonglong2 c0 = *(const ulonglong2*)(base + d);
            ulonglong2 c1 = *(const ulonglong2*)(base + Dn + d);
            ulonglong2 c2 = *(const ulonglong2*)(base + 2 * Dn + d);
            ulonglong2 c3 = *(const ulonglong2*)(base + 3 * Dn + d);
            int ckd = h * 512 + d;
            *(ulonglong2*)&ck[(g * 4 + 0) * Dn + ckd] = c0;
            *(ulonglong2*)&ck[(g * 4 + 1) * Dn + ckd] = c1;
            *(ulonglong2*)&ck[(g * 4 + 2) * Dn + ckd] = c2;
            *(ulonglong2*)&ck[(g * 4 + 3) * Dn + ckd] = c3;
#pragma unroll
            for (int l = 0; l < Ln; l++) {
                ulonglong2 q = *(const ulonglong2*)&qs[l * Dn + ckd];
                fma2(acc[0][l], c0.x, q.x); fma2(acc[0][l], c0.y, q.y);
                fma2(acc[1][l], c1.x, q.x); fma2(acc[1][l], c1.y, q.y);
                fma2(acc[2][l], c2.x, q.x); fma2(acc[2][l], c2.y, q.y);
                fma2(acc[3][l], c3.x, q.x); fma2(acc[3][l], c3.y, q.y);
            }
        }
#pragma unroll
        for (int tt = 0; tt < 4; tt++)
#pragma unroll
            for (int l = 0; l < Ln; l++) {
                float2 f = u2f(acc[tt][l]);
                float v = f.x + f.y;
                for (int off = 16; off; off >>= 1)
                    v += __shfl_xor_sync(0xffffffffu, v, off);
                if (lane == 0)
                    prt[(g * 4 + tt) * 16 + l * 2 + h] = v;
            }
        __syncthreads();

        if (tid < 256) {
            int tt = tid >> 3, l = tid & 7;
            float v = prt[tt * 16 + l * 2] + prt[tt * 16 + l * 2 + 1];
            float e = expf(fminf(v, 60.0f));  // shift-free softmax (scores tiny)
            ps2[tt * 16 + 2 * l] = e;
            ps2[tt * 16 + 2 * l + 1] = e;
        }
        __syncthreads();

        if (w < Ln) {
            float s = ps2[lane * 16 + 2 * w];
            for (int off = 16; off; off >>= 1)
                s += __shfl_xor_sync(0xffffffffu, s, off);
            ssum += s;
        }

        int d2 = tid * 2;
#pragma unroll 2
        for (int tt = 0; tt < SUBSEG; tt++) {
            ull c = *(const ull*)&ck[tt * Dn + d2];
            ulonglong2 p01 = *(const ulonglong2*)&ps2[tt * 16];
            ulonglong2 p23 = *(const ulonglong2*)&ps2[tt * 16 + 4];
            ulonglong2 p45 = *(const ulonglong2*)&ps2[tt * 16 + 8];
            ulonglong2 p67 = *(const ulonglong2*)&ps2[tt * 16 + 12];
            fma2(uacc[0], p01.x, c); fma2(uacc[1], p01.y, c);
            fma2(uacc[2], p23.x, c); fma2(uacc[3], p23.y, c);
            fma2(uacc[4], p45.x, c); fma2(uacc[5], p45.y, c);
            fma2(uacc[6], p67.x, c); fma2(uacc[7], p67.y, c);
        }
    }
#pragma unroll
    for (int l = 0; l < Ln; l++) {
        float2 f = u2f(uacc[l]);
        *(float2*)&g_upart[(((size_t)blockIdx.x * Bn + b) * Ln + l) * Dn + tid * 2] = f;
    }
    if (w < Ln && lane == 0)
        g_ssum[((size_t)b * Ln + w) * NPART + blockIdx.x] = ssum;
}

// ---------------- combine stage-1 partials ----------------
__global__ void k_comb1() {
    __shared__ float inv[Ln];
    int b = blockIdx.y, dc = blockIdx.x;
    int tid = threadIdx.x;
    if (tid < Ln) {
        float s0 = 0.f, s1 = 0.f, s2 = 0.f, s3 = 0.f;
#pragma unroll
        for (int g = 0; g < NPART; g += 4) {
            s0 += g_ssum[((size_t)b * Ln + tid) * NPART + g];
            s1 += g_ssum[((size_t)b * Ln + tid) * NPART + g + 1];
            s2 += g_ssum[((size_t)b * Ln + tid) * NPART + g + 2];
            s3 += g_ssum[((size_t)b * Ln + tid) * NPART + g + 3];
        }
        inv[tid] = 1.0f / ((s0 + s1) + (s2 + s3));
    }
    __syncthreads();
    int dg = dc * 256 + tid;
#pragma unroll
    for (int l = 0; l < Ln; l++) {
        float a0 = 0.f, a1 = 0.f, a2 = 0.f, a3 = 0.f;
#pragma unroll
        for (int s = 0; s < NPART; s += 4) {
            a0 += g_upart[(((size_t)(s + 0) * Bn + b) * Ln + l) * Dn + dg];
            a1 += g_upart[(((size_t)(s + 1) * Bn + b) * Ln + l) * Dn + dg];
            a2 += g_upart[(((size_t)(s + 2) * Bn + b) * Ln + l) * Dn + dg];
            a3 += g_upart[(((size_t)(s + 3) * Bn + b) * Ln + l) * Dn + dg];
        }
        g_U[((size_t)b * Ln + l) * Dn + dg] = ((a0 + a1) + (a2 + a3)) * inv[l];
    }
}

// ---------------- stage-2 scores + softmax over L=8 ----------------
__global__ void k_s2(int pl) {
    __shared__ float ks[Ln][Dn];
    int tid = threadIdx.x, b = blockIdx.y;
    for (int i = tid; i < Ln * Dn / 4; i += 256)
        ((float4*)ks)[i] = ((const float4*)(g_k2 + (size_t)b * Ln * Dn))[i];
    __syncthreads();
    int w = tid >> 5, lane = tid & 31;
    int p0 = blockIdx.x * 16 + w * 2;
    if (p0 > pl - 2) p0 = pl - 2;
    ull acc[2][Ln];
#pragma unroll
    for (int pp = 0; pp < 2; pp++)
#pragma unroll
        for (int l = 0; l < Ln; l++) acc[pp][l] = 0ULL;
#pragma unroll
    for (int i = 0; i < 8; i++) {
        int d = (lane + 32 * i) * 4;
        ulonglong2 q0 = *(const ulonglong2*)(g_qb2 + (size_t)p0 * Dn + d);
        ulonglong2 q1 = *(const ulonglong2*)(g_qb2 + (size_t)(p0 + 1) * Dn + d);
#pragma unroll
        for (int l = 0; l < Ln; l++) {
            ulonglong2 k = *(const ulonglong2*)&ks[l][d];
            fma2(acc[0][l], q0.x, k.x); fma2(acc[0][l], q0.y, k.y);
            fma2(acc[1][l], q1.x, k.x); fma2(acc[1][l], q1.y, k.y);
        }
    }
#pragma unroll
    for (int pp = 0; pp < 2; pp++) {
        float v[Ln];
#pragma unroll
        for (int l = 0; l < Ln; l++) {
            float2 f = u2f(acc[pp][l]);
            float s = f.x + f.y;
            for (int off = 16; off; off >>= 1)
                s += __shfl_xor_sync(0xffffffffu, s, off);
            v[l] = s;
        }
        if (lane == 0) {
            int p = p0 + pp;
            if (p < pl) {
                float m = v[0];
#pragma unroll
                for (int l = 1; l < Ln; l++) m = fmaxf(m, v[l]);
                float e[Ln], s = 0.f;
#pragma unroll
                for (int l = 0; l < Ln; l++) { e[l] = expf(v[l] - m); s += e[l]; }
                float inv = 1.0f / s;
#pragma unroll
                for (int l = 0; l < Ln; l++)
                    g_A2[((size_t)b * pl + p) * Ln + l] = e[l] * inv;
            }
        }
    }
}

// ---------------- gate select: 16 p per block ----------------
__global__ void k_gatesel(const float* __restrict__ w2, const float* __restrict__ b2,
                          const float* __restrict__ b1, int pl) {
    extern __shared__ float sm[];
    float* lvws = sm;                    // 8192
    float* w2T  = lvws + Ln * Dn;        // 16*1026
    float* hs   = w2T + 16 * 1026;       // 1024
    float* a2s  = hs + Dn;               // 128
    float* part = a2s + 128;             // 272
    float* lg   = part + 272;            // 16
    int tid = threadIdx.x, b = blockIdx.y, p0 = blockIdx.x * 16;
    for (int i = tid; i < Ln * Dn / 4; i += 256)
        ((float4*)lvws)[i] = ((const float4*)(g_lvw + (size_t)b * Ln * Dn))[i];
    for (int i = tid; i < Dn * En; i += 256) {
        int d = i >> 4, e = i & 15;
        w2T[e * 1026 + d] = w2[i];
    }
    if (tid < 128) {
        int pi = tid >> 3, l = tid & 7;
        int p = p0 + pi;
        a2s[tid] = (p < pl) ? g_A2[((size_t)b * pl + p) * Ln + l] : 0.f;
    }
    float4 b1v = *(const float4*)(b1 + tid * 4);
    __syncthreads();
    int e_id = tid & 15, dseg = tid >> 4;
    float4 bh_cur = (p0 < pl) ? *(const float4*)(g_bh + (size_t)p0 * Dn + tid * 4)
                              : make_float4(0, 0, 0, 0);
    for (int pi = 0; pi < 16; pi++) {
        int p = p0 + pi;
        if (p >= pl) break;
        // software-pipeline: kick off next-p bh load before this p's work
        float4 bh_next = (pi + 1 < 16 && p + 1 < pl)
            ? *(const float4*)(g_bh + (size_t)(p + 1) * Dn + tid * 4)
            : make_float4(0, 0, 0, 0);
        float4 s4 = bh_cur;
        s4.x += b1v.x; s4.y += b1v.y; s4.z += b1v.z; s4.w += b1v.w;
#pragma unroll
        for (int l = 0; l < Ln; l++) {
            float a = a2s[pi * 8 + l];
            float4 v = ((const float4*)lvws)[l * (Dn / 4) + tid];
            s4.x += a * v.x; s4.y += a * v.y; s4.z += a * v.z; s4.w += a * v.w;
        }
        float4 h4;
        h4.x = gelu_f(s4.x); h4.y = gelu_f(s4.y);
        h4.z = gelu_f(s4.z); h4.w = gelu_f(s4.w);
        ((float4*)hs)[tid] = h4;
        __syncthreads();
        ull lacc = 0ULL;
        int dbase = dseg * 64;
#pragma unroll
        for (int j = 0; j < 32; j++) {
            ull h2 = *(const ull*)&hs[dbase + 2 * j];
            ull wv = *(const ull*)&w2T[e_id * 1026 + dbase + 2 * j];
            fma2(lacc, h2, wv);
        }
        float2 lf = u2f(lacc);
        part[dseg * 17 + e_id] = lf.x + lf.y;
        __syncthreads();
        if (tid < En) {
            float L = b2[tid];
#pragma unroll
            for (int g = 0; g < 16; g++) L += part[g * 17 + tid];
            lg[tid] = L;
        }
        __syncthreads();
        if (tid == 0) {
            float b1s = lg[0]; int e1 = 0;
#pragma unroll
            for (int e = 1; e < En; e++) if (lg[e] > b1s) { b1s = lg[e]; e1 = e; }
            float b2s = -3.4e38f; int e2 = 0;
#pragma unroll
            for (int e = 0; e < En; e++)
                if (e != e1 && lg[e] > b2s) { b2s = lg[e]; e2 = e; }
            float x2 = expf(b2s - b1s);
            float s = 1.f + x2;
            g_sel[(size_t)b * pl + p] = make_float4(
                1.f / s, x2 / s, __int_as_float(e1), __int_as_float(e2));
        }
        __syncthreads();
        bh_cur = bh_next;
    }
}

// ---------------- combine experts ----------------
__global__ void k_combine(const float* __restrict__ qexp, float* __restrict__ out,
                          int pl, int Pfull) {
    __shared__ float4 sel[Bn];
    int p = blockIdx.x, tid = threadIdx.x;
    if (tid < Bn) sel[tid] = g_sel[(size_t)tid * pl + p];
    __syncthreads();
#pragma unroll 4
    for (int b = 0; b < Bn; b++) {
        float4 s = sel[b];
        int eA = __float_as_int(s.z), eB = __float_as_int(s.w);
        float4 va = *(const float4*)(qexp + ((size_t)eA * Pfull + p) * Dn + tid * 4);
        float4 vb = *(const float4*)(qexp + ((size_t)eB * Pfull + p) * Dn + tid * 4);
        float4 o;
        o.x = s.x * va.x + s.y * vb.x;
        o.y = s.x * va.y + s.y * vb.y;
        o.z = s.x * va.z + s.y * vb.z;
        o.w = s.x * va.w + s.y * vb.w;
        *(float4*)(out + ((size_t)b * pl + p) * Dn + tid * 4) = o;
    }
}

// ---------------- launch ----------------
extern "C" void kernel_launch(void* const* d_in, const int* in_sizes, int n_in,
                              void* d_out, int out_size) {
    const float* ctx        = (const float*)d_in[0];
    const float* qexp       = (const float*)d_in[1];
    const float* qpos       = (const float*)d_in[2];
    const float* ptbl       = (const float*)d_in[3];
    const float* lats       = (const float*)d_in[4];
    const float* lat_q_w    = (const float*)d_in[5];
    const float* ctx_k_w    = (const float*)d_in[6];
    const float* ctx_v_w    = (const float*)d_in[7];
    const float* lat_out_w  = (const float*)d_in[8];
    const float* step_q_w   = (const float*)d_in[9];
    const float* lat_k_w    = (const float*)d_in[10];
    const float* lat_v_w    = (const float*)d_in[11];
    const float* step_out_w = (const float*)d_in[12];
    const float* gate_w1    = (const float*)d_in[13];
    const float* gate_b1    = (const float*)d_in[14];
    const float* gate_w2    = (const float*)d_in[15];
    const float* gate_b2    = (const float*)d_in[16];
    float* out = (float*)d_out;

    int pl = out_size / (Bn * Dn);
    int Pfull = in_sizes[2] / Dn;

    float *p_t1p, *p_qeffp, *p_qeff, *p_U;
    float *p_pA, *p_pLC, *p_pkv, *p_pC, *p_plvw;
    float *p_lvw, *p_sb, *p_bcat, *p_bkv, *p_pcat;
    cudaGetSymbolAddress((void**)&p_t1p, g_t1p);
    cudaGetSymbolAddress((void**)&p_qeffp, g_qeffp);
    cudaGetSymbolAddress((void**)&p_qeff, g_qeff);
    cudaGetSymbolAddress((void**)&p_U, g_U);
    cudaGetSymbolAddress((void**)&p_pA, g_pA);
    cudaGetSymbolAddress((void**)&p_pLC, g_pLC);
    cudaGetSymbolAddress((void**)&p_pkv, g_pkv);
    cudaGetSymbolAddress((void**)&p_pC, g_pC);
    cudaGetSymbolAddress((void**)&p_plvw, g_plvw);
    cudaGetSymbolAddress((void**)&p_lvw, g_lvw);
    cudaGetSymbolAddress((void**)&p_sb, g_step_base);
    cudaGetSymbolAddress((void**)&p_bcat, g_bcat);
    cudaGetSymbolAddress((void**)&p_bkv, g_bkv);
    cudaGetSymbolAddress((void**)&p_pcat, g_pcat);

    const float inv_sqrt_d = 0.03125f;
    const int S = Bn * Ln * Dn;

    // 0-2: qeff = (latents @ lat_q_w) @ ctx_k_w^T / sqrt(D)
    k_gemm<<<dim3(16, 1, 8), 256>>>(lats, lat_q_w, p_t1p, Ln, Dn, Dn, 0, nullptr, 1.f, 1, 0);
    k_gemm<<<dim3(16, 1, 8), 256>>>(p_t1p, ctx_k_w, p_qeffp, Ln, Dn, Dn, 1, nullptr, inv_sqrt_d, 8, Ln * Dn);
    k_redN<<<8, 256>>>((float4*)p_qeff, (const float4*)p_qeffp, Ln * Dn / 4, 8, Ln * Dn / 4);

    // 3 (ncu-sampled slot): fused stage-1, single DRAM pass over ctx
    const int smem_f1 = (Ln * Dn + SUBSEG * Dn + SUBSEG * 16 + SUBSEG * 16) * 4;
    cudaFuncSetAttribute(k_fused1, cudaFuncAttributeMaxDynamicSharedMemorySize, smem_f1);
    k_fused1<<<dim3(NPART, Bn), 512, smem_f1>>>(ctx);

    // batch-independent prep
    k_stepbase<<<(pl * Dn + 255) / 256, 256>>>(qpos, ptbl, pl);
    k_pack2<<<Dn * 2048 / 4 / 256, 256>>>(step_q_w, gate_w1, p_bcat, inv_sqrt_d);
    k_pack2<<<Dn * 2048 / 4 / 256, 256>>>(lat_k_w, lat_v_w, p_bkv, 1.f);

    // packed [720,2048,1024] P-GEMM v3, split-K x4
    int gy2 = (pl + 127) / 128;
    k_gemm_v3<<<dim3(32, gy2, 4), 256>>>(p_sb, p_bcat, p_pcat, pl, 2048, Dn, Dn, 1.f, 1, 0);

    // stage-1 finish
    k_comb1<<<dim3(4, Bn), 256>>>();

    // chain: U -> pA -> pLC -> {k2 | pB merged} -> pC -> plvw
    k_gemm_v3<<<dim3(16, 2, 8), 256>>>(p_U,   ctx_v_w,   p_pA,  Bn * Ln, Dn, Dn, Dn, 1.f, 1, 0);
    k_gemm_v3<<<dim3(16, 2, 8), 256>>>(p_pA,  lat_out_w, p_pLC, Bn * Ln, Dn, Dn, Dn, 1.f, 8, S);
    k_gemm_v3<<<dim3(32, 2, 8), 256>>>(p_pLC, p_bkv,     p_pkv, Bn * Ln, 2048, Dn, Dn, 1.f, 8, S);
    k_redk2<<<S / 4 / 256, 256>>>();
    k_gemm_v3<<<dim3(16, 2, 8), 256>>>(p_pkv + 1024, step_out_w, p_pC, Bn * Ln, Dn, Dn, 2048, 1.f, 8, Bn * Ln * 2048);
    k_gemm_v3<<<dim3(16, 2, 8), 256>>>(p_pC, gate_w1 + (size_t)Dn * Dn, p_plvw, Bn * Ln, Dn, Dn, Dn, 1.f, 8, S);
    k_redN<<<S / 4 / 256, 256>>>((float4*)p_lvw, (const float4*)p_plvw, S / 4, 8, S / 4);

    // P-path reduction
    k_redsplit<<<(pl * 256 + 255) / 256, 256>>>(pl);

    // stage-2 attention weights
    k_s2<<<dim3((pl + 15) / 16, Bn), 256>>>(pl);

    // gate select (16 p per block) + streaming expert combine
    const int smem_gs = (Ln * Dn + 16 * 1026 + Dn + 128 + 272 + 16) * 4;
    cudaFuncSetAttribute(k_gatesel, cudaFuncAttributeMaxDynamicSharedMemorySize, smem_gs);
    k_gatesel<<<dim3((pl + 15) / 16, Bn), 256, smem_gs>>>(gate_w2, gate_b2, gate_b1, pl);
    k_combine<<<pl, 256>>>(qexp, out, pl, Pfull);
}

// round 12
// speedup vs baseline: 1.5943x; 1.0181x over previous
#include <cuda_runtime.h>
#include <math.h>
#include <stdint.h>

#define Bn 32
#define Tn 2048
#define Dn 1024
#define En 16
#define Ln 8
#define Pmax 720
#define SUBSEG 32
#define NSUB 2
#define NPART 32           // Tn/(SUBSEG*NSUB)

typedef unsigned long long ull;

__device__ __forceinline__ void fma2(ull& d, ull a, ull b) {
    asm("fma.rn.f32x2 %0, %1, %2, %0;" : "+l"(d) : "l"(a), "l"(b));
}
__device__ __forceinline__ float2 u2f(ull v) {
    float2 f; asm("mov.b64 {%0,%1}, %2;" : "=f"(f.x), "=f"(f.y) : "l"(v)); return f;
}
__device__ __forceinline__ ull pack2(float s) {
    ull d; asm("mov.b64 %0, {%1,%1};" : "=l"(d) : "f"(s)); return d;
}
__device__ __forceinline__ float gelu_f(float x) {
    return 0.5f * x * (1.0f + erff(x * 0.70710678118654752440f));
}

// ---------------- scratch ----------------
__device__ float g_step_base[Pmax * Dn];
__device__ float g_t1p[8 * Ln * Dn];
__device__ float g_qeffp[8 * Ln * Dn];
__device__ float g_qeff[Ln * Dn];
__device__ float g_ssum[Bn * Ln * NPART];
__device__ float g_upart[(size_t)NPART * Bn * Ln * Dn];   // 33.5MB
__device__ float g_U[Bn * Ln * Dn];
__device__ float g_pA[8 * Bn * Ln * Dn];
__device__ float g_pLC[8 * Bn * Ln * Dn];
__device__ float g_pkv[8 * Bn * Ln * 2048];
__device__ float g_pC[8 * Bn * Ln * Dn];
__device__ float g_plvw[8 * Bn * Ln * Dn];
__device__ float g_k2[Bn * Ln * Dn];
__device__ float g_lvw[Bn * Ln * Dn];
__device__ float g_bcat[Dn * 2048];
__device__ float g_bkv[Dn * 2048];
__device__ float g_pcat[4 * Pmax * 2048];
__device__ float g_qb2[Pmax * Dn];
__device__ float g_bh[Pmax * Dn];
__device__ float g_A2[Bn * Pmax * Ln];
__device__ float4 g_sel[Bn * Pmax];

// ---------------- step_base ----------------
__global__ void k_stepbase(const float* __restrict__ qpos,
                           const float* __restrict__ tbl, int pl) {
    int i = blockIdx.x * 256 + threadIdx.x;
    if (i < pl * Dn)
        g_step_base[i] = qpos[i] + tbl[(size_t)pl * Dn + (i & (Dn - 1))];
}

// ---------------- pack two [1024,1024] B's side by side ----------------
__global__ void k_pack2(const float* __restrict__ w_left, const float* __restrict__ w_right,
                        float* __restrict__ dst, float alphaL) {
    int i = blockIdx.x * 256 + threadIdx.x;
    int row = i >> 9;
    int c4 = i & 511;
    float4 v;
    if (c4 < 256) {
        v = ((const float4*)w_left)[row * 256 + c4];
        v.x *= alphaL; v.y *= alphaL; v.z *= alphaL; v.w *= alphaL;
    } else {
        v = ((const float4*)w_right)[row * 256 + (c4 - 256)];
    }
    ((float4*)dst)[i] = v;
}

// ---------------- 64x64 fp32x2 GEMM v2 (thin M=8 qeff GEMMs) ----------------
__global__ void k_gemm(const float* __restrict__ A, const float* __restrict__ B,
                       float* __restrict__ C, int M, int N, int K,
                       int transB, const float* __restrict__ bias, float alpha,
                       int nsumA, int strideA) {
    __shared__ float As[2][16][68];
    __shared__ float Bs[2][16][68];
    int tid = threadIdx.x;
    int tx = tid & 15, ty = tid >> 4;
    int m0 = blockIdx.y * 64, n0 = blockIdx.x * 64;
    int kper = K / gridDim.z;
    int kbeg = blockIdx.z * kper;
    C += (size_t)blockIdx.z * M * N;
    int nk = kper / 16;

    ull acc[4][2];
#pragma unroll
    for (int i = 0; i < 4; i++) { acc[i][0] = 0ULL; acc[i][1] = 0ULL; }

    float4 va, vb4;
    float ra[4], rb[4];
    int am = tid >> 2, ak4 = tid & 3;
    int bk = tid >> 4, bn4 = tid & 15;

#define PREF_V(k0)                                                               \
    {                                                                            \
        int gm = m0 + am;                                                        \
        va = make_float4(0.f, 0.f, 0.f, 0.f);                                    \
        if (gm < M) {                                                            \
            const float* ap = A + (size_t)gm * K + (k0) + ak4 * 4;               \
            va = *(const float4*)ap;                                             \
            for (int s = 1; s < nsumA; s++) {                                    \
                float4 t = *(const float4*)(ap + (size_t)s * strideA);           \
                va.x += t.x; va.y += t.y; va.z += t.z; va.w += t.w;              \
            }                                                                    \
        }                                                                        \
        vb4 = *(const float4*)(B + (size_t)((k0) + bk) * N + n0 + bn4 * 4);      \
    }
#define STORE_V(bf)                                                              \
    {                                                                            \
        As[bf][ak4 * 4 + 0][am] = va.x;                                          \
        As[bf][ak4 * 4 + 1][am] = va.y;                                          \
        As[bf][ak4 * 4 + 2][am] = va.z;                                          \
        As[bf][ak4 * 4 + 3][am] = va.w;                                          \
        *(float4*)&Bs[bf][bk][bn4 * 4] = vb4;                                    \
    }
#define PREF_S(k0)                                                               \
    {                                                                            \
        for (int r = 0; r < 4; r++) {                                            \
            int i = tid + 256 * r;                                               \
            int row = i >> 4, col = i & 15;                                      \
            int gm = m0 + row;                                                   \
            float v = 0.f;                                                       \
            if (gm < M) {                                                        \
                size_t off = (size_t)gm * K + (k0) + col;                        \
                v = A[off];                                                      \
                for (int s = 1; s < nsumA; s++) v += A[off + (size_t)s * strideA]; \
            }                                                                    \
            ra[r] = v;                                                           \
        }                                                                        \
        for (int r = 0; r < 4; r++) {                                            \
            int i = tid + 256 * r;                                               \
            rb[r] = B[(size_t)(n0 + (i >> 4)) * K + (k0) + (i & 15)];            \
        }                                                                        \
    }
#define STORE_S(bf)                                                              \
    {                                                                            \
        for (int r = 0; r < 4; r++) {                                            \
            int i = tid + 256 * r;                                               \
            As[bf][i & 15][i >> 4] = ra[r];                                      \
        }                                                                        \
        for (int r = 0; r < 4; r++) {                                            \
            int i = tid + 256 * r;                                               \
            Bs[bf][i & 15][i >> 4] = rb[r];                                      \
        }                                                                        \
    }
#define COMPUTE(bf)                                                              \
    {                                                                            \
        _Pragma("unroll")                                                        \
        for (int kk = 0; kk < 16; kk++) {                                        \
            float4 a4 = *(const float4*)&As[bf][kk][ty * 4];                     \
            ulonglong2 bb = *(const ulonglong2*)&Bs[bf][kk][tx * 4];             \
            ull a0 = pack2(a4.x), a1 = pack2(a4.y);                              \
            ull a2 = pack2(a4.z), a3 = pack2(a4.w);                              \
            fma2(acc[0][0], a0, bb.x); fma2(acc[0][1], a0, bb.y);                \
            fma2(acc[1][0], a1, bb.x); fma2(acc[1][1], a1, bb.y);                \
            fma2(acc[2][0], a2, bb.x); fma2(acc[2][1], a2, bb.y);                \
            fma2(acc[3][0], a3, bb.x); fma2(acc[3][1], a3, bb.y);                \
        }                                                                        \
    }

    int buf = 0;
    if (!transB) {
        PREF_V(kbeg);
        STORE_V(0);
        __syncthreads();
        for (int kt = 0; kt < nk; kt++) {
            if (kt + 1 < nk) PREF_V(kbeg + (kt + 1) * 16);
            COMPUTE(buf);
            if (kt + 1 < nk) {
                STORE_V(buf ^ 1);
                __syncthreads();
                buf ^= 1;
            }
        }
    } else {
        PREF_S(kbeg);
        STORE_S(0);
        __syncthreads();
        for (int kt = 0; kt < nk; kt++) {
            if (kt + 1 < nk) PREF_S(kbeg + (kt + 1) * 16);
            COMPUTE(buf);
            if (kt + 1 < nk) {
                STORE_S(buf ^ 1);
                __syncthreads();
                buf ^= 1;
            }
        }
    }
#pragma unroll
    for (int i = 0; i < 4; i++) {
        int m = m0 + ty * 4 + i;
        if (m >= M) continue;
        float2 p0 = u2f(acc[i][0]), p1 = u2f(acc[i][1]);
        float4 o;
        o.x = alpha * p0.x; o.y = alpha * p0.y;
        o.z = alpha * p1.x; o.w = alpha * p1.y;
        if (bias) {
            o.x += bias[n0 + tx * 4];     o.y += bias[n0 + tx * 4 + 1];
            o.z += bias[n0 + tx * 4 + 2]; o.w += bias[n0 + tx * 4 + 3];
        }
        *(float4*)&C[(size_t)m * N + n0 + tx * 4] = o;
    }
}

// ---------------- 128x64 fp32x2 GEMM v3 (lda-aware) ----------------
__global__ void __launch_bounds__(256) k_gemm_v3(
    const float* __restrict__ A, const float* __restrict__ B,
    float* __restrict__ C, int M, int N, int K, int lda,
    float alpha, int nsumA, int strideA) {
    __shared__ float As[2][16][132];
    __shared__ float Bs[2][16][68];
    int tid = threadIdx.x;
    int tx = tid & 15, ty = tid >> 4;
    int m0 = blockIdx.y * 128, n0 = blockIdx.x * 64;
    int kper = K / gridDim.z;
    int kbeg = blockIdx.z * kper;
    C += (size_t)blockIdx.z * M * N;
    int nk = kper / 16;

    ull acc[8][2];
#pragma unroll
    for (int i = 0; i < 8; i++) { acc[i][0] = 0ULL; acc[i][1] = 0ULL; }

    float4 va0, va1, vb4;
    int ar = tid >> 2, ak4 = tid & 3;
    int bk = tid >> 4, bn4 = tid & 15;

#define V3_PREF(k0)                                                              \
    {                                                                            \
        int gm0 = m0 + ar, gm1 = m0 + 64 + ar;                                   \
        va0 = make_float4(0.f, 0.f, 0.f, 0.f);                                   \
        va1 = va0;                                                               \
        if (gm0 < M) {                                                           \
            const float* ap = A + (size_t)gm0 * lda + (k0) + ak4 * 4;            \
            va0 = *(const float4*)ap;                                            \
            for (int s = 1; s < nsumA; s++) {                                    \
                float4 t = *(const float4*)(ap + (size_t)s * strideA);           \
                va0.x += t.x; va0.y += t.y; va0.z += t.z; va0.w += t.w;          \
            }                                                                    \
        }                                                                        \
        if (gm1 < M) {                                                           \
            const float* ap = A + (size_t)gm1 * lda + (k0) + ak4 * 4;            \
            va1 = *(const float4*)ap;                                            \
            for (int s = 1; s < nsumA; s++) {                                    \
                float4 t = *(const float4*)(ap + (size_t)s * strideA);           \
                va1.x += t.x; va1.y += t.y; va1.z += t.z; va1.w += t.w;          \
            }                                                                    \
        }                                                                        \
        vb4 = *(const float4*)(B + (size_t)((k0) + bk) * N + n0 + bn4 * 4);      \
    }
#define V3_STORE(bf)                                                             \
    {                                                                            \
        As[bf][ak4 * 4 + 0][ar] = va0.x;                                         \
        As[bf][ak4 * 4 + 1][ar] = va0.y;                                         \
        As[bf][ak4 * 4 + 2][ar] = va0.z;                                         \
        As[bf][ak4 * 4 + 3][ar] = va0.w;                                         \
        As[bf][ak4 * 4 + 0][64 + ar] = va1.x;                                    \
        As[bf][ak4 * 4 + 1][64 + ar] = va1.y;                                    \
        As[bf][ak4 * 4 + 2][64 + ar] = va1.z;                                    \
        As[bf][ak4 * 4 + 3][64 + ar] = va1.w;                                    \
        *(float4*)&Bs[bf][bk][bn4 * 4] = vb4;                                    \
    }
#define V3_COMP(bf)                                                              \
    {                                                                            \
        _Pragma("unroll")                                                        \
        for (int kk = 0; kk < 16; kk++) {                                        \
            float4 a0 = *(const float4*)&As[bf][kk][ty * 8];                     \
            float4 a1 = *(const float4*)&As[bf][kk][ty * 8 + 4];                 \
            ulonglong2 bb = *(const ulonglong2*)&Bs[bf][kk][tx * 4];             \
            ull p0 = pack2(a0.x), p1 = pack2(a0.y);                              \
            ull p2 = pack2(a0.z), p3 = pack2(a0.w);                              \
            ull p4 = pack2(a1.x), p5 = pack2(a1.y);                              \
            ull p6 = pack2(a1.z), p7 = pack2(a1.w);                              \
            fma2(acc[0][0], p0, bb.x); fma2(acc[0][1], p0, bb.y);                \
            fma2(acc[1][0], p1, bb.x); fma2(acc[1][1], p1, bb.y);                \
            fma2(acc[2][0], p2, bb.x); fma2(acc[2][1], p2, bb.y);                \
            fma2(acc[3][0], p3, bb.x); fma2(acc[3][1], p3, bb.y);                \
            fma2(acc[4][0], p4, bb.x); fma2(acc[4][1], p4, bb.y);                \
            fma2(acc[5][0], p5, bb.x); fma2(acc[5][1], p5, bb.y);                \
            fma2(acc[6][0], p6, bb.x); fma2(acc[6][1], p6, bb.y);                \
            fma2(acc[7][0], p7, bb.x); fma2(acc[7][1], p7, bb.y);                \
        }                                                                        \
    }

    int buf = 0;
    V3_PREF(kbeg);
    V3_STORE(0);
    __syncthreads();
    for (int kt = 0; kt < nk; kt++) {
        if (kt + 1 < nk) V3_PREF(kbeg + (kt + 1) * 16);
        V3_COMP(buf);
        if (kt + 1 < nk) {
            V3_STORE(buf ^ 1);
            __syncthreads();
            buf ^= 1;
        }
    }
#pragma unroll
    for (int i = 0; i < 8; i++) {
        int m = m0 + ty * 8 + i;
        if (m >= M) continue;
        float2 p0 = u2f(acc[i][0]), p1 = u2f(acc[i][1]);
        float4 o;
        o.x = alpha * p0.x; o.y = alpha * p0.y;
        o.z = alpha * p1.x; o.w = alpha * p1.y;
        *(float4*)&C[(size_t)m * N + n0 + tx * 4] = o;
    }
}

// ---------------- generic partial reduction ----------------
__global__ void k_redN(float4* __restrict__ dst, const float4* __restrict__ src,
                       int n4, int nparts, int stride4) {
    int i = blockIdx.x * 256 + threadIdx.x;
    if (i >= n4) return;
    float4 s = src[i];
    for (int p = 1; p < nparts; p++) {
        float4 t = src[i + (size_t)p * stride4];
        s.x += t.x; s.y += t.y; s.z += t.z; s.w += t.w;
    }
    dst[i] = s;
}

// ---------------- reduce k2 half of merged pkv partials ----------------
__global__ void k_redk2() {
    int i = blockIdx.x * 256 + threadIdx.x;
    int m = i >> 8, d4 = i & 255;
    const float4* s = (const float4*)g_pkv;
    size_t base = (size_t)m * 512 + d4;
    size_t part = (size_t)Bn * Ln * 512;
    float4 a = s[base];
#pragma unroll
    for (int z = 1; z < 8; z++) {
        float4 t = s[base + z * part];
        a.x += t.x; a.y += t.y; a.z += t.z; a.w += t.w;
    }
    ((float4*)g_k2)[i] = a;
}

// ---------------- de-interleave + reduce the packed P-GEMM (4 partials) ----------
__global__ void k_redsplit(int pl) {
    int i = blockIdx.x * 256 + threadIdx.x;
    if (i >= pl * 256) return;
    int p = i >> 8, d4 = i & 255;
    const float4* s = (const float4*)g_pcat;
    size_t base = (size_t)p * 512 + d4;
    size_t part = (size_t)pl * 512;
    float4 q = s[base], h = s[base + 256];
#pragma unroll
    for (int z = 1; z < 4; z++) {
        float4 tq = s[base + z * part], th = s[base + 256 + z * part];
        q.x += tq.x; q.y += tq.y; q.z += tq.z; q.w += tq.w;
        h.x += th.x; h.y += th.y; h.z += th.z; h.w += th.w;
    }
    ((float4*)g_qb2)[i] = q;
    ((float4*)g_bh)[i] = h;
}

// ---------------- fused stage-1 v2: no ck smem, L2-hot second read ----------------
// grid (NPART=32, Bn), 256 threads (8 warps), ~35KB smem, 2 blocks/SM target.
// Each block: 2 sub-segments of 32 tokens.
//   phase A: warp w owns tokens w*4..w*4+3, FULL d; scores from GMEM loads directly.
//   phase C: thread owns 4 d; re-reads the 32-token tile from GMEM (L2 hit).
__global__ void __launch_bounds__(256, 2) k_fused1(const float* __restrict__ ctx) {
    extern __shared__ float smf[];
    float* qs  = smf;                    // 8*1024 = 32KB
    float* ps2 = qs + Ln * Dn;           // [tt][2l] dup pairs: 32*16
    float* prt = ps2 + SUBSEG * 16;      // [tt][l]: 32*8
    int tid = threadIdx.x;
    for (int i = tid; i < Ln * Dn / 4; i += 256)
        ((float4*)qs)[i] = ((const float4*)g_qeff)[i];
    int b = blockIdx.y;
    int w = tid >> 5, lane = tid & 31;

    ull uacc[Ln][2];
#pragma unroll
    for (int l = 0; l < Ln; l++) { uacc[l][0] = 0ULL; uacc[l][1] = 0ULL; }
    float ssum = 0.f;   // warp w accumulates exp-sum for l = w

    for (int sub = 0; sub < NSUB; sub++) {
        int t0 = (blockIdx.x * NSUB + sub) * SUBSEG;
        const float* base = ctx + ((size_t)b * Tn + t0 + w * 4) * Dn;
        __syncthreads();  // ps2/prt free before overwrite

        // phase A: 4 token rows x full d per warp; no smem staging of ctx
        ull acc[4][Ln];
#pragma unroll
        for (int tt = 0; tt < 4; tt++)
#pragma unroll
            for (int l = 0; l < Ln; l++) acc[tt][l] = 0ULL;
#pragma unroll
        for (int i = 0; i < 8; i++) {
            int d = (lane + 32 * i) * 4;
            ulonglong2 c0 = *(const ulonglong2*)(base + d);
            ulonglong2 c1 = *(const ulonglong2*)(base + Dn + d);
            ulonglong2 c2 = *(const ulonglong2*)(base + 2 * Dn + d);
            ulonglong2 c3 = *(const ulonglong2*)(base + 3 * Dn + d);
#pragma unroll
            for (int l = 0; l < Ln; l++) {
                ulonglong2 q = *(const ulonglong2*)&qs[l * Dn + d];
                fma2(acc[0][l], c0.x, q.x); fma2(acc[0][l], c0.y, q.y);
                fma2(acc[1][l], c1.x, q.x); fma2(acc[1][l], c1.y, q.y);
                fma2(acc[2][l], c2.x, q.x); fma2(acc[2][l], c2.y, q.y);
                fma2(acc[3][l], c3.x, q.x); fma2(acc[3][l], c3.y, q.y);
            }
        }
#pragma unroll
        for (int tt = 0; tt < 4; tt++)
#pragma unroll
            for (int l = 0; l < Ln; l++) {
                float2 f = u2f(acc[tt][l]);
                float v = f.x + f.y;
                for (int off = 16; off; off >>= 1)
                    v += __shfl_xor_sync(0xffffffffu, v, off);
                if (lane == 0)
                    prt[(w * 4 + tt) * 8 + l] = v;
            }
        __syncthreads();

        // exp (shift-free softmax; scores tiny, clamp for safety)
        {
            int tt = tid >> 3, l = tid & 7;
            float e = expf(fminf(prt[tt * 8 + l], 60.0f));
            ps2[tt * 16 + 2 * l] = e;
            ps2[tt * 16 + 2 * l + 1] = e;
        }
        __syncthreads();

        // phase B: warp w accumulates exp-sum for l = w (lane = tt)
        {
            float s = ps2[lane * 16 + 2 * w];
            for (int off = 16; off; off >>= 1)
                s += __shfl_xor_sync(0xffffffffu, s, off);
            ssum += s;
        }

        // phase C: U accumulation; ctx tile re-read from GMEM (L2-hot)
        const float* cb = ctx + ((size_t)b * Tn + t0) * Dn + tid * 4;
#pragma unroll 2
        for (int tt = 0; tt < SUBSEG; tt++) {
            float4 cf = *(const float4*)(cb + (size_t)tt * Dn);
            ull cx, cy;
            asm("mov.b64 %0, {%1,%2};" : "=l"(cx) : "f"(cf.x), "f"(cf.y));
            asm("mov.b64 %0, {%1,%2};" : "=l"(cy) : "f"(cf.z), "f"(cf.w));
            ulonglong2 p01 = *(const ulonglong2*)&ps2[tt * 16];
            ulonglong2 p23 = *(const ulonglong2*)&ps2[tt * 16 + 4];
            ulonglong2 p45 = *(const ulonglong2*)&ps2[tt * 16 + 8];
            ulonglong2 p67 = *(const ulonglong2*)&ps2[tt * 16 + 12];
            fma2(uacc[0][0], p01.x, cx); fma2(uacc[0][1], p01.x, cy);
            fma2(uacc[1][0], p01.y, cx); fma2(uacc[1][1], p01.y, cy);
            fma2(uacc[2][0], p23.x, cx); fma2(uacc[2][1], p23.x, cy);
            fma2(uacc[3][0], p23.y, cx); fma2(uacc[3][1], p23.y, cy);
            fma2(uacc[4][0], p45.x, cx); fma2(uacc[4][1], p45.x, cy);
            fma2(uacc[5][0], p45.y, cx); fma2(uacc[5][1], p45.y, cy);
            fma2(uacc[6][0], p67.x, cx); fma2(uacc[6][1], p67.x, cy);
            fma2(uacc[7][0], p67.y, cx); fma2(uacc[7][1], p67.y, cy);
        }
    }
#pragma unroll
    for (int l = 0; l < Ln; l++) {
        float2 f0 = u2f(uacc[l][0]), f1 = u2f(uacc[l][1]);
        *(float4*)&g_upart[(((size_t)blockIdx.x * Bn + b) * Ln + l) * Dn + tid * 4] =
            make_float4(f0.x, f0.y, f1.x, f1.y);
    }
    if (lane == 0)
        g_ssum[((size_t)b * Ln + w) * NPART + blockIdx.x] = ssum;
}

// ---------------- combine stage-1 partials ----------------
__global__ void k_comb1() {
    __shared__ float inv[Ln];
    int b = blockIdx.y, dc = blockIdx.x;
    int tid = threadIdx.x;
    if (tid < Ln) {
        float s0 = 0.f, s1 = 0.f, s2 = 0.f, s3 = 0.f;
#pragma unroll
        for (int g = 0; g < NPART; g += 4) {
            s0 += g_ssum[((size_t)b * Ln + tid) * NPART + g];
            s1 += g_ssum[((size_t)b * Ln + tid) * NPART + g + 1];
            s2 += g_ssum[((size_t)b * Ln + tid) * NPART + g + 2];
            s3 += g_ssum[((size_t)b * Ln + tid) * NPART + g + 3];
        }
        inv[tid] = 1.0f / ((s0 + s1) + (s2 + s3));
    }
    __syncthreads();
    int dg = dc * 256 + tid;
#pragma unroll
    for (int l = 0; l < Ln; l++) {
        float a0 = 0.f, a1 = 0.f, a2 = 0.f, a3 = 0.f;
#pragma unroll
        for (int s = 0; s < NPART; s += 4) {
            a0 += g_upart[(((size_t)(s + 0) * Bn + b) * Ln + l) * Dn + dg];
            a1 += g_upart[(((size_t)(s + 1) * Bn + b) * Ln + l) * Dn + dg];
            a2 += g_upart[(((size_t)(s + 2) * Bn + b) * Ln + l) * Dn + dg];
            a3 += g_upart[(((size_t)(s + 3) * Bn + b) * Ln + l) * Dn + dg];
        }
        g_U[((size_t)b * Ln + l) * Dn + dg] = ((a0 + a1) + (a2 + a3)) * inv[l];
    }
}

// ---------------- stage-2 scores + softmax over L=8 ----------------
__global__ void k_s2(int pl) {
    __shared__ float ks[Ln][Dn];
    int tid = threadIdx.x, b = blockIdx.y;
    for (int i = tid; i < Ln * Dn / 4; i += 256)
        ((float4*)ks)[i] = ((const float4*)(g_k2 + (size_t)b * Ln * Dn))[i];
    __syncthreads();
    int w = tid >> 5, lane = tid & 31;
    int p0 = blockIdx.x * 16 + w * 2;
    if (p0 > pl - 2) p0 = pl - 2;
    ull acc[2][Ln];
#pragma unroll
    for (int pp = 0; pp < 2; pp++)
#pragma unroll
        for (int l = 0; l < Ln; l++) acc[pp][l] = 0ULL;
#pragma unroll
    for (int i = 0; i < 8; i++) {
        int d = (lane + 32 * i) * 4;
        ulonglong2 q0 = *(const ulonglong2*)(g_qb2 + (size_t)p0 * Dn + d);
        ulonglong2 q1 = *(const ulonglong2*)(g_qb2 + (size_t)(p0 + 1) * Dn + d);
#pragma unroll
        for (int l = 0; l < Ln; l++) {
            ulonglong2 k = *(const ulonglong2*)&ks[l][d];
            fma2(acc[0][l], q0.x, k.x); fma2(acc[0][l], q0.y, k.y);
            fma2(acc[1][l], q1.x, k.x); fma2(acc[1][l], q1.y, k.y);
        }
    }
#pragma unroll
    for (int pp = 0; pp < 2; pp++) {
        float v[Ln];
#pragma unroll
        for (int l = 0; l < Ln; l++) {
            float2 f = u2f(acc[pp][l]);
            float s = f.x + f.y;
            for (int off = 16; off; off >>= 1)
                s += __shfl_xor_sync(0xffffffffu, s, off);
            v[l] = s;
        }
        if (lane == 0) {
            int p = p0 + pp;
            if (p < pl) {
                float m = v[0];
#pragma unroll
                for (int l = 1; l < Ln; l++) m = fmaxf(m, v[l]);
                float e[Ln], s = 0.f;
#pragma unroll
                for (int l = 0; l < Ln; l++) { e[l] = expf(v[l] - m); s += e[l]; }
                float inv = 1.0f / s;
#pragma unroll
                for (int l = 0; l < Ln; l++)
                    g_A2[((size_t)b * pl + p) * Ln + l] = e[l] * inv;
            }
        }
    }
}

// ---------------- gate select: 16 p per block ----------------
__global__ void k_gatesel(const float* __restrict__ w2, const float* __restrict__ b2,
                          const float* __restrict__ b1, int pl) {
    extern __shared__ float sm[];
    float* lvws = sm;
    float* w2T  = lvws + Ln * Dn;
    float* hs   = w2T + 16 * 1026;
    float* a2s  = hs + Dn;
    float* part = a2s + 128;
    float* lg   = part + 272;
    int tid = threadIdx.x, b = blockIdx.y, p0 = blockIdx.x * 16;
    for (int i = tid; i < Ln * Dn / 4; i += 256)
        ((float4*)lvws)[i] = ((const float4*)(g_lvw + (size_t)b * Ln * Dn))[i];
    for (int i = tid; i < Dn * En; i += 256) {
        int d = i >> 4, e = i & 15;
        w2T[e * 1026 + d] = w2[i];
    }
    if (tid < 128) {
        int pi = tid >> 3, l = tid & 7;
        int p = p0 + pi;
        a2s[tid] = (p < pl) ? g_A2[((size_t)b * pl + p) * Ln + l] : 0.f;
    }
    float4 b1v = *(const float4*)(b1 + tid * 4);
    __syncthreads();
    int e_id = tid & 15, dseg = tid >> 4;
    float4 bh_cur = (p0 < pl) ? *(const float4*)(g_bh + (size_t)p0 * Dn + tid * 4)
                              : make_float4(0, 0, 0, 0);
    for (int pi = 0; pi < 16; pi++) {
        int p = p0 + pi;
        if (p >= pl) break;
        float4 bh_next = (pi + 1 < 16 && p + 1 < pl)
            ? *(const float4*)(g_bh + (size_t)(p + 1) * Dn + tid * 4)
            : make_float4(0, 0, 0, 0);
        float4 s4 = bh_cur;
        s4.x += b1v.x; s4.y += b1v.y; s4.z += b1v.z; s4.w += b1v.w;
#pragma unroll
        for (int l = 0; l < Ln; l++) {
            float a = a2s[pi * 8 + l];
            float4 v = ((const float4*)lvws)[l * (Dn / 4) + tid];
            s4.x += a * v.x; s4.y += a * v.y; s4.z += a * v.z; s4.w += a * v.w;
        }
        float4 h4;
        h4.x = gelu_f(s4.x); h4.y = gelu_f(s4.y);
        h4.z = gelu_f(s4.z); h4.w = gelu_f(s4.w);
        ((float4*)hs)[tid] = h4;
        __syncthreads();
        ull lacc = 0ULL;
        int dbase = dseg * 64;
#pragma unroll
        for (int j = 0; j < 32; j++) {
            ull h2 = *(const ull*)&hs[dbase + 2 * j];
            ull wv = *(const ull*)&w2T[e_id * 1026 + dbase + 2 * j];
            fma2(lacc, h2, wv);
        }
        float2 lf = u2f(lacc);
        part[dseg * 17 + e_id] = lf.x + lf.y;
        __syncthreads();
        if (tid < En) {
            float L = b2[tid];
#pragma unroll
            for (int g = 0; g < 16; g++) L += part[g * 17 + tid];
            lg[tid] = L;
        }
        __syncthreads();
        if (tid == 0) {
            float b1s = lg[0]; int e1 = 0;
#pragma unroll
            for (int e = 1; e < En; e++) if (lg[e] > b1s) { b1s = lg[e]; e1 = e; }
            float b2s = -3.4e38f; int e2 = 0;
#pragma unroll
            for (int e = 0; e < En; e++)
                if (e != e1 && lg[e] > b2s) { b2s = lg[e]; e2 = e; }
            float x2 = expf(b2s - b1s);
            float s = 1.f + x2;
            g_sel[(size_t)b * pl + p] = make_float4(
                1.f / s, x2 / s, __int_as_float(e1), __int_as_float(e2));
        }
        __syncthreads();
        bh_cur = bh_next;
    }
}

// ---------------- combine experts ----------------
__global__ void k_combine(const float* __restrict__ qexp, float* __restrict__ out,
                          int pl, int Pfull) {
    __shared__ float4 sel[Bn];
    int p = blockIdx.x, tid = threadIdx.x;
    if (tid < Bn) sel[tid] = g_sel[(size_t)tid * pl + p];
    __syncthreads();
#pragma unroll 4
    for (int b = 0; b < Bn; b++) {
        float4 s = sel[b];
        int eA = __float_as_int(s.z), eB = __float_as_int(s.w);
        float4 va = *(const float4*)(qexp + ((size_t)eA * Pfull + p) * Dn + tid * 4);
        float4 vb = *(const float4*)(qexp + ((size_t)eB * Pfull + p) * Dn + tid * 4);
        float4 o;
        o.x = s.x * va.x + s.y * vb.x;
        o.y = s.x * va.y + s.y * vb.y;
        o.z = s.x * va.z + s.y * vb.z;
        o.w = s.x * va.w + s.y * vb.w;
        *(float4*)(out + ((size_t)b * pl + p) * Dn + tid * 4) = o;
    }
}

// ---------------- launch ----------------
extern "C" void kernel_launch(void* const* d_in, const int* in_sizes, int n_in,
                              void* d_out, int out_size) {
    const float* ctx        = (const float*)d_in[0];
    const float* qexp       = (const float*)d_in[1];
    const float* qpos       = (const float*)d_in[2];
    const float* ptbl       = (const float*)d_in[3];
    const float* lats       = (const float*)d_in[4];
    const float* lat_q_w    = (const float*)d_in[5];
    const float* ctx_k_w    = (const float*)d_in[6];
    const float* ctx_v_w    = (const float*)d_in[7];
    const float* lat_out_w  = (const float*)d_in[8];
    const float* step_q_w   = (const float*)d_in[9];
    const float* lat_k_w    = (const float*)d_in[10];
    const float* lat_v_w    = (const float*)d_in[11];
    const float* step_out_w = (const float*)d_in[12];
    const float* gate_w1    = (const float*)d_in[13];
    const float* gate_b1    = (const float*)d_in[14];
    const float* gate_w2    = (const float*)d_in[15];
    const float* gate_b2    = (const float*)d_in[16];
    float* out = (float*)d_out;

    int pl = out_size / (Bn * Dn);
    int Pfull = in_sizes[2] / Dn;

    float *p_t1p, *p_qeffp, *p_qeff, *p_U;
    float *p_pA, *p_pLC, *p_pkv, *p_pC, *p_plvw;
    float *p_lvw, *p_sb, *p_bcat, *p_bkv, *p_pcat;
    cudaGetSymbolAddress((void**)&p_t1p, g_t1p);
    cudaGetSymbolAddress((void**)&p_qeffp, g_qeffp);
    cudaGetSymbolAddress((void**)&p_qeff, g_qeff);
    cudaGetSymbolAddress((void**)&p_U, g_U);
    cudaGetSymbolAddress((void**)&p_pA, g_pA);
    cudaGetSymbolAddress((void**)&p_pLC, g_pLC);
    cudaGetSymbolAddress((void**)&p_pkv, g_pkv);
    cudaGetSymbolAddress((void**)&p_pC, g_pC);
    cudaGetSymbolAddress((void**)&p_plvw, g_plvw);
    cudaGetSymbolAddress((void**)&p_lvw, g_lvw);
    cudaGetSymbolAddress((void**)&p_sb, g_step_base);
    cudaGetSymbolAddress((void**)&p_bcat, g_bcat);
    cudaGetSymbolAddress((void**)&p_bkv, g_bkv);
    cudaGetSymbolAddress((void**)&p_pcat, g_pcat);

    const float inv_sqrt_d = 0.03125f;
    const int S = Bn * Ln * Dn;

    // 0-2: qeff = (latents @ lat_q_w) @ ctx_k_w^T / sqrt(D)
    k_gemm<<<dim3(16, 1, 8), 256>>>(lats, lat_q_w, p_t1p, Ln, Dn, Dn, 0, nullptr, 1.f, 1, 0);
    k_gemm<<<dim3(16, 1, 8), 256>>>(p_t1p, ctx_k_w, p_qeffp, Ln, Dn, Dn, 1, nullptr, inv_sqrt_d, 8, Ln * Dn);
    k_redN<<<8, 256>>>((float4*)p_qeff, (const float4*)p_qeffp, Ln * Dn / 4, 8, Ln * Dn / 4);

    // 3 (ncu-sampled slot): fused stage-1 v2
    const int smem_f1 = (Ln * Dn + SUBSEG * 16 + SUBSEG * 8) * 4;
    cudaFuncSetAttribute(k_fused1, cudaFuncAttributeMaxDynamicSharedMemorySize, smem_f1);
    k_fused1<<<dim3(NPART, Bn), 256, smem_f1>>>(ctx);

    // batch-independent prep
    k_stepbase<<<(pl * Dn + 255) / 256, 256>>>(qpos, ptbl, pl);
    k_pack2<<<Dn * 2048 / 4 / 256, 256>>>(step_q_w, gate_w1, p_bcat, inv_sqrt_d);
    k_pack2<<<Dn * 2048 / 4 / 256, 256>>>(lat_k_w, lat_v_w, p_bkv, 1.f);

    // packed [720,2048,1024] P-GEMM v3, split-K x4
    int gy2 = (pl + 127) / 128;
    k_gemm_v3<<<dim3(32, gy2, 4), 256>>>(p_sb, p_bcat, p_pcat, pl, 2048, Dn, Dn, 1.f, 1, 0);

    // stage-1 finish
    k_comb1<<<dim3(4, Bn), 256>>>();

    // chain: U -> pA -> pLC -> {k2 | pB merged} -> pC -> plvw
    k_gemm_v3<<<dim3(16, 2, 8), 256>>>(p_U,   ctx_v_w,   p_pA,  Bn * Ln, Dn, Dn, Dn, 1.f, 1, 0);
    k_gemm_v3<<<dim3(16, 2, 8), 256>>>(p_pA,  lat_out_w, p_pLC, Bn * Ln, Dn, Dn, Dn, 1.f, 8, S);
    k_gemm_v3<<<dim3(32, 2, 8), 256>>>(p_pLC, p_bkv,     p_pkv, Bn * Ln, 2048, Dn, Dn, 1.f, 8, S);
    k_redk2<<<S / 4 / 256, 256>>>();
    k_gemm_v3<<<dim3(16, 2, 8), 256>>>(p_pkv + 1024, step_out_w, p_pC, Bn * Ln, Dn, Dn, 2048, 1.f, 8, Bn * Ln * 2048);
    k_gemm_v3<<<dim3(16, 2, 8), 256>>>(p_pC, gate_w1 + (size_t)Dn * Dn, p_plvw, Bn * Ln, Dn, Dn, Dn, 1.f, 8, S);
    k_redN<<<S / 4 / 256, 256>>>((float4*)p_lvw, (const float4*)p_plvw, S / 4, 8, S / 4);

    // P-path reduction
    k_redsplit<<<(pl * 256 + 255) / 256, 256>>>(pl);

    // stage-2 attention weights
    k_s2<<<dim3((pl + 15) / 16, Bn), 256>>>(pl);

    // gate select (16 p per block) + streaming expert combine
    const int smem_gs = (Ln * Dn + 16 * 1026 + Dn + 128 + 272 + 16) * 4;
    cudaFuncSetAttribute(k_gatesel, cudaFuncAttributeMaxDynamicSharedMemorySize, smem_gs);
    k_gatesel<<<dim3((pl + 15) / 16, Bn), 256, smem_gs>>>(gate_w2, gate_b2, gate_b1, pl);
    k_combine<<<pl, 256>>>(qexp, out, pl, Pfull);
}

// round 14
// speedup vs baseline: 1.7128x; 1.0743x over previous
#include <cuda_runtime.h>
#include <math.h>
#include <stdint.h>

#define Bn 32
#define Tn 2048
#define Dn 1024
#define En 16
#define Ln 8
#define Pmax 720
#define SUBSEG 32
#define NSUB 4
#define NPART 16           // Tn/(SUBSEG*NSUB)

typedef unsigned long long ull;

__device__ __forceinline__ void fma2(ull& d, ull a, ull b) {
    asm("fma.rn.f32x2 %0, %1, %2, %0;" : "+l"(d) : "l"(a), "l"(b));
}
__device__ __forceinline__ float2 u2f(ull v) {
    float2 f; asm("mov.b64 {%0,%1}, %2;" : "=f"(f.x), "=f"(f.y) : "l"(v)); return f;
}
__device__ __forceinline__ ull pack2(float s) {
    ull d; asm("mov.b64 %0, {%1,%1};" : "=l"(d) : "f"(s)); return d;
}
__device__ __forceinline__ float gelu_f(float x) {
    return 0.5f * x * (1.0f + erff(x * 0.70710678118654752440f));
}

// ---------------- scratch ----------------
__device__ float g_step_base[Pmax * Dn];
__device__ float g_t1p[8 * Ln * Dn];
__device__ float g_qeffp[8 * Ln * Dn];
__device__ float g_qeff[Ln * Dn];
__device__ float g_ssum[Bn * Ln * NPART];
__device__ float g_upart[(size_t)NPART * Bn * Ln * Dn];
__device__ float g_U[Bn * Ln * Dn];
__device__ float g_pA[8 * Bn * Ln * Dn];
__device__ float g_pLC[8 * Bn * Ln * Dn];
__device__ float g_LC[Bn * Ln * Dn];
__device__ float g_pkv[8 * Bn * Ln * 2048];
__device__ float g_vmat[Bn * Ln * Dn];
__device__ float g_pC[8 * Bn * Ln * Dn];
__device__ float g_Cmat[Bn * Ln * Dn];
__device__ float g_plvw[8 * Bn * Ln * Dn];
__device__ float g_k2[Bn * Ln * Dn];
__device__ float g_lvw[Bn * Ln * Dn];
__device__ float g_bcat[Dn * 2048];
__device__ float g_bkv[Dn * 2048];
__device__ float g_pcat[4 * Pmax * 2048];
__device__ float g_qb2[Pmax * Dn];
__device__ float g_bh[Pmax * Dn];
__device__ float g_A2[Bn * Pmax * Ln];
__device__ float4 g_sel[Bn * Pmax];

// ---------------- merged prep: step_base + both weight packs ----------------
__global__ void k_prep(const float* __restrict__ qpos, const float* __restrict__ tbl,
                       const float* __restrict__ sqw, const float* __restrict__ gw1,
                       const float* __restrict__ lkw, const float* __restrict__ lvww,
                       int pl, int nsb, float alpha) {
    int bid = blockIdx.x;
    if (bid < nsb) {
        int i = bid * 256 + threadIdx.x;
        if (i < pl * Dn)
            g_step_base[i] = qpos[i] + tbl[(size_t)pl * Dn + (i & (Dn - 1))];
        return;
    }
    bid -= nsb;
    const float* wl;
    const float* wr;
    float* dst;
    float al;
    if (bid < 2048) { wl = sqw; wr = gw1; dst = g_bcat; al = alpha; }
    else { bid -= 2048; wl = lkw; wr = lvww; dst = g_bkv; al = 1.f; }
    int i = bid * 256 + threadIdx.x;
    int row = i >> 9, c4 = i & 511;
    float4 v;
    if (c4 < 256) {
        v = ((const float4*)wl)[row * 256 + c4];
        v.x *= al; v.y *= al; v.z *= al; v.w *= al;
    } else {
        v = ((const float4*)wr)[row * 256 + (c4 - 256)];
    }
    ((float4*)dst)[i] = v;
}

// ---------------- 64x64 fp32x2 GEMM v2 (thin M=8 qeff GEMMs) ----------------
__global__ void k_gemm(const float* __restrict__ A, const float* __restrict__ B,
                       float* __restrict__ C, int M, int N, int K,
                       int transB, const float* __restrict__ bias, float alpha,
                       int nsumA, int strideA) {
    __shared__ float As[2][16][68];
    __shared__ float Bs[2][16][68];
    int tid = threadIdx.x;
    int tx = tid & 15, ty = tid >> 4;
    int m0 = blockIdx.y * 64, n0 = blockIdx.x * 64;
    int kper = K / gridDim.z;
    int kbeg = blockIdx.z * kper;
    C += (size_t)blockIdx.z * M * N;
    int nk = kper / 16;

    ull acc[4][2];
#pragma unroll
    for (int i = 0; i < 4; i++) { acc[i][0] = 0ULL; acc[i][1] = 0ULL; }

    float4 va, vb4;
    float ra[4], rb[4];
    int am = tid >> 2, ak4 = tid & 3;
    int bk = tid >> 4, bn4 = tid & 15;

#define PREF_V(k0)                                                               \
    {                                                                            \
        int gm = m0 + am;                                                        \
        va = make_float4(0.f, 0.f, 0.f, 0.f);                                    \
        if (gm < M) {                                                            \
            const float* ap = A + (size_t)gm * K + (k0) + ak4 * 4;               \
            va = *(const float4*)ap;                                             \
            for (int s = 1; s < nsumA; s++) {                                    \
                float4 t = *(const float4*)(ap + (size_t)s * strideA);           \
                va.x += t.x; va.y += t.y; va.z += t.z; va.w += t.w;              \
            }                                                                    \
        }                                                                        \
        vb4 = *(const float4*)(B + (size_t)((k0) + bk) * N + n0 + bn4 * 4);      \
    }
#define STORE_V(bf)                                                              \
    {                                                                            \
        As[bf][ak4 * 4 + 0][am] = va.x;                                          \
        As[bf][ak4 * 4 + 1][am] = va.y;                                          \
        As[bf][ak4 * 4 + 2][am] = va.z;                                          \
        As[bf][ak4 * 4 + 3][am] = va.w;                                          \
        *(float4*)&Bs[bf][bk][bn4 * 4] = vb4;                                    \
    }
#define PREF_S(k0)                                                               \
    {                                                                            \
        for (int r = 0; r < 4; r++) {                                            \
            int i = tid + 256 * r;                                               \
            int row = i >> 4, col = i & 15;                                      \
            int gm = m0 + row;                                                   \
            float v = 0.f;                                                       \
            if (gm < M) {                                                        \
                size_t off = (size_t)gm * K + (k0) + col;                        \
                v = A[off];                                                      \
                for (int s = 1; s < nsumA; s++) v += A[off + (size_t)s * strideA]; \
            }                                                                    \
            ra[r] = v;                                                           \
        }                                                                        \
        for (int r = 0; r < 4; r++) {                                            \
            int i = tid + 256 * r;                                               \
            rb[r] = B[(size_t)(n0 + (i >> 4)) * K + (k0) + (i & 15)];            \
        }                                                                        \
    }
#define STORE_S(bf)                                                              \
    {                                                                            \
        for (int r = 0; r < 4; r++) {                                            \
            int i = tid + 256 * r;                                               \
            As[bf][i & 15][i >> 4] = ra[r];                                      \
        }                                                                        \
        for (int r = 0; r < 4; r++) {                                            \
            int i = tid + 256 * r;                                               \
            Bs[bf][i & 15][i >> 4] = rb[r];                                      \
        }                                                                        \
    }
#define COMPUTE(bf)                                                              \
    {                                                                            \
        _Pragma("unroll")                                                        \
        for (int kk = 0; kk < 16; kk++) {                                        \
            float4 a4 = *(const float4*)&As[bf][kk][ty * 4];                     \
            ulonglong2 bb = *(const ulonglong2*)&Bs[bf][kk][tx * 4];             \
            ull a0 = pack2(a4.x), a1 = pack2(a4.y);                              \
            ull a2 = pack2(a4.z), a3 = pack2(a4.w);                              \
            fma2(acc[0][0], a0, bb.x); fma2(acc[0][1], a0, bb.y);                \
            fma2(acc[1][0], a1, bb.x); fma2(acc[1][1], a1, bb.y);                \
            fma2(acc[2][0], a2, bb.x); fma2(acc[2][1], a2, bb.y);                \
            fma2(acc[3][0], a3, bb.x); fma2(acc[3][1], a3, bb.y);                \
        }                                                                        \
    }

    int buf = 0;
    if (!transB) {
        PREF_V(kbeg);
        STORE_V(0);
        __syncthreads();
        for (int kt = 0; kt < nk; kt++) {
            if (kt + 1 < nk) PREF_V(kbeg + (kt + 1) * 16);
            COMPUTE(buf);
            if (kt + 1 < nk) {
                STORE_V(buf ^ 1);
                __syncthreads();
                buf ^= 1;
            }
        }
    } else {
        PREF_S(kbeg);
        STORE_S(0);
        __syncthreads();
        for (int kt = 0; kt < nk; kt++) {
            if (kt + 1 < nk) PREF_S(kbeg + (kt + 1) * 16);
            COMPUTE(buf);
            if (kt + 1 < nk) {
                STORE_S(buf ^ 1);
                __syncthreads();
                buf ^= 1;
            }
        }
    }
#pragma unroll
    for (int i = 0; i < 4; i++) {
        int m = m0 + ty * 4 + i;
        if (m >= M) continue;
        float2 p0 = u2f(acc[i][0]), p1 = u2f(acc[i][1]);
        float4 o;
        o.x = alpha * p0.x; o.y = alpha * p0.y;
        o.z = alpha * p1.x; o.w = alpha * p1.y;
        if (bias) {
            o.x += bias[n0 + tx * 4];     o.y += bias[n0 + tx * 4 + 1];
            o.z += bias[n0 + tx * 4 + 2]; o.w += bias[n0 + tx * 4 + 3];
        }
        *(float4*)&C[(size_t)m * N + n0 + tx * 4] = o;
    }
}

// ---------------- 128x64 fp32x2 GEMM v3 (lda-aware) ----------------
__global__ void __launch_bounds__(256) k_gemm_v3(
    const float* __restrict__ A, const float* __restrict__ B,
    float* __restrict__ C, int M, int N, int K, int lda,
    float alpha, int nsumA, int strideA) {
    __shared__ float As[2][16][132];
    __shared__ float Bs[2][16][68];
    int tid = threadIdx.x;
    int tx = tid & 15, ty = tid >> 4;
    int m0 = blockIdx.y * 128, n0 = blockIdx.x * 64;
    int kper = K / gridDim.z;
    int kbeg = blockIdx.z * kper;
    C += (size_t)blockIdx.z * M * N;
    int nk = kper / 16;

    ull acc[8][2];
#pragma unroll
    for (int i = 0; i < 8; i++) { acc[i][0] = 0ULL; acc[i][1] = 0ULL; }

    float4 va0, va1, vb4;
    int ar = tid >> 2, ak4 = tid & 3;
    int bk = tid >> 4, bn4 = tid & 15;

#define V3_PREF(k0)                                                              \
    {                                                                            \
        int gm0 = m0 + ar, gm1 = m0 + 64 + ar;                                   \
        va0 = make_float4(0.f, 0.f, 0.f, 0.f);                                   \
        va1 = va0;                                                               \
        if (gm0 < M) {                                                           \
            const float* ap = A + (size_t)gm0 * lda + (k0) + ak4 * 4;            \
            va0 = *(const float4*)ap;                                            \
            for (int s = 1; s < nsumA; s++) {                                    \
                float4 t = *(const float4*)(ap + (size_t)s * strideA);           \
                va0.x += t.x; va0.y += t.y; va0.z += t.z; va0.w += t.w;          \
            }                                                                    \
        }                                                                        \
        if (gm1 < M) {                                                           \
            const float* ap = A + (size_t)gm1 * lda + (k0) + ak4 * 4;            \
            va1 = *(const float4*)ap;                                            \
            for (int s = 1; s < nsumA; s++) {                                    \
                float4 t = *(const float4*)(ap + (size_t)s * strideA);           \
                va1.x += t.x; va1.y += t.y; va1.z += t.z; va1.w += t.w;          \
            }                                                                    \
        }                                                                        \
        vb4 = *(const float4*)(B + (size_t)((k0) + bk) * N + n0 + bn4 * 4);      \
    }
#define V3_STORE(bf)                                                             \
    {                                                                            \
        As[bf][ak4 * 4 + 0][ar] = va0.x;                                         \
        As[bf][ak4 * 4 + 1][ar] = va0.y;                                         \
        As[bf][ak4 * 4 + 2][ar] = va0.z;                                         \
        As[bf][ak4 * 4 + 3][ar] = va0.w;                                         \
        As[bf][ak4 * 4 + 0][64 + ar] = va1.x;                                    \
        As[bf][ak4 * 4 + 1][64 + ar] = va1.y;                                    \
        As[bf][ak4 * 4 + 2][64 + ar] = va1.z;                                    \
        As[bf][ak4 * 4 + 3][64 + ar] = va1.w;                                    \
        *(float4*)&Bs[bf][bk][bn4 * 4] = vb4;                                    \
    }
#define V3_COMP(bf)                                                              \
    {                                                                            \
        _Pragma("unroll")                                                        \
        for (int kk = 0; kk < 16; kk++) {                                        \
            float4 a0 = *(const float4*)&As[bf][kk][ty * 8];                     \
            float4 a1 = *(const float4*)&As[bf][kk][ty * 8 + 4];                 \
            ulonglong2 bb = *(const ulonglong2*)&Bs[bf][kk][tx * 4];             \
            ull p0 = pack2(a0.x), p1 = pack2(a0.y);                              \
            ull p2 = pack2(a0.z), p3 = pack2(a0.w);                              \
            ull p4 = pack2(a1.x), p5 = pack2(a1.y);                              \
            ull p6 = pack2(a1.z), p7 = pack2(a1.w);                              \
            fma2(acc[0][0], p0, bb.x); fma2(acc[0][1], p0, bb.y);                \
            fma2(acc[1][0], p1, bb.x); fma2(acc[1][1], p1, bb.y);                \
            fma2(acc[2][0], p2, bb.x); fma2(acc[2][1], p2, bb.y);                \
            fma2(acc[3][0], p3, bb.x); fma2(acc[3][1], p3, bb.y);                \
            fma2(acc[4][0], p4, bb.x); fma2(acc[4][1], p4, bb.y);                \
            fma2(acc[5][0], p5, bb.x); fma2(acc[5][1], p5, bb.y);                \
            fma2(acc[6][0], p6, bb.x); fma2(acc[6][1], p6, bb.y);                \
            fma2(acc[7][0], p7, bb.x); fma2(acc[7][1], p7, bb.y);                \
        }                                                                        \
    }

    int buf = 0;
    V3_PREF(kbeg);
    V3_STORE(0);
    __syncthreads();
    for (int kt = 0; kt < nk; kt++) {
        if (kt + 1 < nk) V3_PREF(kbeg + (kt + 1) * 16);
        V3_COMP(buf);
        if (kt + 1 < nk) {
            V3_STORE(buf ^ 1);
            __syncthreads();
            buf ^= 1;
        }
    }
#pragma unroll
    for (int i = 0; i < 8; i++) {
        int m = m0 + ty * 8 + i;
        if (m >= M) continue;
        float2 p0 = u2f(acc[i][0]), p1 = u2f(acc[i][1]);
        float4 o;
        o.x = alpha * p0.x; o.y = alpha * p0.y;
        o.z = alpha * p1.x; o.w = alpha * p1.y;
        *(float4*)&C[(size_t)m * N + n0 + tx * 4] = o;
    }
}

// ---------------- generic partial reduction ----------------
__global__ void k_redN(float4* __restrict__ dst, const float4* __restrict__ src,
                       int n4, int nparts, int stride4) {
    int i = blockIdx.x * 256 + threadIdx.x;
    if (i >= n4) return;
    float4 s = src[i];
    for (int p = 1; p < nparts; p++) {
        float4 t = src[i + (size_t)p * stride4];
        s.x += t.x; s.y += t.y; s.z += t.z; s.w += t.w;
    }
    dst[i] = s;
}

// ---------------- reduce both halves of merged pkv partials -> k2, vmat ----------
__global__ void k_redkv() {
    int i = blockIdx.x * 256 + threadIdx.x;   // over Bn*Ln*2048/4
    int m = i >> 9, c4 = i & 511;
    const float4* s = (const float4*)g_pkv;
    size_t base = (size_t)m * 512 + c4;
    size_t part = (size_t)Bn * Ln * 512;
    float4 a = s[base];
#pragma unroll
    for (int z = 1; z < 8; z++) {
        float4 t = s[base + z * part];
        a.x += t.x; a.y += t.y; a.z += t.z; a.w += t.w;
    }
    if (c4 < 256) ((float4*)g_k2)[m * 256 + c4] = a;
    else          ((float4*)g_vmat)[m * 256 + (c4 - 256)] = a;
}

// ---------------- de-interleave + reduce the packed P-GEMM (4 partials) ----------
__global__ void k_redsplit(int pl) {
    int i = blockIdx.x * 256 + threadIdx.x;
    if (i >= pl * 256) return;
    int p = i >> 8, d4 = i & 255;
    const float4* s = (const float4*)g_pcat;
    size_t base = (size_t)p * 512 + d4;
    size_t part = (size_t)pl * 512;
    float4 q = s[base], h = s[base + 256];
#pragma unroll
    for (int z = 1; z < 4; z++) {
        float4 tq = s[base + z * part], th = s[base + 256 + z * part];
        q.x += tq.x; q.y += tq.y; q.z += tq.z; q.w += tq.w;
        h.x += th.x; h.y += th.y; h.z += th.z; h.w += th.w;
    }
    ((float4*)g_qb2)[i] = q;
    ((float4*)g_bh)[i] = h;
}

// ---------------- fused stage-1 v3: pipelined A(s+1)/C(s), dbl-buffered scores ----
// grid (NPART=16, Bn), 256 threads, ~38KB smem, 2 blocks/SM. 4 subs of 32 tokens.
__global__ void __launch_bounds__(256, 2) k_fused1(const float* __restrict__ ctx) {
    extern __shared__ float smf[];
    float* qs  = smf;                    // 8*1024
    float* ps2 = qs + Ln * Dn;           // [2][tt*16+2l]
    float* prt = ps2 + 2 * SUBSEG * 16;  // [2][tt*8+l]
    int tid = threadIdx.x;
    for (int i = tid; i < Ln * Dn / 4; i += 256)
        ((float4*)qs)[i] = ((const float4*)g_qeff)[i];
    int b = blockIdx.y;
    int w = tid >> 5, lane = tid & 31;

    ull uacc[Ln][2];
#pragma unroll
    for (int l = 0; l < Ln; l++) { uacc[l][0] = 0ULL; uacc[l][1] = 0ULL; }
    float ssum = 0.f;

#define F1_PHASE_A(s, pb)                                                        \
    {                                                                            \
        const float* base = ctx +                                                \
            ((size_t)b * Tn + (blockIdx.x * NSUB + (s)) * SUBSEG + w * 4) * Dn;  \
        ull acc[4][Ln];                                                          \
        _Pragma("unroll")                                                        \
        for (int tt = 0; tt < 4; tt++)                                           \
            _Pragma("unroll")                                                    \
            for (int l = 0; l < Ln; l++) acc[tt][l] = 0ULL;                      \
        _Pragma("unroll")                                                        \
        for (int i = 0; i < 8; i++) {                                            \
            int d = (lane + 32 * i) * 4;                                         \
            ulonglong2 c0 = *(const ulonglong2*)(base + d);                      \
            ulonglong2 c1 = *(const ulonglong2*)(base + Dn + d);                 \
            ulonglong2 c2 = *(const ulonglong2*)(base + 2 * Dn + d);             \
            ulonglong2 c3 = *(const ulonglong2*)(base + 3 * Dn + d);             \
            _Pragma("unroll")                                                    \
            for (int l = 0; l < Ln; l++) {                                       \
                ulonglong2 q = *(const ulonglong2*)&qs[l * Dn + d];              \
                fma2(acc[0][l], c0.x, q.x); fma2(acc[0][l], c0.y, q.y);          \
                fma2(acc[1][l], c1.x, q.x); fma2(acc[1][l], c1.y, q.y);          \
                fma2(acc[2][l], c2.x, q.x); fma2(acc[2][l], c2.y, q.y);          \
                fma2(acc[3][l], c3.x, q.x); fma2(acc[3][l], c3.y, q.y);          \
            }                                                                    \
        }                                                                        \
        _Pragma("unroll")                                                        \
        for (int tt = 0; tt < 4; tt++)                                           \
            _Pragma("unroll")                                                    \
            for (int l = 0; l < Ln; l++) {                                       \
                float2 f = u2f(acc[tt][l]);                                      \
                float v = f.x + f.y;                                             \
                for (int off = 16; off; off >>= 1)                               \
                    v += __shfl_xor_sync(0xffffffffu, v, off);                   \
                if (lane == 0)                                                   \
                    prt[(pb) * 256 + (w * 4 + tt) * 8 + l] = v;                  \
            }                                                                    \
    }
#define F1_EXP(pb)                                                               \
    {                                                                            \
        int tt = tid >> 3, l = tid & 7;                                          \
        float e = expf(fminf(prt[(pb) * 256 + tt * 8 + l], 60.0f));              \
        ps2[(pb) * 512 + tt * 16 + 2 * l] = e;                                   \
        ps2[(pb) * 512 + tt * 16 + 2 * l + 1] = e;                               \
    }

    __syncthreads();   // qs fully loaded before ANY warp reads it (R13 bug fix)

    // prologue
    F1_PHASE_A(0, 0);
    __syncthreads();
    F1_EXP(0);
    __syncthreads();

    for (int s = 0; s < NSUB; s++) {
        int cur = s & 1, nxt = cur ^ 1;
        if (s + 1 < NSUB) F1_PHASE_A(s + 1, nxt);  // DRAM loads overlap C below

        // phase C for sub s (L2-hot re-read)
        const float* cb = ctx +
            ((size_t)b * Tn + (blockIdx.x * NSUB + s) * SUBSEG) * Dn + tid * 4;
        const float* pp = ps2 + cur * 512;
#pragma unroll 2
        for (int tt = 0; tt < SUBSEG; tt++) {
            float4 cf = *(const float4*)(cb + (size_t)tt * Dn);
            ull cx, cy;
            asm("mov.b64 %0, {%1,%2};" : "=l"(cx) : "f"(cf.x), "f"(cf.y));
            asm("mov.b64 %0, {%1,%2};" : "=l"(cy) : "f"(cf.z), "f"(cf.w));
            ulonglong2 p01 = *(const ulonglong2*)&pp[tt * 16];
            ulonglong2 p23 = *(const ulonglong2*)&pp[tt * 16 + 4];
            ulonglong2 p45 = *(const ulonglong2*)&pp[tt * 16 + 8];
            ulonglong2 p67 = *(const ulonglong2*)&pp[tt * 16 + 12];
            fma2(uacc[0][0], p01.x, cx); fma2(uacc[0][1], p01.x, cy);
            fma2(uacc[1][0], p01.y, cx); fma2(uacc[1][1], p01.y, cy);
            fma2(uacc[2][0], p23.x, cx); fma2(uacc[2][1], p23.x, cy);
            fma2(uacc[3][0], p23.y, cx); fma2(uacc[3][1], p23.y, cy);
            fma2(uacc[4][0], p45.x, cx); fma2(uacc[4][1], p45.x, cy);
            fma2(uacc[5][0], p45.y, cx); fma2(uacc[5][1], p45.y, cy);
            fma2(uacc[6][0], p67.x, cx); fma2(uacc[6][1], p67.x, cy);
            fma2(uacc[7][0], p67.y, cx); fma2(uacc[7][1], p67.y, cy);
        }

        // phase B: warp w sums exps for l = w over tt = lane
        {
            float sv = pp[lane * 16 + 2 * w];
            for (int off = 16; off; off >>= 1)
                sv += __shfl_xor_sync(0xffffffffu, sv, off);
            ssum += sv;
        }
        __syncthreads();
        if (s + 1 < NSUB) F1_EXP(nxt);
        __syncthreads();
    }
#pragma unroll
    for (int l = 0; l < Ln; l++) {
        float2 f0 = u2f(uacc[l][0]), f1 = u2f(uacc[l][1]);
        *(float4*)&g_upart[(((size_t)blockIdx.x * Bn + b) * Ln + l) * Dn + tid * 4] =
            make_float4(f0.x, f0.y, f1.x, f1.y);
    }
    if (lane == 0)
        g_ssum[((size_t)b * Ln + w) * NPART + blockIdx.x] = ssum;
}

// ---------------- combine stage-1 partials ----------------
__global__ void k_comb1() {
    __shared__ float inv[Ln];
    int b = blockIdx.y, dc = blockIdx.x;
    int tid = threadIdx.x;
    if (tid < Ln) {
        float s0 = 0.f, s1 = 0.f, s2 = 0.f, s3 = 0.f;
#pragma unroll
        for (int g = 0; g < NPART; g += 4) {
            s0 += g_ssum[((size_t)b * Ln + tid) * NPART + g];
            s1 += g_ssum[((size_t)b * Ln + tid) * NPART + g + 1];
            s2 += g_ssum[((size_t)b * Ln + tid) * NPART + g + 2];
            s3 += g_ssum[((size_t)b * Ln + tid) * NPART + g + 3];
        }
        inv[tid] = 1.0f / ((s0 + s1) + (s2 + s3));
    }
    __syncthreads();
    int dg = dc * 256 + tid;
#pragma unroll
    for (int l = 0; l < Ln; l++) {
        float a0 = 0.f, a1 = 0.f, a2 = 0.f, a3 = 0.f;
#pragma unroll
        for (int s = 0; s < NPART; s += 4) {
            a0 += g_upart[(((size_t)(s + 0) * Bn + b) * Ln + l) * Dn + dg];
            a1 += g_upart[(((size_t)(s + 1) * Bn + b) * Ln + l) * Dn + dg];
            a2 += g_upart[(((size_t)(s + 2) * Bn + b) * Ln + l) * Dn + dg];
            a3 += g_upart[(((size_t)(s + 3) * Bn + b) * Ln + l) * Dn + dg];
        }
        g_U[((size_t)b * Ln + l) * Dn + dg] = ((a0 + a1) + (a2 + a3)) * inv[l];
    }
}

// ---------------- stage-2 scores + softmax over L=8 ----------------
__global__ void k_s2(int pl) {
    __shared__ float ks[Ln][Dn];
    int tid = threadIdx.x, b = blockIdx.y;
    for (int i = tid; i < Ln * Dn / 4; i += 256)
        ((float4*)ks)[i] = ((const float4*)(g_k2 + (size_t)b * Ln * Dn))[i];
    __syncthreads();
    int w = tid >> 5, lane = tid & 31;
    int p0 = blockIdx.x * 16 + w * 2;
    if (p0 > pl - 2) p0 = pl - 2;
    ull acc[2][Ln];
#pragma unroll
    for (int pp = 0; pp < 2; pp++)
#pragma unroll
        for (int l = 0; l < Ln; l++) acc[pp][l] = 0ULL;
#pragma unroll
    for (int i = 0; i < 8; i++) {
        int d = (lane + 32 * i) * 4;
        ulonglong2 q0 = *(const ulonglong2*)(g_qb2 + (size_t)p0 * Dn + d);
        ulonglong2 q1 = *(const ulonglong2*)(g_qb2 + (size_t)(p0 + 1) * Dn + d);
#pragma unroll
        for (int l = 0; l < Ln; l++) {
            ulonglong2 k = *(const ulonglong2*)&ks[l][d];
            fma2(acc[0][l], q0.x, k.x); fma2(acc[0][l], q0.y, k.y);
            fma2(acc[1][l], q1.x, k.x); fma2(acc[1][l], q1.y, k.y);
        }
    }
#pragma unroll
    for (int pp = 0; pp < 2; pp++) {
        float v[Ln];
#pragma unroll
        for (int l = 0; l < Ln; l++) {
            float2 f = u2f(acc[pp][l]);
            float s = f.x + f.y;
            for (int off = 16; off; off >>= 1)
                s += __shfl_xor_sync(0xffffffffu, s, off);
            v[l] = s;
        }
        if (lane == 0) {
            int p = p0 + pp;
            if (p < pl) {
                float m = v[0];
#pragma unroll
                for (int l = 1; l < Ln; l++) m = fmaxf(m, v[l]);
                float e[Ln], s = 0.f;
#pragma unroll
                for (int l = 0; l < Ln; l++) { e[l] = expf(v[l] - m); s += e[l]; }
                float inv = 1.0f / s;
#pragma unroll
                for (int l = 0; l < Ln; l++)
                    g_A2[((size_t)b * pl + p) * Ln + l] = e[l] * inv;
            }
        }
    }
}

// ---------------- gate select: 16 p per block ----------------
__global__ void k_gatesel(const float* __restrict__ w2, const float* __restrict__ b2,
                          const float* __restrict__ b1, int pl) {
    extern __shared__ float sm[];
    float* lvws = sm;
    float* w2T  = lvws + Ln * Dn;
    float* hs   = w2T + 16 * 1026;
    float* a2s  = hs + Dn;
    float* part = a2s + 128;
    float* lg   = part + 272;
    int tid = threadIdx.x, b = blockIdx.y, p0 = blockIdx.x * 16;
    for (int i = tid; i < Ln * Dn / 4; i += 256)
        ((float4*)lvws)[i] = ((const float4*)(g_lvw + (size_t)b * Ln * Dn))[i];
    for (int i = tid; i < Dn * En; i += 256) {
        int d = i >> 4, e = i & 15;
        w2T[e * 1026 + d] = w2[i];
    }
    if (tid < 128) {
        int pi = tid >> 3, l = tid & 7;
        int p = p0 + pi;
        a2s[tid] = (p < pl) ? g_A2[((size_t)b * pl + p) * Ln + l] : 0.f;
    }
    float4 b1v = *(const float4*)(b1 + tid * 4);
    __syncthreads();
    int e_id = tid & 15, dseg = tid >> 4;
    float4 bh_cur = (p0 < pl) ? *(const float4*)(g_bh + (size_t)p0 * Dn + tid * 4)
                              : make_float4(0, 0, 0, 0);
    for (int pi = 0; pi < 16; pi++) {
        int p = p0 + pi;
        if (p >= pl) break;
        float4 bh_next = (pi + 1 < 16 && p + 1 < pl)
            ? *(const float4*)(g_bh + (size_t)(p + 1) * Dn + tid * 4)
            : make_float4(0, 0, 0, 0);
        float4 s4 = bh_cur;
        s4.x += b1v.x; s4.y += b1v.y; s4.z += b1v.z; s4.w += b1v.w;
#pragma unroll
        for (int l = 0; l < Ln; l++) {
            float a = a2s[pi * 8 + l];
            float4 v = ((const float4*)lvws)[l * (Dn / 4) + tid];
            s4.x += a * v.x; s4.y += a * v.y; s4.z += a * v.z; s4.w += a * v.w;
        }
        float4 h4;
        h4.x = gelu_f(s4.x); h4.y = gelu_f(s4.y);
        h4.z = gelu_f(s4.z); h4.w = gelu_f(s4.w);
        ((float4*)hs)[tid] = h4;
        __syncthreads();
        ull lacc = 0ULL;
        int dbase = dseg * 64;
#pragma unroll
        for (int j = 0; j < 32; j++) {
            ull h2 = *(const ull*)&hs[dbase + 2 * j];
            ull wv = *(const ull*)&w2T[e_id * 1026 + dbase + 2 * j];
            fma2(lacc, h2, wv);
        }
        float2 lf = u2f(lacc);
        part[dseg * 17 + e_id] = lf.x + lf.y;
        __syncthreads();
        if (tid < En) {
            float L = b2[tid];
#pragma unroll
            for (int g = 0; g < 16; g++) L += part[g * 17 + tid];
            lg[tid] = L;
        }
        __syncthreads();
        if (tid == 0) {
            float b1s = lg[0]; int e1 = 0;
#pragma unroll
            for (int e = 1; e < En; e++) if (lg[e] > b1s) { b1s = lg[e]; e1 = e; }
            float b2s = -3.4e38f; int e2 = 0;
#pragma unroll
            for (int e = 0; e < En; e++)
                if (e != e1 && lg[e] > b2s) { b2s = lg[e]; e2 = e; }
            float x2 = expf(b2s - b1s);
            float s = 1.f + x2;
            g_sel[(size_t)b * pl + p] = make_float4(
                1.f / s, x2 / s, __int_as_float(e1), __int_as_float(e2));
        }
        __syncthreads();
        bh_cur = bh_next;
    }
}

// ---------------- combine experts ----------------
__global__ void k_combine(const float* __restrict__ qexp, float* __restrict__ out,
                          int pl, int Pfull) {
    __shared__ float4 sel[Bn];
    int p = blockIdx.x, tid = threadIdx.x;
    if (tid < Bn) sel[tid] = g_sel[(size_t)tid * pl + p];
    __syncthreads();
#pragma unroll 4
    for (int b = 0; b < Bn; b++) {
        float4 s = sel[b];
        int eA = __float_as_int(s.z), eB = __float_as_int(s.w);
        float4 va = *(const float4*)(qexp + ((size_t)eA * Pfull + p) * Dn + tid * 4);
        float4 vb = *(const float4*)(qexp + ((size_t)eB * Pfull + p) * Dn + tid * 4);
        float4 o;
        o.x = s.x * va.x + s.y * vb.x;
        o.y = s.x * va.y + s.y * vb.y;
        o.z = s.x * va.z + s.y * vb.z;
        o.w = s.x * va.w + s.y * vb.w;
        *(float4*)(out + ((size_t)b * pl + p) * Dn + tid * 4) = o;
    }
}

// ---------------- launch ----------------
extern "C" void kernel_launch(void* const* d_in, const int* in_sizes, int n_in,
                              void* d_out, int out_size) {
    const float* ctx        = (const float*)d_in[0];
    const float* qexp       = (const float*)d_in[1];
    const float* qpos       = (const float*)d_in[2];
    const float* ptbl       = (const float*)d_in[3];
    const float* lats       = (const float*)d_in[4];
    const float* lat_q_w    = (const float*)d_in[5];
    const float* ctx_k_w    = (const float*)d_in[6];
    const float* ctx_v_w    = (const float*)d_in[7];
    const float* lat_out_w  = (const float*)d_in[8];
    const float* step_q_w   = (const float*)d_in[9];
    const float* lat_k_w    = (const float*)d_in[10];
    const float* lat_v_w    = (const float*)d_in[11];
    const float* step_out_w = (const float*)d_in[12];
    const float* gate_w1    = (const float*)d_in[13];
    const float* gate_b1    = (const float*)d_in[14];
    const float* gate_w2    = (const float*)d_in[15];
    const float* gate_b2    = (const float*)d_in[16];
    float* out = (float*)d_out;

    int pl = out_size / (Bn * Dn);
    int Pfull = in_sizes[2] / Dn;

    float *p_t1p, *p_qeffp, *p_qeff, *p_U;
    float *p_pA, *p_pLC, *p_LCm, *p_pkv, *p_vmat, *p_pC, *p_Cmat, *p_plvw;
    float *p_lvw, *p_sb, *p_bcat, *p_bkv, *p_pcat;
    cudaGetSymbolAddress((void**)&p_t1p, g_t1p);
    cudaGetSymbolAddress((void**)&p_qeffp, g_qeffp);
    cudaGetSymbolAddress((void**)&p_qeff, g_qeff);
    cudaGetSymbolAddress((void**)&p_U, g_U);
    cudaGetSymbolAddress((void**)&p_pA, g_pA);
    cudaGetSymbolAddress((void**)&p_pLC, g_pLC);
    cudaGetSymbolAddress((void**)&p_LCm, g_LC);
    cudaGetSymbolAddress((void**)&p_pkv, g_pkv);
    cudaGetSymbolAddress((void**)&p_vmat, g_vmat);
    cudaGetSymbolAddress((void**)&p_pC, g_pC);
    cudaGetSymbolAddress((void**)&p_Cmat, g_Cmat);
    cudaGetSymbolAddress((void**)&p_plvw, g_plvw);
    cudaGetSymbolAddress((void**)&p_lvw, g_lvw);
    cudaGetSymbolAddress((void**)&p_sb, g_step_base);
    cudaGetSymbolAddress((void**)&p_bcat, g_bcat);
    cudaGetSymbolAddress((void**)&p_bkv, g_bkv);
    cudaGetSymbolAddress((void**)&p_pcat, g_pcat);

    const float inv_sqrt_d = 0.03125f;
    const int S = Bn * Ln * Dn;

    // 0-2: qeff = (latents @ lat_q_w) @ ctx_k_w^T / sqrt(D)
    k_gemm<<<dim3(16, 1, 8), 256>>>(lats, lat_q_w, p_t1p, Ln, Dn, Dn, 0, nullptr, 1.f, 1, 0);
    k_gemm<<<dim3(16, 1, 8), 256>>>(p_t1p, ctx_k_w, p_qeffp, Ln, Dn, Dn, 1, nullptr, inv_sqrt_d, 8, Ln * Dn);
    k_redN<<<8, 256>>>((float4*)p_qeff, (const float4*)p_qeffp, Ln * Dn / 4, 8, Ln * Dn / 4);

    // 3 (ncu-sampled slot): fused stage-1 v3 (pipelined)
    const int smem_f1 = (Ln * Dn + 2 * SUBSEG * 16 + 2 * SUBSEG * 8) * 4;
    cudaFuncSetAttribute(k_fused1, cudaFuncAttributeMaxDynamicSharedMemorySize, smem_f1);
    k_fused1<<<dim3(NPART, Bn), 256, smem_f1>>>(ctx);

    // merged batch-independent prep
    int nsb = (pl * Dn + 255) / 256;
    k_prep<<<nsb + 4096, 256>>>(qpos, ptbl, step_q_w, gate_w1, lat_k_w, lat_v_w,
                                pl, nsb, inv_sqrt_d);

    // packed [720,2048,1024] P-GEMM v3, split-K x4
    int gy2 = (pl + 127) / 128;
    k_gemm_v3<<<dim3(32, gy2, 4), 256>>>(p_sb, p_bcat, p_pcat, pl, 2048, Dn, Dn, 1.f, 1, 0);

    // stage-1 finish
    k_comb1<<<dim3(4, Bn), 256>>>();

    // chain with materialized intermediates
    k_gemm_v3<<<dim3(16, 2, 8), 256>>>(p_U,  ctx_v_w,   p_pA,  Bn * Ln, Dn, Dn, Dn, 1.f, 1, 0);
    k_gemm_v3<<<dim3(16, 2, 8), 256>>>(p_pA, lat_out_w, p_pLC, Bn * Ln, Dn, Dn, Dn, 1.f, 8, S);
    k_redN<<<S / 4 / 256, 256>>>((float4*)p_LCm, (const float4*)p_pLC, S / 4, 8, S / 4);
    k_gemm_v3<<<dim3(32, 2, 8), 256>>>(p_LCm, p_bkv, p_pkv, Bn * Ln, 2048, Dn, Dn, 1.f, 1, 0);
    k_redkv<<<Bn * Ln * 2048 / 4 / 256, 256>>>();
    k_gemm_v3<<<dim3(16, 2, 8), 256>>>(p_vmat, step_out_w, p_pC, Bn * Ln, Dn, Dn, Dn, 1.f, 1, 0);
    k_redN<<<S / 4 / 256, 256>>>((float4*)p_Cmat, (const float4*)p_pC, S / 4, 8, S / 4);
    k_gemm_v3<<<dim3(16, 2, 8), 256>>>(p_Cmat, gate_w1 + (size_t)Dn * Dn, p_plvw, Bn * Ln, Dn, Dn, Dn, 1.f, 1, 0);
    k_redN<<<S / 4 / 256, 256>>>((float4*)p_lvw, (const float4*)p_plvw, S / 4, 8, S / 4);

    // P-path reduction
    k_redsplit<<<(pl * 256 + 255) / 256, 256>>>(pl);

    // stage-2 attention weights
    k_s2<<<dim3((pl + 15) / 16, Bn), 256>>>(pl);

    // gate select (16 p per block) + streaming expert combine
    const int smem_gs = (Ln * Dn + 16 * 1026 + Dn + 128 + 272 + 16) * 4;
    cudaFuncSetAttribute(k_gatesel, cudaFuncAttributeMaxDynamicSharedMemorySize, smem_gs);
    k_gatesel<<<dim3((pl + 15) / 16, Bn), 256, smem_gs>>>(gate_w2, gate_b2, gate_b1, pl);
    k_combine<<<pl, 256>>>(qexp, out, pl, Pfull);
}